// round 10
// baseline (speedup 1.0000x reference)
#include <cuda_runtime.h>
#include <cuda_bf16.h>
#include <cstdint>

#define NB   8
#define NN   256
#define NIN  16
#define NH   32
#define TILE 16
#define NT   (NN/TILE)          // 16
#define NTRI (NT*(NT+1)/2)      // 136
#define NBLK2 (NB*NTRI)         // 1088

typedef unsigned long long ull;

// ---- packed f32x2 helpers ----
__device__ __forceinline__ ull packf2(float lo, float hi) {
    ull r; asm("mov.b64 %0, {%1, %2};" : "=l"(r) : "f"(lo), "f"(hi)); return r;
}
__device__ __forceinline__ ull packdup(float v) {
    ull r; asm("mov.b64 %0, {%1, %1};" : "=l"(r) : "f"(v)); return r;
}
__device__ __forceinline__ ull ffma2(ull a, ull b, ull c) {
    ull d; asm("fma.rn.f32x2 %0, %1, %2, %3;" : "=l"(d) : "l"(a), "l"(b), "l"(c)); return d;
}
__device__ __forceinline__ float2 unpackf2(ull v) {
    float lo, hi; asm("mov.b64 {%0, %1}, %2;" : "=f"(lo), "=f"(hi) : "l"(v));
    return make_float2(lo, hi);
}
__device__ __forceinline__ float2 bf2f(unsigned int u) {
    return __bfloat1622float2(*reinterpret_cast<__nv_bfloat162*>(&u));
}
__device__ __forceinline__ unsigned int f2bf(float a, float b) {
    __nv_bfloat162 h = __floats2bfloat162_rn(a, b);
    return *reinterpret_cast<unsigned int*>(&h);
}

// ---- scratch (device globals) ----
__device__ __nv_bfloat16 g_G[(size_t)NB*NTRI*256*64];   // 35.6 MB pair-form rows
__device__ float g_R1[NB*NN*NH];
__device__ float g_Dg1[NB*NN*NH];
__device__ float g_T1[NB*NH];
__device__ float g_rp[(size_t)NB*NT*NT*512];            // 4 MB rowsum partials
__device__ float g_diag[NB*NN*NH];
__device__ float g_R2[NB*NN*NH];
__device__ float g_Dg2[NB*NN*NH];
__device__ float g_t2p[NB*NT*NH];                       // per-tile T2 partials
__device__ float g_part[(size_t)NBLK2*NH];
__device__ float g_nopsink[4];

// ============================================================
// NOP: launch-order shim so k1f is the 4th launch (ncu profiles #4).
// ============================================================
__global__ void __launch_bounds__(32) nop_kernel(int v) {
    if (threadIdx.x == 0) g_nopsink[v] = (float)v;
}

// ============================================================
// P1: parallel positional precompute. grid (NT, NB).
// ============================================================
__global__ void __launch_bounds__(256) p1_kernel(const float* __restrict__ x,
                                                 const float* __restrict__ W1,
                                                 const float* __restrict__ b1) {
    int ti = blockIdx.x, b = blockIdx.y, t = threadIdx.x;
    __shared__ float xs[NN*17];
    __shared__ float Ws[NH*NH*5];
    __shared__ float part[16*16];
    __shared__ float Ss[NIN];

    const float4* xg = (const float4*)(x + (size_t)b*NN*NIN);
    for (int e = t; e < NN*NIN/4; e += 256) {
        float4 v = xg[e];
        int r = e >> 2, c0 = (e & 3)*4;
        float* dst = xs + r*17 + c0;
        dst[0] = v.x; dst[1] = v.y; dst[2] = v.z; dst[3] = v.w;
    }
    for (int e = t; e < NH*NH*5; e += 256) Ws[e] = W1[e];
    __syncthreads();

    {
        int ch = t >> 4, d = t & 15;
        float s = 0.f;
        #pragma unroll
        for (int r = 0; r < 16; r++) s += xs[(ch*16 + r)*17 + d];
        part[ch*16 + d] = s;
    }
    __syncthreads();
    if (t < NIN) {
        float s = 0.f;
        #pragma unroll
        for (int ch = 0; ch < 16; ch++) s += part[ch*16 + t];
        Ss[t] = s;
    }
    __syncthreads();

    const float inv_n = 1.0f/(float)NN, inv_n2 = inv_n*inv_n;
    #pragma unroll
    for (int it = 0; it < 2; it++) {
        int item = t + it*256;
        int r = item >> 5, s = item & 31;
        int i = ti*16 + r;
        float rv = 0.f, dg = 0.f;
        #pragma unroll
        for (int d = 0; d < NIN; d++) {
            float xi = xs[i*17 + d];
            const float* wd  = &Ws[(d*NH + s)*5];
            const float* wd2 = &Ws[((NIN+d)*NH + s)*5];
            rv += xi*wd[3] + xi*Ss[d]*wd2[3];
            dg += xi*(wd[0] + wd[1] + wd[2]) + xi*xi*wd2[2];
        }
        g_R1 [((size_t)b*NN + i)*NH + s] = rv*inv_n;
        g_Dg1[((size_t)b*NN + i)*NH + s] = dg;
    }
    if (ti == 0 && t < NH) {
        int s = t;
        float tv = b1[s];
        #pragma unroll
        for (int d = 0; d < NIN; d++) {
            tv += Ss[d]*inv_n2       * Ws[(d*NH + s)*5 + 4];
            tv += Ss[d]*Ss[d]*inv_n2 * Ws[((NIN+d)*NH + s)*5 + 4];
        }
        g_T1[b*NH + s] = tv;
    }
}

// ============================================================
// K1F: fused layer-1 + layer-2 GEMM.
// Phase 1: 512 threads = (pair p, s-half).
// Phase 2: split — threads <256 run 2-pair-blocked GEMM (W LDS halved),
//          threads >=256 concurrently emit rowsum partials + diag.
// ============================================================
__global__ void __launch_bounds__(512, 2) k1f_kernel(const float* __restrict__ x,
                                                     const float* __restrict__ W1,
                                                     const float* __restrict__ W2) {
    extern __shared__ __align__(16) char smraw[];
    ull*   Wa2 = (ull*)smraw;                       // 256
    ull*   Wp2 = Wa2 + 256;                         // 512
    ull*   Wm2 = Wp2 + 512;                         // 512
    float* xi   = (float*)(Wm2 + 512);              // 272
    float* xj   = xi + 272;                         // 272
    float* posI = xj + 272;                         // 512
    float* posJ = posI + 512;                       // 512
    float* dgs  = posJ + 512;                       // 512
    float* t1s  = dgs + 512;                        // 32
    unsigned int* apS = (unsigned int*)(t1s + 32);  // 256*17
    unsigned int* amS = apS + 256*17;               // 256*17

    int tp = blockIdx.x, b = blockIdx.y, t = threadIdx.x;
    int ti = 0, rr0 = tp;
    while (rr0 >= NT - ti) { rr0 -= NT - ti; ti++; }
    int tj = ti + rr0;
    int I = ti*TILE, J = tj*TILE;
    int bid = b*NTRI + tp;
    bool isdiag = (ti == tj);

    if (t < 256) {
        int r = t >> 4, c = t & 15;
        xi[r*17 + c] = x[(size_t)b*NN*NIN + (I+r)*NIN + c];
        int d = r, k = c, s0 = 2*k;
        float a0 = W1[((NIN+d)*NH + s0  )*5 + 0] + W1[((NIN+d)*NH + s0  )*5 + 1];
        float a1 = W1[((NIN+d)*NH + s0+1)*5 + 0] + W1[((NIN+d)*NH + s0+1)*5 + 1];
        Wa2[t] = packf2(a0, a1);
    } else {
        int e = t - 256;
        int r = e >> 4, c = e & 15;
        xj[r*17 + c] = x[(size_t)b*NN*NIN + (J+r)*NIN + c];
    }
    {
        int e = t;
        int tt = e >> 4, k = e & 15, s0 = 2*k;
        float w00 = W2[(tt*NH + s0  )*5 + 0], w01 = W2[(tt*NH + s0  )*5 + 1];
        float w10 = W2[(tt*NH + s0+1)*5 + 0], w11 = W2[(tt*NH + s0+1)*5 + 1];
        Wp2[e] = packf2(w00 + w01, w10 + w11);
        Wm2[e] = packf2(w00 - w01, w10 - w11);
    }
    {
        int e = t;
        int r = e >> 5, s = e & 31;
        posI[e] = g_R1 [((size_t)b*NN + I + r)*NH + s];
        posJ[e] = g_R1 [((size_t)b*NN + J + r)*NH + s];
        dgs[e]  = g_Dg1[((size_t)b*NN + I + r)*NH + s];
    }
    if (t < NH) t1s[t] = g_T1[b*NH + t];
    __syncthreads();

    // ---- phase 1: layer-1, 512 threads = (pair p, s-half sh1) ----
    {
        int p = t & 255, sh1 = t >> 8;
        int ii = p >> 4, jj = p & 15;
        int sb1 = sh1*16;
        bool dgflag = isdiag && (ii == jj);

        ull acc2[8];
        #pragma unroll
        for (int k = 0; k < 8; k++) acc2[k] = 0ull;
        #pragma unroll
        for (int d = 0; d < NIN; d++) {
            float zd = xi[ii*17 + d] * xj[jj*17 + d];
            ull zdup = packdup(zd);
            const ulonglong2* w = (const ulonglong2*)(Wa2 + d*16 + sh1*8);
            #pragma unroll
            for (int k4 = 0; k4 < 4; k4++) {
                ulonglong2 ww = w[k4];
                acc2[2*k4]   = ffma2(zdup, ww.x, acc2[2*k4]);
                acc2[2*k4+1] = ffma2(zdup, ww.y, acc2[2*k4+1]);
            }
        }
        #pragma unroll
        for (int k = 0; k < 8; k++) {
            float2 m = unpackf2(acc2[k]);
            int s0 = sb1 + 2*k, s1 = s0 + 1;
            float e0 = dgflag ? dgs[ii*NH + s0] : 0.f;
            float e1 = dgflag ? dgs[ii*NH + s1] : 0.f;
            float t0 = t1s[s0], t1v = t1s[s1];
            float c1lo = fmaxf(m.x + posI[ii*NH + s0] + t0 + e0, 0.f);
            float c1hi = fmaxf(m.y + posI[ii*NH + s1] + t1v + e1, 0.f);
            float c2lo = fmaxf(m.x + posJ[jj*NH + s0] + t0 + e0, 0.f);
            float c2hi = fmaxf(m.y + posJ[jj*NH + s1] + t1v + e1, 0.f);
            apS[p*17 + sh1*8 + k] = f2bf(c1lo + c2lo, c1hi + c2hi);
            amS[p*17 + sh1*8 + k] = f2bf(c1lo - c2lo, c1hi - c2hi);
        }
    }
    __syncthreads();

    if (t >= 256) {
        // ---- rowsum partials + diag: 2 items per upper thread ----
        #pragma unroll
        for (int half = 0; half < 2; half++) {
            int e = (t - 256) + half*256;     // 0..511
            int r = e >> 5, s = e & 31;
            int w16 = s >> 1, hi = s & 1;
            float vI = 0.f;
            #pragma unroll
            for (int q = 0; q < 16; q++) {
                float2 fa = bf2f(apS[(r*16 + q)*17 + w16]);
                float2 fm = bf2f(amS[(r*16 + q)*17 + w16]);
                vI += hi ? (fa.y + fm.y) : (fa.x + fm.x);
            }
            g_rp[((size_t)((b*NT + ti)*NT + tj))*512 + e] = 0.5f*vI;
            if (!isdiag) {
                float vJ = 0.f;
                #pragma unroll
                for (int q = 0; q < 16; q++) {
                    float2 fa = bf2f(apS[(q*16 + r)*17 + w16]);
                    float2 fm = bf2f(amS[(q*16 + r)*17 + w16]);
                    vJ += hi ? (fa.y - fm.y) : (fa.x - fm.x);
                }
                g_rp[((size_t)((b*NT + tj)*NT + ti))*512 + e] = 0.5f*vJ;
            } else {
                float2 fa = bf2f(apS[(r*16 + r)*17 + w16]);
                float2 fm = bf2f(amS[(r*16 + r)*17 + w16]);
                float dv = hi ? (fa.y + fm.y) : (fa.x + fm.x);
                g_diag[((size_t)b*NN + I + r)*NH + s] = 0.5f*dv;
            }
        }
    } else {
        // ---- phase 2: 2-pair-blocked layer-2 GEMM (threads < 256) ----
        int duo = t & 127, shg = t >> 7;
        int sbg = shg*16;
        const unsigned int* paA = apS + duo*17;
        const unsigned int* paB = apS + (duo + 128)*17;
        const unsigned int* maA = amS + duo*17;
        const unsigned int* maB = amS + (duo + 128)*17;
        size_t growA = ((size_t)bid*256 + duo)*64;
        size_t growB = ((size_t)bid*256 + duo + 128)*64;

        {   // P pass
            ull aA[8], aB[8];
            #pragma unroll
            for (int k = 0; k < 8; k++) { aA[k] = 0ull; aB[k] = 0ull; }
            #pragma unroll 4
            for (int w16 = 0; w16 < 16; w16++) {
                float2 fA = bf2f(paA[w16]);
                float2 fB = bf2f(paB[w16]);
                #pragma unroll
                for (int h = 0; h < 2; h++) {
                    int tt = 2*w16 + h;
                    ull xA = packdup(h ? fA.y : fA.x);
                    ull xB = packdup(h ? fB.y : fB.x);
                    const ulonglong2* wp = (const ulonglong2*)(Wp2 + tt*16 + shg*8);
                    #pragma unroll
                    for (int q = 0; q < 4; q++) {
                        ulonglong2 ww = wp[q];
                        aA[2*q]   = ffma2(xA, ww.x, aA[2*q]);
                        aA[2*q+1] = ffma2(xA, ww.y, aA[2*q+1]);
                        aB[2*q]   = ffma2(xB, ww.x, aB[2*q]);
                        aB[2*q+1] = ffma2(xB, ww.y, aB[2*q+1]);
                    }
                }
            }
            unsigned int oA[8], oB[8];
            #pragma unroll
            for (int k = 0; k < 8; k++) {
                float2 PA = unpackf2(aA[k]);
                float2 PB = unpackf2(aB[k]);
                oA[k] = f2bf(0.5f*PA.x, 0.5f*PA.y);
                oB[k] = f2bf(0.5f*PB.x, 0.5f*PB.y);
            }
            uint4* dA = (uint4*)(g_G + growA + sbg);
            dA[0] = make_uint4(oA[0], oA[1], oA[2], oA[3]);
            dA[1] = make_uint4(oA[4], oA[5], oA[6], oA[7]);
            uint4* dB = (uint4*)(g_G + growB + sbg);
            dB[0] = make_uint4(oB[0], oB[1], oB[2], oB[3]);
            dB[1] = make_uint4(oB[4], oB[5], oB[6], oB[7]);
        }
        {   // M pass
            ull aA[8], aB[8];
            #pragma unroll
            for (int k = 0; k < 8; k++) { aA[k] = 0ull; aB[k] = 0ull; }
            #pragma unroll 4
            for (int w16 = 0; w16 < 16; w16++) {
                float2 fA = bf2f(maA[w16]);
                float2 fB = bf2f(maB[w16]);
                #pragma unroll
                for (int h = 0; h < 2; h++) {
                    int tt = 2*w16 + h;
                    ull xA = packdup(h ? fA.y : fA.x);
                    ull xB = packdup(h ? fB.y : fB.x);
                    const ulonglong2* wm = (const ulonglong2*)(Wm2 + tt*16 + shg*8);
                    #pragma unroll
                    for (int q = 0; q < 4; q++) {
                        ulonglong2 ww = wm[q];
                        aA[2*q]   = ffma2(xA, ww.x, aA[2*q]);
                        aA[2*q+1] = ffma2(xA, ww.y, aA[2*q+1]);
                        aB[2*q]   = ffma2(xB, ww.x, aB[2*q]);
                        aB[2*q+1] = ffma2(xB, ww.y, aB[2*q+1]);
                    }
                }
            }
            unsigned int oA[8], oB[8];
            #pragma unroll
            for (int k = 0; k < 8; k++) {
                float2 MA = unpackf2(aA[k]);
                float2 MB = unpackf2(aB[k]);
                oA[k] = f2bf(0.5f*MA.x, 0.5f*MA.y);
                oB[k] = f2bf(0.5f*MB.x, 0.5f*MB.y);
            }
            uint4* dA = (uint4*)(g_G + growA + 32 + sbg);
            dA[0] = make_uint4(oA[0], oA[1], oA[2], oA[3]);
            dA[1] = make_uint4(oA[4], oA[5], oA[6], oA[7]);
            uint4* dB = (uint4*)(g_G + growB + 32 + sbg);
            dB[0] = make_uint4(oB[0], oB[1], oB[2], oB[3]);
            dB[1] = make_uint4(oB[4], oB[5], oB[6], oB[7]);
        }
    }
}

// ============================================================
// P2: coalesced rowsum gather + layer-2 positional terms + T2 partials.
// ============================================================
__global__ void __launch_bounds__(256) p2_kernel(const float* __restrict__ W2) {
    int ti = blockIdx.x, b = blockIdx.y, t = threadIdx.x;
    __shared__ float Ws3[NH*NH], Ws2s[NH*NH], Ws4[NH*NH];
    __shared__ float raS[16*33], dvS[16*33];
    __shared__ float totS[NH];

    for (int e = t; e < NH*NH; e += 256) {
        Ws3[e]  = W2[e*5 + 3];
        Ws2s[e] = W2[e*5 + 2];
        Ws4[e]  = W2[e*5 + 4];
    }

    int ii = t >> 4, sp = t & 15;
    float2 acc = make_float2(0.f, 0.f);
    const float* base = g_rp + (size_t)(b*NT + ti)*NT*512 + ii*NH + 2*sp;
    #pragma unroll
    for (int tj = 0; tj < NT; tj++) {
        float2 v = *(const float2*)(base + tj*512);
        acc.x += v.x; acc.y += v.y;
    }
    raS[ii*33 + 2*sp] = acc.x; raS[ii*33 + 2*sp + 1] = acc.y;
    {
        float2 dv = *(const float2*)(g_diag + ((size_t)b*NN + ti*16 + ii)*NH + 2*sp);
        dvS[ii*33 + 2*sp] = dv.x; dvS[ii*33 + 2*sp + 1] = dv.y;
    }
    __syncthreads();

    if (t < NH) {
        float s = 0.f;
        #pragma unroll
        for (int r = 0; r < 16; r++) s += raS[r*33 + t];
        totS[t] = s;
    }
    __syncthreads();
    if (t < NH) {
        float a = 0.f;
        #pragma unroll
        for (int q = 0; q < NH; q++) a = fmaf(totS[q], Ws4[q*NH + t], a);
        g_t2p[(b*NT + ti)*NH + t] = a;
    }

    const float inv_n = 1.0f/(float)NN;
    int s0 = t & 15;
    float r2a = 0.f, r2b = 0.f, d2a = 0.f, d2b = 0.f;
    #pragma unroll
    for (int q = 0; q < NH; q++) {
        float rq = raS[ii*33 + q]*inv_n;
        float dq = dvS[ii*33 + q];
        r2a = fmaf(rq, Ws3[q*NH + s0],      r2a);
        r2b = fmaf(rq, Ws3[q*NH + s0 + 16], r2b);
        d2a = fmaf(dq, Ws2s[q*NH + s0],      d2a);
        d2b = fmaf(dq, Ws2s[q*NH + s0 + 16], d2b);
    }
    size_t ro = ((size_t)b*NN + ti*16 + ii)*NH;
    g_R2 [ro + s0]      = r2a;
    g_R2 [ro + s0 + 16] = r2b;
    g_Dg2[ro + s0]      = d2a;
    g_Dg2[ro + s0 + 16] = d2b;
}

// ============================================================
// K2B: streaming epilogue — pair-form G, cheap T2 sum, conflict-free reduce.
// ============================================================
__global__ void __launch_bounds__(256) k2b_kernel(const float* __restrict__ b2) {
    __shared__ float bs1[512], bs2[512], dgI[512];
    __shared__ float t2s[NH];
    __shared__ float red[256*33];
    __shared__ float part2[8*NH];

    int tp = blockIdx.x, b = blockIdx.y, t = threadIdx.x;
    int ti = 0, rr0 = tp;
    while (rr0 >= NT - ti) { rr0 -= NT - ti; ti++; }
    int tj = ti + rr0;
    int I = ti*TILE, J = tj*TILE;
    int bid = b*NTRI + tp;
    bool isdiag = (ti == tj);

    for (int e = t; e < 512; e += 256) {
        int r = e >> 5, s = e & 31;
        bs1[e] = g_R2[((size_t)b*NN + I + r)*NH + s];
        bs2[e] = g_R2[((size_t)b*NN + J + r)*NH + s];
        dgI[e] = g_Dg2[((size_t)b*NN + I + r)*NH + s];
    }
    if (t < NH) {
        const float inv_n2 = 1.0f/((float)NN*(float)NN);
        float a = 0.f;
        #pragma unroll
        for (int k = 0; k < NT; k++) a += g_t2p[(b*NT + k)*NH + t];
        t2s[t] = b2[t] + a*inv_n2;
    }
    __syncthreads();

    int ii = t >> 4, jj = t & 15;
    const uint4* g = (const uint4*)(g_G + ((size_t)bid*256 + t)*64);
    uint4 qp[4], qm[4];
    #pragma unroll
    for (int v4 = 0; v4 < 4; v4++) { qp[v4] = g[v4]; qm[v4] = g[v4 + 4]; }

    float cs[NH];
    #pragma unroll
    for (int v4 = 0; v4 < 4; v4++) {
        unsigned int up[4] = {qp[v4].x, qp[v4].y, qp[v4].z, qp[v4].w};
        unsigned int um[4] = {qm[v4].x, qm[v4].y, qm[v4].z, qm[v4].w};
        #pragma unroll
        for (int u = 0; u < 4; u++) {
            int s0 = v4*8 + 2*u;
            float2 fp = bf2f(up[u]);
            float2 fm = bf2f(um[u]);
            #pragma unroll
            for (int h = 0; h < 2; h++) {
                int s = s0 + h;
                float pv = h ? fp.y : fp.x;
                float mv = h ? fm.y : fm.x;
                float b1v = bs1[ii*NH + s] + t2s[s];
                if (isdiag && ii == jj) b1v += dgI[ii*NH + s];
                float c1 = fmaxf(pv + mv + b1v, 0.f);
                float c2 = fmaxf(pv - mv + bs2[jj*NH + s] + t2s[s], 0.f);
                float v = c1 + c2;
                if (isdiag) v = (ii < jj) ? (c1 + c2) : ((ii == jj) ? c1 : 0.f);
                cs[s] = v;
            }
        }
    }

    #pragma unroll
    for (int s = 0; s < NH; s++) red[t*33 + s] = cs[s];
    __syncthreads();
    {
        int s = t & 31, c = t >> 5;
        float tsum = 0.f;
        #pragma unroll
        for (int r = 0; r < 32; r++) tsum += red[(c*32 + r)*33 + s];
        part2[c*NH + s] = tsum;
    }
    __syncthreads();
    if (t < NH) {
        float p = 0.f;
        #pragma unroll
        for (int c = 0; c < 8; c++) p += part2[c*NH + t];
        g_part[(size_t)bid*NH + t] = p;
    }
}

// ============================================================
// Final: parallel partial reduce + MLP 32->128->128->1.
// ============================================================
__global__ void __launch_bounds__(256) fin_kernel(const float* __restrict__ D1,
                                                  const float* __restrict__ db1,
                                                  const float* __restrict__ D2,
                                                  const float* __restrict__ db2,
                                                  const float* __restrict__ D3,
                                                  const float* __restrict__ db3,
                                                  float* __restrict__ out) {
    int b = blockIdx.x, tid = threadIdx.x;
    __shared__ float pp[8*NH];
    __shared__ float p[NH];
    __shared__ float m1[128];
    __shared__ float h2p[256];
    __shared__ float m2[128];
    __shared__ float wr[4];

    {
        int s = tid & 31, c = tid >> 5;
        float a = 0.f;
        #pragma unroll 4
        for (int k = c; k < NTRI; k += 8) a += g_part[(size_t)(b*NTRI + k)*NH + s];
        pp[tid] = a;
    }
    __syncthreads();
    if (tid < NH) {
        float t = 0.f;
        #pragma unroll
        for (int c = 0; c < 8; c++) t += pp[c*NH + tid];
        p[tid] = fmaxf(t, 0.f);
    }
    __syncthreads();
    if (tid < 128) {
        float a = db1[tid];
        #pragma unroll
        for (int q = 0; q < NH; q++) a = fmaf(p[q], D1[q*128 + tid], a);
        m1[tid] = fmaxf(a, 0.f);
    }
    __syncthreads();
    {
        int o = tid & 127, half = tid >> 7;
        float a = 0.f;
        #pragma unroll 16
        for (int e = half*64; e < half*64 + 64; e++)
            a = fmaf(m1[e], D2[e*128 + o], a);
        h2p[tid] = a;
    }
    __syncthreads();
    if (tid < 128) m2[tid] = fmaxf(h2p[tid] + h2p[128 + tid] + db2[tid], 0.f);
    __syncthreads();
    if (tid < 128) {
        float v = m2[tid] * D3[tid];
        #pragma unroll
        for (int o = 16; o; o >>= 1) v += __shfl_xor_sync(0xffffffffu, v, o);
        if ((tid & 31) == 0) wr[tid >> 5] = v;
    }
    __syncthreads();
    if (tid == 0) out[b] = wr[0] + wr[1] + wr[2] + wr[3] + db3[0];
}

extern "C" void kernel_launch(void* const* d_in, const int* in_sizes, int n_in,
                              void* d_out, int out_size) {
    const float* x   = (const float*)d_in[0];
    const float* W1  = (const float*)d_in[1];
    const float* b1  = (const float*)d_in[2];
    const float* W2  = (const float*)d_in[3];
    const float* b2  = (const float*)d_in[4];
    const float* D1  = (const float*)d_in[5];
    const float* db1 = (const float*)d_in[6];
    const float* D2  = (const float*)d_in[7];
    const float* db2 = (const float*)d_in[8];
    const float* D3  = (const float*)d_in[9];
    const float* db3 = (const float*)d_in[10];
    float* out = (float*)d_out;

    size_t k1f_smem = 53504;
    cudaFuncSetAttribute(k1f_kernel, cudaFuncAttributeMaxDynamicSharedMemorySize,
                         (int)k1f_smem);

    p1_kernel<<<dim3(NT, NB), 256>>>(x, W1, b1);   // launch 1
    nop_kernel<<<1, 32>>>(0);                      // launch 2
    nop_kernel<<<1, 32>>>(1);                      // launch 3
    k1f_kernel<<<dim3(NTRI, NB), 512, k1f_smem>>>(x, W1, W2);  // launch 4 -> profiled
    p2_kernel<<<dim3(NT, NB), 256>>>(W2);
    k2b_kernel<<<dim3(NTRI, NB), 256>>>(b2);
    fin_kernel<<<NB, 256>>>(D1, db1, D2, db2, D3, db3, out);
}

// round 11
// speedup vs baseline: 1.5419x; 1.5419x over previous
#include <cuda_runtime.h>
#include <cuda_bf16.h>
#include <cstdint>

#define NB   8
#define NN   256
#define NIN  16
#define NH   32
#define TILE 16
#define NT   (NN/TILE)          // 16
#define NTRI (NT*(NT+1)/2)      // 136
#define NBLK2 (NB*NTRI)         // 1088

typedef unsigned long long ull;

// ---- packed f32x2 helpers ----
__device__ __forceinline__ ull packf2(float lo, float hi) {
    ull r; asm("mov.b64 %0, {%1, %2};" : "=l"(r) : "f"(lo), "f"(hi)); return r;
}
__device__ __forceinline__ ull packdup(float v) {
    ull r; asm("mov.b64 %0, {%1, %1};" : "=l"(r) : "f"(v)); return r;
}
__device__ __forceinline__ ull ffma2(ull a, ull b, ull c) {
    ull d; asm("fma.rn.f32x2 %0, %1, %2, %3;" : "=l"(d) : "l"(a), "l"(b), "l"(c)); return d;
}
__device__ __forceinline__ float2 unpackf2(ull v) {
    float lo, hi; asm("mov.b64 {%0, %1}, %2;" : "=f"(lo), "=f"(hi) : "l"(v));
    return make_float2(lo, hi);
}
__device__ __forceinline__ float2 bf2f(unsigned int u) {
    return __bfloat1622float2(*reinterpret_cast<__nv_bfloat162*>(&u));
}
__device__ __forceinline__ unsigned int f2bf(float a, float b) {
    __nv_bfloat162 h = __floats2bfloat162_rn(a, b);
    return *reinterpret_cast<unsigned int*>(&h);
}

// ---- scratch (device globals) ----
__device__ __nv_bfloat16 g_G[(size_t)NB*NTRI*256*64];   // 35.6 MB pair-form rows
__device__ float g_R1[NB*NN*NH];
__device__ float g_Dg1[NB*NN*NH];
__device__ float g_T1[NB*NH];
__device__ float g_rp[(size_t)NB*NT*NT*512];            // 4 MB rowsum partials
__device__ float g_diag[NB*NN*NH];
__device__ float g_R2[NB*NN*NH];
__device__ float g_Dg2[NB*NN*NH];
__device__ float g_t2p[NB*NT*NH];                       // per-tile T2 partials
__device__ float g_part[(size_t)NBLK2*NH];
__device__ float g_nopsink[4];

// ============================================================
// NOP: launch-order shim so k1f is the 4th launch (ncu profiles #4).
// ============================================================
__global__ void __launch_bounds__(32) nop_kernel(int v) {
    if (threadIdx.x == 0) g_nopsink[v] = (float)v;
}

// ============================================================
// P1: parallel positional precompute. grid (NT, NB).
// ============================================================
__global__ void __launch_bounds__(256) p1_kernel(const float* __restrict__ x,
                                                 const float* __restrict__ W1,
                                                 const float* __restrict__ b1) {
    int ti = blockIdx.x, b = blockIdx.y, t = threadIdx.x;
    __shared__ float xs[NN*17];
    __shared__ float Ws[NH*NH*5];
    __shared__ float part[16*16];
    __shared__ float Ss[NIN];

    const float4* xg = (const float4*)(x + (size_t)b*NN*NIN);
    for (int e = t; e < NN*NIN/4; e += 256) {
        float4 v = xg[e];
        int r = e >> 2, c0 = (e & 3)*4;
        float* dst = xs + r*17 + c0;
        dst[0] = v.x; dst[1] = v.y; dst[2] = v.z; dst[3] = v.w;
    }
    for (int e = t; e < NH*NH*5; e += 256) Ws[e] = W1[e];
    __syncthreads();

    {
        int ch = t >> 4, d = t & 15;
        float s = 0.f;
        #pragma unroll
        for (int r = 0; r < 16; r++) s += xs[(ch*16 + r)*17 + d];
        part[ch*16 + d] = s;
    }
    __syncthreads();
    if (t < NIN) {
        float s = 0.f;
        #pragma unroll
        for (int ch = 0; ch < 16; ch++) s += part[ch*16 + t];
        Ss[t] = s;
    }
    __syncthreads();

    const float inv_n = 1.0f/(float)NN, inv_n2 = inv_n*inv_n;
    #pragma unroll
    for (int it = 0; it < 2; it++) {
        int item = t + it*256;
        int r = item >> 5, s = item & 31;
        int i = ti*16 + r;
        float rv = 0.f, dg = 0.f;
        #pragma unroll
        for (int d = 0; d < NIN; d++) {
            float xi = xs[i*17 + d];
            const float* wd  = &Ws[(d*NH + s)*5];
            const float* wd2 = &Ws[((NIN+d)*NH + s)*5];
            rv += xi*wd[3] + xi*Ss[d]*wd2[3];
            dg += xi*(wd[0] + wd[1] + wd[2]) + xi*xi*wd2[2];
        }
        g_R1 [((size_t)b*NN + i)*NH + s] = rv*inv_n;
        g_Dg1[((size_t)b*NN + i)*NH + s] = dg;
    }
    if (ti == 0 && t < NH) {
        int s = t;
        float tv = b1[s];
        #pragma unroll
        for (int d = 0; d < NIN; d++) {
            tv += Ss[d]*inv_n2       * Ws[(d*NH + s)*5 + 4];
            tv += Ss[d]*Ss[d]*inv_n2 * Ws[((NIN+d)*NH + s)*5 + 4];
        }
        g_T1[b*NH + s] = tv;
    }
}

// ============================================================
// K1F: fused layer-1 + layer-2 GEMM (R9 structure).
// Phase 1: 512 threads = (pair p, s-half).
// Rowsums: all 512 threads (1 item each).
// Phase 2 GEMM: 512 threads = (duo 0..127, s-quarter 0..3); each thread
// does 2 pairs x 8 s per pass -> W LDS halved, 16-reg accumulators.
// ============================================================
__global__ void __launch_bounds__(512, 2) k1f_kernel(const float* __restrict__ x,
                                                     const float* __restrict__ W1,
                                                     const float* __restrict__ W2) {
    extern __shared__ __align__(16) char smraw[];
    ull*   Wa2 = (ull*)smraw;                       // 256
    ull*   Wp2 = Wa2 + 256;                         // 512
    ull*   Wm2 = Wp2 + 512;                         // 512
    float* xi   = (float*)(Wm2 + 512);              // 272
    float* xj   = xi + 272;                         // 272
    float* posI = xj + 272;                         // 512
    float* posJ = posI + 512;                       // 512
    float* dgs  = posJ + 512;                       // 512
    float* t1s  = dgs + 512;                        // 32
    unsigned int* apS = (unsigned int*)(t1s + 32);  // 256*17
    unsigned int* amS = apS + 256*17;               // 256*17

    int tp = blockIdx.x, b = blockIdx.y, t = threadIdx.x;
    int ti = 0, rr0 = tp;
    while (rr0 >= NT - ti) { rr0 -= NT - ti; ti++; }
    int tj = ti + rr0;
    int I = ti*TILE, J = tj*TILE;
    int bid = b*NTRI + tp;
    bool isdiag = (ti == tj);

    if (t < 256) {
        int r = t >> 4, c = t & 15;
        xi[r*17 + c] = x[(size_t)b*NN*NIN + (I+r)*NIN + c];
        int d = r, k = c, s0 = 2*k;
        float a0 = W1[((NIN+d)*NH + s0  )*5 + 0] + W1[((NIN+d)*NH + s0  )*5 + 1];
        float a1 = W1[((NIN+d)*NH + s0+1)*5 + 0] + W1[((NIN+d)*NH + s0+1)*5 + 1];
        Wa2[t] = packf2(a0, a1);
    } else {
        int e = t - 256;
        int r = e >> 4, c = e & 15;
        xj[r*17 + c] = x[(size_t)b*NN*NIN + (J+r)*NIN + c];
    }
    {
        int e = t;
        int tt = e >> 4, k = e & 15, s0 = 2*k;
        float w00 = W2[(tt*NH + s0  )*5 + 0], w01 = W2[(tt*NH + s0  )*5 + 1];
        float w10 = W2[(tt*NH + s0+1)*5 + 0], w11 = W2[(tt*NH + s0+1)*5 + 1];
        Wp2[e] = packf2(w00 + w01, w10 + w11);
        Wm2[e] = packf2(w00 - w01, w10 - w11);
    }
    {
        int e = t;
        int r = e >> 5, s = e & 31;
        posI[e] = g_R1 [((size_t)b*NN + I + r)*NH + s];
        posJ[e] = g_R1 [((size_t)b*NN + J + r)*NH + s];
        dgs[e]  = g_Dg1[((size_t)b*NN + I + r)*NH + s];
    }
    if (t < NH) t1s[t] = g_T1[b*NH + t];
    __syncthreads();

    // ---- phase 1: layer-1, 512 threads = (pair p, s-half sh1) ----
    {
        int p = t & 255, sh1 = t >> 8;
        int ii = p >> 4, jj = p & 15;
        int sb1 = sh1*16;
        bool dgflag = isdiag && (ii == jj);

        ull acc2[8];
        #pragma unroll
        for (int k = 0; k < 8; k++) acc2[k] = 0ull;
        #pragma unroll
        for (int d = 0; d < NIN; d++) {
            float zd = xi[ii*17 + d] * xj[jj*17 + d];
            ull zdup = packdup(zd);
            const ulonglong2* w = (const ulonglong2*)(Wa2 + d*16 + sh1*8);
            #pragma unroll
            for (int k4 = 0; k4 < 4; k4++) {
                ulonglong2 ww = w[k4];
                acc2[2*k4]   = ffma2(zdup, ww.x, acc2[2*k4]);
                acc2[2*k4+1] = ffma2(zdup, ww.y, acc2[2*k4+1]);
            }
        }
        #pragma unroll
        for (int k = 0; k < 8; k++) {
            float2 m = unpackf2(acc2[k]);
            int s0 = sb1 + 2*k, s1 = s0 + 1;
            float e0 = dgflag ? dgs[ii*NH + s0] : 0.f;
            float e1 = dgflag ? dgs[ii*NH + s1] : 0.f;
            float t0 = t1s[s0], t1v = t1s[s1];
            float c1lo = fmaxf(m.x + posI[ii*NH + s0] + t0 + e0, 0.f);
            float c1hi = fmaxf(m.y + posI[ii*NH + s1] + t1v + e1, 0.f);
            float c2lo = fmaxf(m.x + posJ[jj*NH + s0] + t0 + e0, 0.f);
            float c2hi = fmaxf(m.y + posJ[jj*NH + s1] + t1v + e1, 0.f);
            apS[p*17 + sh1*8 + k] = f2bf(c1lo + c2lo, c1hi + c2hi);
            amS[p*17 + sh1*8 + k] = f2bf(c1lo - c2lo, c1hi - c2hi);
        }
    }
    __syncthreads();

    // ---- rowsum partials + diag: all 512 threads, 1 item each ----
    {
        int r = t >> 5, s = t & 31;
        int w16 = s >> 1, hi = s & 1;
        float vI = 0.f;
        #pragma unroll
        for (int q = 0; q < 16; q++) {
            float2 fa = bf2f(apS[(r*16 + q)*17 + w16]);
            float2 fm = bf2f(amS[(r*16 + q)*17 + w16]);
            vI += hi ? (fa.y + fm.y) : (fa.x + fm.x);
        }
        g_rp[((size_t)((b*NT + ti)*NT + tj))*512 + t] = 0.5f*vI;
        if (!isdiag) {
            float vJ = 0.f;
            #pragma unroll
            for (int q = 0; q < 16; q++) {
                float2 fa = bf2f(apS[(q*16 + r)*17 + w16]);
                float2 fm = bf2f(amS[(q*16 + r)*17 + w16]);
                vJ += hi ? (fa.y - fm.y) : (fa.x - fm.x);
            }
            g_rp[((size_t)((b*NT + tj)*NT + ti))*512 + t] = 0.5f*vJ;
        } else {
            float2 fa = bf2f(apS[(r*16 + r)*17 + w16]);
            float2 fm = bf2f(amS[(r*16 + r)*17 + w16]);
            float dv = hi ? (fa.y + fm.y) : (fa.x + fm.x);
            g_diag[((size_t)b*NN + I + r)*NH + s] = 0.5f*dv;
        }
    }

    // ---- phase 2: GEMM, 2 pairs x 8 s per thread per pass ----
    {
        int duo = t & 127, sq = t >> 7;          // sq 0..3
        int sbq = sq*8;                           // s-range [sbq, sbq+8)
        const unsigned int* paA = apS + duo*17;
        const unsigned int* paB = apS + (duo + 128)*17;
        const unsigned int* maA = amS + duo*17;
        const unsigned int* maB = amS + (duo + 128)*17;
        size_t growA = ((size_t)bid*256 + duo)*64;
        size_t growB = ((size_t)bid*256 + duo + 128)*64;

        {   // P pass
            ull aA[4], aB[4];
            #pragma unroll
            for (int k = 0; k < 4; k++) { aA[k] = 0ull; aB[k] = 0ull; }
            #pragma unroll 4
            for (int w16 = 0; w16 < 16; w16++) {
                float2 fA = bf2f(paA[w16]);
                float2 fB = bf2f(paB[w16]);
                #pragma unroll
                for (int h = 0; h < 2; h++) {
                    int tt = 2*w16 + h;
                    ull xA = packdup(h ? fA.y : fA.x);
                    ull xB = packdup(h ? fB.y : fB.x);
                    const ulonglong2* wp = (const ulonglong2*)(Wp2 + tt*16 + sq*4);
                    ulonglong2 w0 = wp[0], w1 = wp[1];
                    aA[0] = ffma2(xA, w0.x, aA[0]);
                    aA[1] = ffma2(xA, w0.y, aA[1]);
                    aA[2] = ffma2(xA, w1.x, aA[2]);
                    aA[3] = ffma2(xA, w1.y, aA[3]);
                    aB[0] = ffma2(xB, w0.x, aB[0]);
                    aB[1] = ffma2(xB, w0.y, aB[1]);
                    aB[2] = ffma2(xB, w1.x, aB[2]);
                    aB[3] = ffma2(xB, w1.y, aB[3]);
                }
            }
            unsigned int oA[4], oB[4];
            #pragma unroll
            for (int k = 0; k < 4; k++) {
                float2 PA = unpackf2(aA[k]);
                float2 PB = unpackf2(aB[k]);
                oA[k] = f2bf(0.5f*PA.x, 0.5f*PA.y);
                oB[k] = f2bf(0.5f*PB.x, 0.5f*PB.y);
            }
            *(uint4*)(g_G + growA + sbq) = make_uint4(oA[0], oA[1], oA[2], oA[3]);
            *(uint4*)(g_G + growB + sbq) = make_uint4(oB[0], oB[1], oB[2], oB[3]);
        }
        {   // M pass
            ull aA[4], aB[4];
            #pragma unroll
            for (int k = 0; k < 4; k++) { aA[k] = 0ull; aB[k] = 0ull; }
            #pragma unroll 4
            for (int w16 = 0; w16 < 16; w16++) {
                float2 fA = bf2f(maA[w16]);
                float2 fB = bf2f(maB[w16]);
                #pragma unroll
                for (int h = 0; h < 2; h++) {
                    int tt = 2*w16 + h;
                    ull xA = packdup(h ? fA.y : fA.x);
                    ull xB = packdup(h ? fB.y : fB.x);
                    const ulonglong2* wm = (const ulonglong2*)(Wm2 + tt*16 + sq*4);
                    ulonglong2 w0 = wm[0], w1 = wm[1];
                    aA[0] = ffma2(xA, w0.x, aA[0]);
                    aA[1] = ffma2(xA, w0.y, aA[1]);
                    aA[2] = ffma2(xA, w1.x, aA[2]);
                    aA[3] = ffma2(xA, w1.y, aA[3]);
                    aB[0] = ffma2(xB, w0.x, aB[0]);
                    aB[1] = ffma2(xB, w0.y, aB[1]);
                    aB[2] = ffma2(xB, w1.x, aB[2]);
                    aB[3] = ffma2(xB, w1.y, aB[3]);
                }
            }
            unsigned int oA[4], oB[4];
            #pragma unroll
            for (int k = 0; k < 4; k++) {
                float2 MA = unpackf2(aA[k]);
                float2 MB = unpackf2(aB[k]);
                oA[k] = f2bf(0.5f*MA.x, 0.5f*MA.y);
                oB[k] = f2bf(0.5f*MB.x, 0.5f*MB.y);
            }
            *(uint4*)(g_G + growA + 32 + sbq) = make_uint4(oA[0], oA[1], oA[2], oA[3]);
            *(uint4*)(g_G + growB + 32 + sbq) = make_uint4(oB[0], oB[1], oB[2], oB[3]);
        }
    }
}

// ============================================================
// P2: coalesced rowsum gather + layer-2 positional terms + T2 partials.
// ============================================================
__global__ void __launch_bounds__(256) p2_kernel(const float* __restrict__ W2) {
    int ti = blockIdx.x, b = blockIdx.y, t = threadIdx.x;
    __shared__ float Ws3[NH*NH], Ws2s[NH*NH], Ws4[NH*NH];
    __shared__ float raS[16*33], dvS[16*33];
    __shared__ float totS[NH];

    for (int e = t; e < NH*NH; e += 256) {
        Ws3[e]  = W2[e*5 + 3];
        Ws2s[e] = W2[e*5 + 2];
        Ws4[e]  = W2[e*5 + 4];
    }

    int ii = t >> 4, sp = t & 15;
    float2 acc = make_float2(0.f, 0.f);
    const float* base = g_rp + (size_t)(b*NT + ti)*NT*512 + ii*NH + 2*sp;
    #pragma unroll
    for (int tj = 0; tj < NT; tj++) {
        float2 v = *(const float2*)(base + tj*512);
        acc.x += v.x; acc.y += v.y;
    }
    raS[ii*33 + 2*sp] = acc.x; raS[ii*33 + 2*sp + 1] = acc.y;
    {
        float2 dv = *(const float2*)(g_diag + ((size_t)b*NN + ti*16 + ii)*NH + 2*sp);
        dvS[ii*33 + 2*sp] = dv.x; dvS[ii*33 + 2*sp + 1] = dv.y;
    }
    __syncthreads();

    if (t < NH) {
        float s = 0.f;
        #pragma unroll
        for (int r = 0; r < 16; r++) s += raS[r*33 + t];
        totS[t] = s;
    }
    __syncthreads();
    if (t < NH) {
        float a = 0.f;
        #pragma unroll
        for (int q = 0; q < NH; q++) a = fmaf(totS[q], Ws4[q*NH + t], a);
        g_t2p[(b*NT + ti)*NH + t] = a;
    }

    const float inv_n = 1.0f/(float)NN;
    int s0 = t & 15;
    float r2a = 0.f, r2b = 0.f, d2a = 0.f, d2b = 0.f;
    #pragma unroll
    for (int q = 0; q < NH; q++) {
        float rq = raS[ii*33 + q]*inv_n;
        float dq = dvS[ii*33 + q];
        r2a = fmaf(rq, Ws3[q*NH + s0],      r2a);
        r2b = fmaf(rq, Ws3[q*NH + s0 + 16], r2b);
        d2a = fmaf(dq, Ws2s[q*NH + s0],      d2a);
        d2b = fmaf(dq, Ws2s[q*NH + s0 + 16], d2b);
    }
    size_t ro = ((size_t)b*NN + ti*16 + ii)*NH;
    g_R2 [ro + s0]      = r2a;
    g_R2 [ro + s0 + 16] = r2b;
    g_Dg2[ro + s0]      = d2a;
    g_Dg2[ro + s0 + 16] = d2b;
}

// ============================================================
// K2B: streaming epilogue — pair-form G, cheap T2 sum, conflict-free reduce.
// ============================================================
__global__ void __launch_bounds__(256) k2b_kernel(const float* __restrict__ b2) {
    __shared__ float bs1[512], bs2[512], dgI[512];
    __shared__ float t2s[NH];
    __shared__ float red[256*33];
    __shared__ float part2[8*NH];

    int tp = blockIdx.x, b = blockIdx.y, t = threadIdx.x;
    int ti = 0, rr0 = tp;
    while (rr0 >= NT - ti) { rr0 -= NT - ti; ti++; }
    int tj = ti + rr0;
    int I = ti*TILE, J = tj*TILE;
    int bid = b*NTRI + tp;
    bool isdiag = (ti == tj);

    for (int e = t; e < 512; e += 256) {
        int r = e >> 5, s = e & 31;
        bs1[e] = g_R2[((size_t)b*NN + I + r)*NH + s];
        bs2[e] = g_R2[((size_t)b*NN + J + r)*NH + s];
        dgI[e] = g_Dg2[((size_t)b*NN + I + r)*NH + s];
    }
    if (t < NH) {
        const float inv_n2 = 1.0f/((float)NN*(float)NN);
        float a = 0.f;
        #pragma unroll
        for (int k = 0; k < NT; k++) a += g_t2p[(b*NT + k)*NH + t];
        t2s[t] = b2[t] + a*inv_n2;
    }
    __syncthreads();

    int ii = t >> 4, jj = t & 15;
    const uint4* g = (const uint4*)(g_G + ((size_t)bid*256 + t)*64);
    uint4 qp[4], qm[4];
    #pragma unroll
    for (int v4 = 0; v4 < 4; v4++) { qp[v4] = g[v4]; qm[v4] = g[v4 + 4]; }

    float cs[NH];
    #pragma unroll
    for (int v4 = 0; v4 < 4; v4++) {
        unsigned int up[4] = {qp[v4].x, qp[v4].y, qp[v4].z, qp[v4].w};
        unsigned int um[4] = {qm[v4].x, qm[v4].y, qm[v4].z, qm[v4].w};
        #pragma unroll
        for (int u = 0; u < 4; u++) {
            int s0 = v4*8 + 2*u;
            float2 fp = bf2f(up[u]);
            float2 fm = bf2f(um[u]);
            #pragma unroll
            for (int h = 0; h < 2; h++) {
                int s = s0 + h;
                float pv = h ? fp.y : fp.x;
                float mv = h ? fm.y : fm.x;
                float b1v = bs1[ii*NH + s] + t2s[s];
                if (isdiag && ii == jj) b1v += dgI[ii*NH + s];
                float c1 = fmaxf(pv + mv + b1v, 0.f);
                float c2 = fmaxf(pv - mv + bs2[jj*NH + s] + t2s[s], 0.f);
                float v = c1 + c2;
                if (isdiag) v = (ii < jj) ? (c1 + c2) : ((ii == jj) ? c1 : 0.f);
                cs[s] = v;
            }
        }
    }

    #pragma unroll
    for (int s = 0; s < NH; s++) red[t*33 + s] = cs[s];
    __syncthreads();
    {
        int s = t & 31, c = t >> 5;
        float tsum = 0.f;
        #pragma unroll
        for (int r = 0; r < 32; r++) tsum += red[(c*32 + r)*33 + s];
        part2[c*NH + s] = tsum;
    }
    __syncthreads();
    if (t < NH) {
        float p = 0.f;
        #pragma unroll
        for (int c = 0; c < 8; c++) p += part2[c*NH + t];
        g_part[(size_t)bid*NH + t] = p;
    }
}

// ============================================================
// Final: parallel partial reduce + MLP 32->128->128->1.
// ============================================================
__global__ void __launch_bounds__(256) fin_kernel(const float* __restrict__ D1,
                                                  const float* __restrict__ db1,
                                                  const float* __restrict__ D2,
                                                  const float* __restrict__ db2,
                                                  const float* __restrict__ D3,
                                                  const float* __restrict__ db3,
                                                  float* __restrict__ out) {
    int b = blockIdx.x, tid = threadIdx.x;
    __shared__ float pp[8*NH];
    __shared__ float p[NH];
    __shared__ float m1[128];
    __shared__ float h2p[256];
    __shared__ float m2[128];
    __shared__ float wr[4];

    {
        int s = tid & 31, c = tid >> 5;
        float a = 0.f;
        #pragma unroll 4
        for (int k = c; k < NTRI; k += 8) a += g_part[(size_t)(b*NTRI + k)*NH + s];
        pp[tid] = a;
    }
    __syncthreads();
    if (tid < NH) {
        float t = 0.f;
        #pragma unroll
        for (int c = 0; c < 8; c++) t += pp[c*NH + tid];
        p[tid] = fmaxf(t, 0.f);
    }
    __syncthreads();
    if (tid < 128) {
        float a = db1[tid];
        #pragma unroll
        for (int q = 0; q < NH; q++) a = fmaf(p[q], D1[q*128 + tid], a);
        m1[tid] = fmaxf(a, 0.f);
    }
    __syncthreads();
    {
        int o = tid & 127, half = tid >> 7;
        float a = 0.f;
        #pragma unroll 16
        for (int e = half*64; e < half*64 + 64; e++)
            a = fmaf(m1[e], D2[e*128 + o], a);
        h2p[tid] = a;
    }
    __syncthreads();
    if (tid < 128) m2[tid] = fmaxf(h2p[tid] + h2p[128 + tid] + db2[tid], 0.f);
    __syncthreads();
    if (tid < 128) {
        float v = m2[tid] * D3[tid];
        #pragma unroll
        for (int o = 16; o; o >>= 1) v += __shfl_xor_sync(0xffffffffu, v, o);
        if ((tid & 31) == 0) wr[tid >> 5] = v;
    }
    __syncthreads();
    if (tid == 0) out[b] = wr[0] + wr[1] + wr[2] + wr[3] + db3[0];
}

extern "C" void kernel_launch(void* const* d_in, const int* in_sizes, int n_in,
                              void* d_out, int out_size) {
    const float* x   = (const float*)d_in[0];
    const float* W1  = (const float*)d_in[1];
    const float* b1  = (const float*)d_in[2];
    const float* W2  = (const float*)d_in[3];
    const float* b2  = (const float*)d_in[4];
    const float* D1  = (const float*)d_in[5];
    const float* db1 = (const float*)d_in[6];
    const float* D2  = (const float*)d_in[7];
    const float* db2 = (const float*)d_in[8];
    const float* D3  = (const float*)d_in[9];
    const float* db3 = (const float*)d_in[10];
    float* out = (float*)d_out;

    size_t k1f_smem = 53504;
    cudaFuncSetAttribute(k1f_kernel, cudaFuncAttributeMaxDynamicSharedMemorySize,
                         (int)k1f_smem);

    p1_kernel<<<dim3(NT, NB), 256>>>(x, W1, b1);   // launch 1
    nop_kernel<<<1, 32>>>(0);                      // launch 2
    nop_kernel<<<1, 32>>>(1);                      // launch 3
    k1f_kernel<<<dim3(NTRI, NB), 512, k1f_smem>>>(x, W1, W2);  // launch 4 -> profiled
    p2_kernel<<<dim3(NT, NB), 256>>>(W2);
    k2b_kernel<<<dim3(NTRI, NB), 256>>>(b2);
    fin_kernel<<<NB, 256>>>(D1, db1, D2, db2, D3, db3, out);
}

// round 12
// speedup vs baseline: 1.6230x; 1.0526x over previous
#include <cuda_runtime.h>
#include <cuda_bf16.h>
#include <cstdint>

#define NB   8
#define NN   256
#define NIN  16
#define NH   32
#define TILE 16
#define NT   (NN/TILE)          // 16
#define NTRI (NT*(NT+1)/2)      // 136
#define NBLK2 (NB*NTRI)         // 1088

typedef unsigned long long ull;

// ---- packed f32x2 helpers ----
__device__ __forceinline__ ull packf2(float lo, float hi) {
    ull r; asm("mov.b64 %0, {%1, %2};" : "=l"(r) : "f"(lo), "f"(hi)); return r;
}
__device__ __forceinline__ ull packdup(float v) {
    ull r; asm("mov.b64 %0, {%1, %1};" : "=l"(r) : "f"(v)); return r;
}
__device__ __forceinline__ ull ffma2(ull a, ull b, ull c) {
    ull d; asm("fma.rn.f32x2 %0, %1, %2, %3;" : "=l"(d) : "l"(a), "l"(b), "l"(c)); return d;
}
__device__ __forceinline__ float2 unpackf2(ull v) {
    float lo, hi; asm("mov.b64 {%0, %1}, %2;" : "=f"(lo), "=f"(hi) : "l"(v));
    return make_float2(lo, hi);
}
__device__ __forceinline__ float2 bf2f(unsigned int u) {
    return __bfloat1622float2(*reinterpret_cast<__nv_bfloat162*>(&u));
}
__device__ __forceinline__ unsigned int f2bf(float a, float b) {
    __nv_bfloat162 h = __floats2bfloat162_rn(a, b);
    return *reinterpret_cast<unsigned int*>(&h);
}

// ---- scratch (device globals) ----
__device__ __nv_bfloat16 g_G[(size_t)NB*NTRI*256*64];   // 35.6 MB pair-form rows
__device__ float g_R1[NB*NN*NH];
__device__ float g_Dg1[NB*NN*NH];
__device__ float g_T1[NB*NH];
__device__ float g_rp[(size_t)NB*NT*NT*512];            // 4 MB rowsum partials
__device__ float g_diag[NB*NN*NH];
__device__ float g_R2[NB*NN*NH];
__device__ float g_Dg2[NB*NN*NH];
__device__ float g_t2p[NB*NT*NH];                       // per-tile T2 partials
__device__ float g_part[(size_t)NBLK2*NH];

// ============================================================
// P1: parallel positional precompute. grid (NT, NB).
// ============================================================
__global__ void __launch_bounds__(256) p1_kernel(const float* __restrict__ x,
                                                 const float* __restrict__ W1,
                                                 const float* __restrict__ b1) {
    int ti = blockIdx.x, b = blockIdx.y, t = threadIdx.x;
    __shared__ float xs[NN*17];
    __shared__ float Ws[NH*NH*5];
    __shared__ float part[16*16];
    __shared__ float Ss[NIN];

    const float4* xg = (const float4*)(x + (size_t)b*NN*NIN);
    for (int e = t; e < NN*NIN/4; e += 256) {
        float4 v = xg[e];
        int r = e >> 2, c0 = (e & 3)*4;
        float* dst = xs + r*17 + c0;
        dst[0] = v.x; dst[1] = v.y; dst[2] = v.z; dst[3] = v.w;
    }
    for (int e = t; e < NH*NH*5; e += 256) Ws[e] = W1[e];
    __syncthreads();

    {
        int ch = t >> 4, d = t & 15;
        float s = 0.f;
        #pragma unroll
        for (int r = 0; r < 16; r++) s += xs[(ch*16 + r)*17 + d];
        part[ch*16 + d] = s;
    }
    __syncthreads();
    if (t < NIN) {
        float s = 0.f;
        #pragma unroll
        for (int ch = 0; ch < 16; ch++) s += part[ch*16 + t];
        Ss[t] = s;
    }
    __syncthreads();

    const float inv_n = 1.0f/(float)NN, inv_n2 = inv_n*inv_n;
    #pragma unroll
    for (int it = 0; it < 2; it++) {
        int item = t + it*256;
        int r = item >> 5, s = item & 31;
        int i = ti*16 + r;
        float rv = 0.f, dg = 0.f;
        #pragma unroll
        for (int d = 0; d < NIN; d++) {
            float xi = xs[i*17 + d];
            const float* wd  = &Ws[(d*NH + s)*5];
            const float* wd2 = &Ws[((NIN+d)*NH + s)*5];
            rv += xi*wd[3] + xi*Ss[d]*wd2[3];
            dg += xi*(wd[0] + wd[1] + wd[2]) + xi*xi*wd2[2];
        }
        g_R1 [((size_t)b*NN + i)*NH + s] = rv*inv_n;
        g_Dg1[((size_t)b*NN + i)*NH + s] = dg;
    }
    if (ti == 0 && t < NH) {
        int s = t;
        float tv = b1[s];
        #pragma unroll
        for (int d = 0; d < NIN; d++) {
            tv += Ss[d]*inv_n2       * Ws[(d*NH + s)*5 + 4];
            tv += Ss[d]*Ss[d]*inv_n2 * Ws[((NIN+d)*NH + s)*5 + 4];
        }
        g_T1[b*NH + s] = tv;
    }
}

// ============================================================
// K1F: fused layer-1 + layer-2 GEMM.
// Phase 1: 512 threads = (pair p, s-half).
// Rowsums: 512 threads = (side, row, word) — both bf16 lanes per load.
// Phase 2 GEMM: 512 threads = (duo, s-quarter); 2 pairs x 8 s per pass.
// ============================================================
__global__ void __launch_bounds__(512, 2) k1f_kernel(const float* __restrict__ x,
                                                     const float* __restrict__ W1,
                                                     const float* __restrict__ W2) {
    extern __shared__ __align__(16) char smraw[];
    ull*   Wa2 = (ull*)smraw;                       // 256
    ull*   Wp2 = Wa2 + 256;                         // 512
    ull*   Wm2 = Wp2 + 512;                         // 512
    float* xi   = (float*)(Wm2 + 512);              // 272
    float* xj   = xi + 272;                         // 272
    float* posI = xj + 272;                         // 512
    float* posJ = posI + 512;                       // 512
    float* dgs  = posJ + 512;                       // 512
    float* t1s  = dgs + 512;                        // 32
    unsigned int* apS = (unsigned int*)(t1s + 32);  // 256*17
    unsigned int* amS = apS + 256*17;               // 256*17

    int tp = blockIdx.x, b = blockIdx.y, t = threadIdx.x;
    int ti = 0, rr0 = tp;
    while (rr0 >= NT - ti) { rr0 -= NT - ti; ti++; }
    int tj = ti + rr0;
    int I = ti*TILE, J = tj*TILE;
    int bid = b*NTRI + tp;
    bool isdiag = (ti == tj);

    if (t < 256) {
        int r = t >> 4, c = t & 15;
        xi[r*17 + c] = x[(size_t)b*NN*NIN + (I+r)*NIN + c];
        int d = r, k = c, s0 = 2*k;
        float a0 = W1[((NIN+d)*NH + s0  )*5 + 0] + W1[((NIN+d)*NH + s0  )*5 + 1];
        float a1 = W1[((NIN+d)*NH + s0+1)*5 + 0] + W1[((NIN+d)*NH + s0+1)*5 + 1];
        Wa2[t] = packf2(a0, a1);
    } else {
        int e = t - 256;
        int r = e >> 4, c = e & 15;
        xj[r*17 + c] = x[(size_t)b*NN*NIN + (J+r)*NIN + c];
    }
    {
        int e = t;
        int tt = e >> 4, k = e & 15, s0 = 2*k;
        float w00 = W2[(tt*NH + s0  )*5 + 0], w01 = W2[(tt*NH + s0  )*5 + 1];
        float w10 = W2[(tt*NH + s0+1)*5 + 0], w11 = W2[(tt*NH + s0+1)*5 + 1];
        Wp2[e] = packf2(w00 + w01, w10 + w11);
        Wm2[e] = packf2(w00 - w01, w10 - w11);
    }
    {
        int e = t;
        int r = e >> 5, s = e & 31;
        posI[e] = g_R1 [((size_t)b*NN + I + r)*NH + s];
        posJ[e] = g_R1 [((size_t)b*NN + J + r)*NH + s];
        dgs[e]  = g_Dg1[((size_t)b*NN + I + r)*NH + s];
    }
    if (t < NH) t1s[t] = g_T1[b*NH + t];
    __syncthreads();

    // ---- phase 1: layer-1, 512 threads = (pair p, s-half sh1) ----
    {
        int p = t & 255, sh1 = t >> 8;
        int ii = p >> 4, jj = p & 15;
        int sb1 = sh1*16;
        bool dgflag = isdiag && (ii == jj);

        ull acc2[8];
        #pragma unroll
        for (int k = 0; k < 8; k++) acc2[k] = 0ull;
        #pragma unroll
        for (int d = 0; d < NIN; d++) {
            float zd = xi[ii*17 + d] * xj[jj*17 + d];
            ull zdup = packdup(zd);
            const ulonglong2* w = (const ulonglong2*)(Wa2 + d*16 + sh1*8);
            #pragma unroll
            for (int k4 = 0; k4 < 4; k4++) {
                ulonglong2 ww = w[k4];
                acc2[2*k4]   = ffma2(zdup, ww.x, acc2[2*k4]);
                acc2[2*k4+1] = ffma2(zdup, ww.y, acc2[2*k4+1]);
            }
        }
        #pragma unroll
        for (int k = 0; k < 8; k++) {
            float2 m = unpackf2(acc2[k]);
            int s0 = sb1 + 2*k, s1 = s0 + 1;
            float e0 = dgflag ? dgs[ii*NH + s0] : 0.f;
            float e1 = dgflag ? dgs[ii*NH + s1] : 0.f;
            float t0 = t1s[s0], t1v = t1s[s1];
            float c1lo = fmaxf(m.x + posI[ii*NH + s0] + t0 + e0, 0.f);
            float c1hi = fmaxf(m.y + posI[ii*NH + s1] + t1v + e1, 0.f);
            float c2lo = fmaxf(m.x + posJ[jj*NH + s0] + t0 + e0, 0.f);
            float c2hi = fmaxf(m.y + posJ[jj*NH + s1] + t1v + e1, 0.f);
            apS[p*17 + sh1*8 + k] = f2bf(c1lo + c2lo, c1hi + c2hi);
            amS[p*17 + sh1*8 + k] = f2bf(c1lo - c2lo, c1hi - c2hi);
        }
    }
    __syncthreads();

    // ---- rowsum partials + diag: 512 threads = (side, r, w16), both lanes ----
    {
        int side = t >> 8, e = t & 255;
        int r = e >> 4, w16 = e & 15;
        if (side == 0) {
            float lo = 0.f, hi = 0.f;
            #pragma unroll
            for (int q = 0; q < 16; q++) {
                float2 fa = bf2f(apS[(r*16 + q)*17 + w16]);
                float2 fm = bf2f(amS[(r*16 + q)*17 + w16]);
                lo += fa.x + fm.x;
                hi += fa.y + fm.y;
            }
            *(float2*)(g_rp + ((size_t)((b*NT + ti)*NT + tj))*512 + r*NH + 2*w16)
                = make_float2(0.5f*lo, 0.5f*hi);
        } else if (!isdiag) {
            float lo = 0.f, hi = 0.f;
            #pragma unroll
            for (int q = 0; q < 16; q++) {
                float2 fa = bf2f(apS[(q*16 + r)*17 + w16]);
                float2 fm = bf2f(amS[(q*16 + r)*17 + w16]);
                lo += fa.x - fm.x;
                hi += fa.y - fm.y;
            }
            *(float2*)(g_rp + ((size_t)((b*NT + tj)*NT + ti))*512 + r*NH + 2*w16)
                = make_float2(0.5f*lo, 0.5f*hi);
        } else {
            float2 fa = bf2f(apS[(r*16 + r)*17 + w16]);
            float2 fm = bf2f(amS[(r*16 + r)*17 + w16]);
            *(float2*)(g_diag + ((size_t)b*NN + I + r)*NH + 2*w16)
                = make_float2(0.5f*(fa.x + fm.x), 0.5f*(fa.y + fm.y));
        }
    }

    // ---- phase 2: GEMM, 2 pairs x 8 s per thread per pass ----
    {
        int duo = t & 127, sq = t >> 7;          // sq 0..3
        int sbq = sq*8;
        const unsigned int* paA = apS + duo*17;
        const unsigned int* paB = apS + (duo + 128)*17;
        const unsigned int* maA = amS + duo*17;
        const unsigned int* maB = amS + (duo + 128)*17;
        size_t growA = ((size_t)bid*256 + duo)*64;
        size_t growB = ((size_t)bid*256 + duo + 128)*64;

        {   // P pass
            ull aA[4], aB[4];
            #pragma unroll
            for (int k = 0; k < 4; k++) { aA[k] = 0ull; aB[k] = 0ull; }
            #pragma unroll 4
            for (int w16 = 0; w16 < 16; w16++) {
                float2 fA = bf2f(paA[w16]);
                float2 fB = bf2f(paB[w16]);
                #pragma unroll
                for (int h = 0; h < 2; h++) {
                    int tt = 2*w16 + h;
                    ull xA = packdup(h ? fA.y : fA.x);
                    ull xB = packdup(h ? fB.y : fB.x);
                    const ulonglong2* wp = (const ulonglong2*)(Wp2 + tt*16 + sq*4);
                    ulonglong2 w0 = wp[0], w1 = wp[1];
                    aA[0] = ffma2(xA, w0.x, aA[0]);
                    aA[1] = ffma2(xA, w0.y, aA[1]);
                    aA[2] = ffma2(xA, w1.x, aA[2]);
                    aA[3] = ffma2(xA, w1.y, aA[3]);
                    aB[0] = ffma2(xB, w0.x, aB[0]);
                    aB[1] = ffma2(xB, w0.y, aB[1]);
                    aB[2] = ffma2(xB, w1.x, aB[2]);
                    aB[3] = ffma2(xB, w1.y, aB[3]);
                }
            }
            unsigned int oA[4], oB[4];
            #pragma unroll
            for (int k = 0; k < 4; k++) {
                float2 PA = unpackf2(aA[k]);
                float2 PB = unpackf2(aB[k]);
                oA[k] = f2bf(0.5f*PA.x, 0.5f*PA.y);
                oB[k] = f2bf(0.5f*PB.x, 0.5f*PB.y);
            }
            *(uint4*)(g_G + growA + sbq) = make_uint4(oA[0], oA[1], oA[2], oA[3]);
            *(uint4*)(g_G + growB + sbq) = make_uint4(oB[0], oB[1], oB[2], oB[3]);
        }
        {   // M pass
            ull aA[4], aB[4];
            #pragma unroll
            for (int k = 0; k < 4; k++) { aA[k] = 0ull; aB[k] = 0ull; }
            #pragma unroll 4
            for (int w16 = 0; w16 < 16; w16++) {
                float2 fA = bf2f(maA[w16]);
                float2 fB = bf2f(maB[w16]);
                #pragma unroll
                for (int h = 0; h < 2; h++) {
                    int tt = 2*w16 + h;
                    ull xA = packdup(h ? fA.y : fA.x);
                    ull xB = packdup(h ? fB.y : fB.x);
                    const ulonglong2* wm = (const ulonglong2*)(Wm2 + tt*16 + sq*4);
                    ulonglong2 w0 = wm[0], w1 = wm[1];
                    aA[0] = ffma2(xA, w0.x, aA[0]);
                    aA[1] = ffma2(xA, w0.y, aA[1]);
                    aA[2] = ffma2(xA, w1.x, aA[2]);
                    aA[3] = ffma2(xA, w1.y, aA[3]);
                    aB[0] = ffma2(xB, w0.x, aB[0]);
                    aB[1] = ffma2(xB, w0.y, aB[1]);
                    aB[2] = ffma2(xB, w1.x, aB[2]);
                    aB[3] = ffma2(xB, w1.y, aB[3]);
                }
            }
            unsigned int oA[4], oB[4];
            #pragma unroll
            for (int k = 0; k < 4; k++) {
                float2 MA = unpackf2(aA[k]);
                float2 MB = unpackf2(aB[k]);
                oA[k] = f2bf(0.5f*MA.x, 0.5f*MA.y);
                oB[k] = f2bf(0.5f*MB.x, 0.5f*MB.y);
            }
            *(uint4*)(g_G + growA + 32 + sbq) = make_uint4(oA[0], oA[1], oA[2], oA[3]);
            *(uint4*)(g_G + growB + 32 + sbq) = make_uint4(oB[0], oB[1], oB[2], oB[3]);
        }
    }
}

// ============================================================
// P2: coalesced rowsum gather + layer-2 positional terms + T2 partials.
// ============================================================
__global__ void __launch_bounds__(256) p2_kernel(const float* __restrict__ W2) {
    int ti = blockIdx.x, b = blockIdx.y, t = threadIdx.x;
    __shared__ float Ws3[NH*NH], Ws2s[NH*NH], Ws4[NH*NH];
    __shared__ float raS[16*33], dvS[16*33];
    __shared__ float totS[NH];

    for (int e = t; e < NH*NH; e += 256) {
        Ws3[e]  = W2[e*5 + 3];
        Ws2s[e] = W2[e*5 + 2];
        Ws4[e]  = W2[e*5 + 4];
    }

    int ii = t >> 4, sp = t & 15;
    float2 acc = make_float2(0.f, 0.f);
    const float* base = g_rp + (size_t)(b*NT + ti)*NT*512 + ii*NH + 2*sp;
    #pragma unroll
    for (int tj = 0; tj < NT; tj++) {
        float2 v = *(const float2*)(base + tj*512);
        acc.x += v.x; acc.y += v.y;
    }
    raS[ii*33 + 2*sp] = acc.x; raS[ii*33 + 2*sp + 1] = acc.y;
    {
        float2 dv = *(const float2*)(g_diag + ((size_t)b*NN + ti*16 + ii)*NH + 2*sp);
        dvS[ii*33 + 2*sp] = dv.x; dvS[ii*33 + 2*sp + 1] = dv.y;
    }
    __syncthreads();

    if (t < NH) {
        float s = 0.f;
        #pragma unroll
        for (int r = 0; r < 16; r++) s += raS[r*33 + t];
        totS[t] = s;
    }
    __syncthreads();
    if (t < NH) {
        float a = 0.f;
        #pragma unroll
        for (int q = 0; q < NH; q++) a = fmaf(totS[q], Ws4[q*NH + t], a);
        g_t2p[(b*NT + ti)*NH + t] = a;
    }

    const float inv_n = 1.0f/(float)NN;
    int s0 = t & 15;
    float r2a = 0.f, r2b = 0.f, d2a = 0.f, d2b = 0.f;
    #pragma unroll
    for (int q = 0; q < NH; q++) {
        float rq = raS[ii*33 + q]*inv_n;
        float dq = dvS[ii*33 + q];
        r2a = fmaf(rq, Ws3[q*NH + s0],      r2a);
        r2b = fmaf(rq, Ws3[q*NH + s0 + 16], r2b);
        d2a = fmaf(dq, Ws2s[q*NH + s0],      d2a);
        d2b = fmaf(dq, Ws2s[q*NH + s0 + 16], d2b);
    }
    size_t ro = ((size_t)b*NN + ti*16 + ii)*NH;
    g_R2 [ro + s0]      = r2a;
    g_R2 [ro + s0 + 16] = r2b;
    g_Dg2[ro + s0]      = d2a;
    g_Dg2[ro + s0 + 16] = d2b;
}

// ============================================================
// K2B: streaming epilogue — pair-form G, cheap T2 sum, conflict-free reduce.
// ============================================================
__global__ void __launch_bounds__(256) k2b_kernel(const float* __restrict__ b2) {
    __shared__ float bs1[512], bs2[512], dgI[512];
    __shared__ float t2s[NH];
    __shared__ float red[256*33];
    __shared__ float part2[8*NH];

    int tp = blockIdx.x, b = blockIdx.y, t = threadIdx.x;
    int ti = 0, rr0 = tp;
    while (rr0 >= NT - ti) { rr0 -= NT - ti; ti++; }
    int tj = ti + rr0;
    int I = ti*TILE, J = tj*TILE;
    int bid = b*NTRI + tp;
    bool isdiag = (ti == tj);

    for (int e = t; e < 512; e += 256) {
        int r = e >> 5, s = e & 31;
        bs1[e] = g_R2[((size_t)b*NN + I + r)*NH + s];
        bs2[e] = g_R2[((size_t)b*NN + J + r)*NH + s];
        dgI[e] = g_Dg2[((size_t)b*NN + I + r)*NH + s];
    }
    if (t < NH) {
        const float inv_n2 = 1.0f/((float)NN*(float)NN);
        float a = 0.f;
        #pragma unroll
        for (int k = 0; k < NT; k++) a += g_t2p[(b*NT + k)*NH + t];
        t2s[t] = b2[t] + a*inv_n2;
    }
    __syncthreads();

    int ii = t >> 4, jj = t & 15;
    const uint4* g = (const uint4*)(g_G + ((size_t)bid*256 + t)*64);
    uint4 qp[4], qm[4];
    #pragma unroll
    for (int v4 = 0; v4 < 4; v4++) { qp[v4] = g[v4]; qm[v4] = g[v4 + 4]; }

    float cs[NH];
    #pragma unroll
    for (int v4 = 0; v4 < 4; v4++) {
        unsigned int up[4] = {qp[v4].x, qp[v4].y, qp[v4].z, qp[v4].w};
        unsigned int um[4] = {qm[v4].x, qm[v4].y, qm[v4].z, qm[v4].w};
        #pragma unroll
        for (int u = 0; u < 4; u++) {
            int s0 = v4*8 + 2*u;
            float2 fp = bf2f(up[u]);
            float2 fm = bf2f(um[u]);
            #pragma unroll
            for (int h = 0; h < 2; h++) {
                int s = s0 + h;
                float pv = h ? fp.y : fp.x;
                float mv = h ? fm.y : fm.x;
                float b1v = bs1[ii*NH + s] + t2s[s];
                if (isdiag && ii == jj) b1v += dgI[ii*NH + s];
                float c1 = fmaxf(pv + mv + b1v, 0.f);
                float c2 = fmaxf(pv - mv + bs2[jj*NH + s] + t2s[s], 0.f);
                float v = c1 + c2;
                if (isdiag) v = (ii < jj) ? (c1 + c2) : ((ii == jj) ? c1 : 0.f);
                cs[s] = v;
            }
        }
    }

    #pragma unroll
    for (int s = 0; s < NH; s++) red[t*33 + s] = cs[s];
    __syncthreads();
    {
        int s = t & 31, c = t >> 5;
        float tsum = 0.f;
        #pragma unroll
        for (int r = 0; r < 32; r++) tsum += red[(c*32 + r)*33 + s];
        part2[c*NH + s] = tsum;
    }
    __syncthreads();
    if (t < NH) {
        float p = 0.f;
        #pragma unroll
        for (int c = 0; c < 8; c++) p += part2[c*NH + t];
        g_part[(size_t)bid*NH + t] = p;
    }
}

// ============================================================
// Final: parallel partial reduce + MLP 32->128->128->1.
// ============================================================
__global__ void __launch_bounds__(256) fin_kernel(const float* __restrict__ D1,
                                                  const float* __restrict__ db1,
                                                  const float* __restrict__ D2,
                                                  const float* __restrict__ db2,
                                                  const float* __restrict__ D3,
                                                  const float* __restrict__ db3,
                                                  float* __restrict__ out) {
    int b = blockIdx.x, tid = threadIdx.x;
    __shared__ float pp[8*NH];
    __shared__ float p[NH];
    __shared__ float m1[128];
    __shared__ float h2p[256];
    __shared__ float m2[128];
    __shared__ float wr[4];

    {
        int s = tid & 31, c = tid >> 5;
        float a = 0.f;
        #pragma unroll 4
        for (int k = c; k < NTRI; k += 8) a += g_part[(size_t)(b*NTRI + k)*NH + s];
        pp[tid] = a;
    }
    __syncthreads();
    if (tid < NH) {
        float t = 0.f;
        #pragma unroll
        for (int c = 0; c < 8; c++) t += pp[c*NH + tid];
        p[tid] = fmaxf(t, 0.f);
    }
    __syncthreads();
    if (tid < 128) {
        float a = db1[tid];
        #pragma unroll
        for (int q = 0; q < NH; q++) a = fmaf(p[q], D1[q*128 + tid], a);
        m1[tid] = fmaxf(a, 0.f);
    }
    __syncthreads();
    {
        int o = tid & 127, half = tid >> 7;
        float a = 0.f;
        #pragma unroll 16
        for (int e = half*64; e < half*64 + 64; e++)
            a = fmaf(m1[e], D2[e*128 + o], a);
        h2p[tid] = a;
    }
    __syncthreads();
    if (tid < 128) m2[tid] = fmaxf(h2p[tid] + h2p[128 + tid] + db2[tid], 0.f);
    __syncthreads();
    if (tid < 128) {
        float v = m2[tid] * D3[tid];
        #pragma unroll
        for (int o = 16; o; o >>= 1) v += __shfl_xor_sync(0xffffffffu, v, o);
        if ((tid & 31) == 0) wr[tid >> 5] = v;
    }
    __syncthreads();
    if (tid == 0) out[b] = wr[0] + wr[1] + wr[2] + wr[3] + db3[0];
}

extern "C" void kernel_launch(void* const* d_in, const int* in_sizes, int n_in,
                              void* d_out, int out_size) {
    const float* x   = (const float*)d_in[0];
    const float* W1  = (const float*)d_in[1];
    const float* b1  = (const float*)d_in[2];
    const float* W2  = (const float*)d_in[3];
    const float* b2  = (const float*)d_in[4];
    const float* D1  = (const float*)d_in[5];
    const float* db1 = (const float*)d_in[6];
    const float* D2  = (const float*)d_in[7];
    const float* db2 = (const float*)d_in[8];
    const float* D3  = (const float*)d_in[9];
    const float* db3 = (const float*)d_in[10];
    float* out = (float*)d_out;

    size_t k1f_smem = 53504;
    cudaFuncSetAttribute(k1f_kernel, cudaFuncAttributeMaxDynamicSharedMemorySize,
                         (int)k1f_smem);

    p1_kernel<<<dim3(NT, NB), 256>>>(x, W1, b1);                // 1
    k1f_kernel<<<dim3(NTRI, NB), 512, k1f_smem>>>(x, W1, W2);   // 2
    p2_kernel<<<dim3(NT, NB), 256>>>(W2);                       // 3
    k2b_kernel<<<dim3(NTRI, NB), 256>>>(b2);                    // 4 -> profiled
    fin_kernel<<<NB, 256>>>(D1, db1, D2, db2, D3, db3, out);    // 5
}

// round 13
// speedup vs baseline: 1.9503x; 1.2017x over previous
#include <cuda_runtime.h>
#include <cuda_bf16.h>
#include <cstdint>

#define NB   8
#define NN   256
#define NIN  16
#define NH   32
#define TILE 16
#define NT   (NN/TILE)          // 16
#define NTRI (NT*(NT+1)/2)      // 136
#define NBLK2 (NB*NTRI)         // 1088
#define STR  20                 // apS/amS row stride (words): 80B, 16B-aligned, phase-disjoint

typedef unsigned long long ull;

// ---- packed f32x2 helpers ----
__device__ __forceinline__ ull packf2(float lo, float hi) {
    ull r; asm("mov.b64 %0, {%1, %2};" : "=l"(r) : "f"(lo), "f"(hi)); return r;
}
__device__ __forceinline__ ull packdup(float v) {
    ull r; asm("mov.b64 %0, {%1, %1};" : "=l"(r) : "f"(v)); return r;
}
__device__ __forceinline__ ull ffma2(ull a, ull b, ull c) {
    ull d; asm("fma.rn.f32x2 %0, %1, %2, %3;" : "=l"(d) : "l"(a), "l"(b), "l"(c)); return d;
}
__device__ __forceinline__ float2 unpackf2(ull v) {
    float lo, hi; asm("mov.b64 {%0, %1}, %2;" : "=f"(lo), "=f"(hi) : "l"(v));
    return make_float2(lo, hi);
}
__device__ __forceinline__ float2 bf2f(unsigned int u) {
    return __bfloat1622float2(*reinterpret_cast<__nv_bfloat162*>(&u));
}
__device__ __forceinline__ unsigned int f2bf(float a, float b) {
    __nv_bfloat162 h = __floats2bfloat162_rn(a, b);
    return *reinterpret_cast<unsigned int*>(&h);
}

// ---- scratch (device globals) ----
__device__ __nv_bfloat16 g_G[(size_t)NB*NTRI*256*64];   // 35.6 MB pair-form rows
__device__ float g_R1[NB*NN*NH];
__device__ float g_Dg1[NB*NN*NH];
__device__ float g_T1[NB*NH];
__device__ float g_rp[(size_t)NB*NT*NT*512];            // 4 MB rowsum partials
__device__ float g_diag[NB*NN*NH];
__device__ float g_R2[NB*NN*NH];
__device__ float g_Dg2[NB*NN*NH];
__device__ float g_t2p[NB*NT*NH];                       // per-tile T2 partials
__device__ float g_part[(size_t)NBLK2*NH];

// ============================================================
// P1: parallel positional precompute. grid (NT, NB).
// ============================================================
__global__ void __launch_bounds__(256) p1_kernel(const float* __restrict__ x,
                                                 const float* __restrict__ W1,
                                                 const float* __restrict__ b1) {
    int ti = blockIdx.x, b = blockIdx.y, t = threadIdx.x;
    __shared__ float xs[NN*17];
    __shared__ float Ws[NH*NH*5];
    __shared__ float part[16*16];
    __shared__ float Ss[NIN];

    const float4* xg = (const float4*)(x + (size_t)b*NN*NIN);
    for (int e = t; e < NN*NIN/4; e += 256) {
        float4 v = xg[e];
        int r = e >> 2, c0 = (e & 3)*4;
        float* dst = xs + r*17 + c0;
        dst[0] = v.x; dst[1] = v.y; dst[2] = v.z; dst[3] = v.w;
    }
    for (int e = t; e < NH*NH*5; e += 256) Ws[e] = W1[e];
    __syncthreads();

    {
        int ch = t >> 4, d = t & 15;
        float s = 0.f;
        #pragma unroll
        for (int r = 0; r < 16; r++) s += xs[(ch*16 + r)*17 + d];
        part[ch*16 + d] = s;
    }
    __syncthreads();
    if (t < NIN) {
        float s = 0.f;
        #pragma unroll
        for (int ch = 0; ch < 16; ch++) s += part[ch*16 + t];
        Ss[t] = s;
    }
    __syncthreads();

    const float inv_n = 1.0f/(float)NN, inv_n2 = inv_n*inv_n;
    #pragma unroll
    for (int it = 0; it < 2; it++) {
        int item = t + it*256;
        int r = item >> 5, s = item & 31;
        int i = ti*16 + r;
        float rv = 0.f, dg = 0.f;
        #pragma unroll
        for (int d = 0; d < NIN; d++) {
            float xi = xs[i*17 + d];
            const float* wd  = &Ws[(d*NH + s)*5];
            const float* wd2 = &Ws[((NIN+d)*NH + s)*5];
            rv += xi*wd[3] + xi*Ss[d]*wd2[3];
            dg += xi*(wd[0] + wd[1] + wd[2]) + xi*xi*wd2[2];
        }
        g_R1 [((size_t)b*NN + i)*NH + s] = rv*inv_n;
        g_Dg1[((size_t)b*NN + i)*NH + s] = dg;
    }
    if (ti == 0 && t < NH) {
        int s = t;
        float tv = b1[s];
        #pragma unroll
        for (int d = 0; d < NIN; d++) {
            tv += Ss[d]*inv_n2       * Ws[(d*NH + s)*5 + 4];
            tv += Ss[d]*Ss[d]*inv_n2 * Ws[((NIN+d)*NH + s)*5 + 4];
        }
        g_T1[b*NH + s] = tv;
    }
}

// ============================================================
// K1F: fused layer-1 + layer-2 GEMM. Positional arrays padded to
// stride 36 (conflict-free float4 row loads); apS/amS stride 20
// (vectorized phase-1 stores + GEMM A loads).
// ============================================================
__global__ void __launch_bounds__(512, 2) k1f_kernel(const float* __restrict__ x,
                                                     const float* __restrict__ W1,
                                                     const float* __restrict__ W2) {
    extern __shared__ __align__(16) char smraw[];
    ull*   Wa2 = (ull*)smraw;                       // 256 ull @0
    ull*   Wp2 = Wa2 + 256;                         // 512 ull @2048
    ull*   Wm2 = Wp2 + 512;                         // 512 ull @6144
    float* xi   = (float*)(Wm2 + 512);              // 272 @10240
    float* xj   = xi + 272;                         // 272
    float* posI = xj + 272;                         // 16*36 = 576
    float* posJ = posI + 576;                       // 576
    float* dgs  = posJ + 576;                       // 576
    float* t1s  = dgs + 576;                        // 32
    unsigned int* apS = (unsigned int*)(t1s + 32);  // 256*20
    unsigned int* amS = apS + 256*STR;              // 256*20
    // total: 10240 + 1088*2 + 2304*3 + 128 + 20480*2 = 60416 B

    int tp = blockIdx.x, b = blockIdx.y, t = threadIdx.x;
    int ti = 0, rr0 = tp;
    while (rr0 >= NT - ti) { rr0 -= NT - ti; ti++; }
    int tj = ti + rr0;
    int I = ti*TILE, J = tj*TILE;
    int bid = b*NTRI + tp;
    bool isdiag = (ti == tj);

    if (t < 256) {
        int r = t >> 4, c = t & 15;
        xi[r*17 + c] = x[(size_t)b*NN*NIN + (I+r)*NIN + c];
        int d = r, k = c, s0 = 2*k;
        float a0 = W1[((NIN+d)*NH + s0  )*5 + 0] + W1[((NIN+d)*NH + s0  )*5 + 1];
        float a1 = W1[((NIN+d)*NH + s0+1)*5 + 0] + W1[((NIN+d)*NH + s0+1)*5 + 1];
        Wa2[t] = packf2(a0, a1);
    } else {
        int e = t - 256;
        int r = e >> 4, c = e & 15;
        xj[r*17 + c] = x[(size_t)b*NN*NIN + (J+r)*NIN + c];
    }
    {
        int e = t;
        int tt = e >> 4, k = e & 15, s0 = 2*k;
        float w00 = W2[(tt*NH + s0  )*5 + 0], w01 = W2[(tt*NH + s0  )*5 + 1];
        float w10 = W2[(tt*NH + s0+1)*5 + 0], w11 = W2[(tt*NH + s0+1)*5 + 1];
        Wp2[e] = packf2(w00 + w01, w10 + w11);
        Wm2[e] = packf2(w00 - w01, w10 - w11);
    }
    {
        int e = t;
        int r = e >> 5, s = e & 31;
        posI[r*36 + s] = g_R1 [((size_t)b*NN + I + r)*NH + s];
        posJ[r*36 + s] = g_R1 [((size_t)b*NN + J + r)*NH + s];
        dgs [r*36 + s] = g_Dg1[((size_t)b*NN + I + r)*NH + s];
    }
    if (t < NH) t1s[t] = g_T1[b*NH + t];
    __syncthreads();

    // ---- phase 1: layer-1, 512 threads = (pair p, s-half sh1) ----
    {
        int p = t & 255, sh1 = t >> 8;
        int ii = p >> 4, jj = p & 15;
        int sb1 = sh1*16;
        bool dgflag = isdiag && (ii == jj);

        ull acc2[8];
        #pragma unroll
        for (int k = 0; k < 8; k++) acc2[k] = 0ull;
        #pragma unroll
        for (int d = 0; d < NIN; d++) {
            float zd = xi[ii*17 + d] * xj[jj*17 + d];
            ull zdup = packdup(zd);
            const ulonglong2* w = (const ulonglong2*)(Wa2 + d*16 + sh1*8);
            #pragma unroll
            for (int k4 = 0; k4 < 4; k4++) {
                ulonglong2 ww = w[k4];
                acc2[2*k4]   = ffma2(zdup, ww.x, acc2[2*k4]);
                acc2[2*k4+1] = ffma2(zdup, ww.y, acc2[2*k4+1]);
            }
        }

        // vectorized positional row loads (stride 36 -> 2-way max)
        float pI[16], pJ[16];
        {
            const float4* pIr = (const float4*)(posI + ii*36 + sb1);
            const float4* pJr = (const float4*)(posJ + jj*36 + sb1);
            #pragma unroll
            for (int q = 0; q < 4; q++) {
                float4 a = pIr[q]; float4 c = pJr[q];
                pI[4*q] = a.x; pI[4*q+1] = a.y; pI[4*q+2] = a.z; pI[4*q+3] = a.w;
                pJ[4*q] = c.x; pJ[4*q+1] = c.y; pJ[4*q+2] = c.z; pJ[4*q+3] = c.w;
            }
        }

        unsigned int oa[8], om[8];
        #pragma unroll
        for (int k = 0; k < 8; k++) {
            float2 m = unpackf2(acc2[k]);
            int s0 = sb1 + 2*k, s1 = s0 + 1;
            float e0 = dgflag ? dgs[ii*36 + s0] : 0.f;
            float e1 = dgflag ? dgs[ii*36 + s1] : 0.f;
            float t0 = t1s[s0], t1v = t1s[s1];
            float c1lo = fmaxf(m.x + pI[2*k]   + t0 + e0, 0.f);
            float c1hi = fmaxf(m.y + pI[2*k+1] + t1v + e1, 0.f);
            float c2lo = fmaxf(m.x + pJ[2*k]   + t0 + e0, 0.f);
            float c2hi = fmaxf(m.y + pJ[2*k+1] + t1v + e1, 0.f);
            oa[k] = f2bf(c1lo + c2lo, c1hi + c2hi);
            om[k] = f2bf(c1lo - c2lo, c1hi - c2hi);
        }
        *(uint4*)(apS + p*STR + sh1*8)     = make_uint4(oa[0], oa[1], oa[2], oa[3]);
        *(uint4*)(apS + p*STR + sh1*8 + 4) = make_uint4(oa[4], oa[5], oa[6], oa[7]);
        *(uint4*)(amS + p*STR + sh1*8)     = make_uint4(om[0], om[1], om[2], om[3]);
        *(uint4*)(amS + p*STR + sh1*8 + 4) = make_uint4(om[4], om[5], om[6], om[7]);
    }
    __syncthreads();

    // ---- rowsum partials + diag: 512 threads = (side, r, w16), both lanes ----
    {
        int side = t >> 8, e = t & 255;
        int r = e >> 4, w16 = e & 15;
        if (side == 0) {
            float lo = 0.f, hi = 0.f;
            #pragma unroll
            for (int q = 0; q < 16; q++) {
                float2 fa = bf2f(apS[(r*16 + q)*STR + w16]);
                float2 fm = bf2f(amS[(r*16 + q)*STR + w16]);
                lo += fa.x + fm.x;
                hi += fa.y + fm.y;
            }
            *(float2*)(g_rp + ((size_t)((b*NT + ti)*NT + tj))*512 + r*NH + 2*w16)
                = make_float2(0.5f*lo, 0.5f*hi);
        } else if (!isdiag) {
            float lo = 0.f, hi = 0.f;
            #pragma unroll
            for (int q = 0; q < 16; q++) {
                float2 fa = bf2f(apS[(q*16 + r)*STR + w16]);
                float2 fm = bf2f(amS[(q*16 + r)*STR + w16]);
                lo += fa.x - fm.x;
                hi += fa.y - fm.y;
            }
            *(float2*)(g_rp + ((size_t)((b*NT + tj)*NT + ti))*512 + r*NH + 2*w16)
                = make_float2(0.5f*lo, 0.5f*hi);
        } else {
            float2 fa = bf2f(apS[(r*16 + r)*STR + w16]);
            float2 fm = bf2f(amS[(r*16 + r)*STR + w16]);
            *(float2*)(g_diag + ((size_t)b*NN + I + r)*NH + 2*w16)
                = make_float2(0.5f*(fa.x + fm.x), 0.5f*(fa.y + fm.y));
        }
    }

    // ---- phase 2: GEMM, 2 pairs x 8 s per thread; vectorized A loads ----
    {
        int duo = t & 127, sq = t >> 7;
        int sbq = sq*8;
        const uint4* pa4A = (const uint4*)(apS + duo*STR);
        const uint4* pa4B = (const uint4*)(apS + (duo + 128)*STR);
        const uint4* ma4A = (const uint4*)(amS + duo*STR);
        const uint4* ma4B = (const uint4*)(amS + (duo + 128)*STR);
        size_t growA = ((size_t)bid*256 + duo)*64;
        size_t growB = ((size_t)bid*256 + duo + 128)*64;

        {   // P pass
            ull aA[4], aB[4];
            #pragma unroll
            for (int k = 0; k < 4; k++) { aA[k] = 0ull; aB[k] = 0ull; }
            #pragma unroll
            for (int g = 0; g < 4; g++) {
                uint4 vA = pa4A[g], vB = pa4B[g];
                unsigned int wA[4] = {vA.x, vA.y, vA.z, vA.w};
                unsigned int wB[4] = {vB.x, vB.y, vB.z, vB.w};
                #pragma unroll
                for (int u = 0; u < 4; u++) {
                    float2 fA = bf2f(wA[u]);
                    float2 fB = bf2f(wB[u]);
                    int w16 = 4*g + u;
                    #pragma unroll
                    for (int h = 0; h < 2; h++) {
                        int tt = 2*w16 + h;
                        ull xA = packdup(h ? fA.y : fA.x);
                        ull xB = packdup(h ? fB.y : fB.x);
                        const ulonglong2* wp = (const ulonglong2*)(Wp2 + tt*16 + sq*4);
                        ulonglong2 w0 = wp[0], w1 = wp[1];
                        aA[0] = ffma2(xA, w0.x, aA[0]);
                        aA[1] = ffma2(xA, w0.y, aA[1]);
                        aA[2] = ffma2(xA, w1.x, aA[2]);
                        aA[3] = ffma2(xA, w1.y, aA[3]);
                        aB[0] = ffma2(xB, w0.x, aB[0]);
                        aB[1] = ffma2(xB, w0.y, aB[1]);
                        aB[2] = ffma2(xB, w1.x, aB[2]);
                        aB[3] = ffma2(xB, w1.y, aB[3]);
                    }
                }
            }
            unsigned int oA[4], oB[4];
            #pragma unroll
            for (int k = 0; k < 4; k++) {
                float2 PA = unpackf2(aA[k]);
                float2 PB = unpackf2(aB[k]);
                oA[k] = f2bf(0.5f*PA.x, 0.5f*PA.y);
                oB[k] = f2bf(0.5f*PB.x, 0.5f*PB.y);
            }
            *(uint4*)(g_G + growA + sbq) = make_uint4(oA[0], oA[1], oA[2], oA[3]);
            *(uint4*)(g_G + growB + sbq) = make_uint4(oB[0], oB[1], oB[2], oB[3]);
        }
        {   // M pass
            ull aA[4], aB[4];
            #pragma unroll
            for (int k = 0; k < 4; k++) { aA[k] = 0ull; aB[k] = 0ull; }
            #pragma unroll
            for (int g = 0; g < 4; g++) {
                uint4 vA = ma4A[g], vB = ma4B[g];
                unsigned int wA[4] = {vA.x, vA.y, vA.z, vA.w};
                unsigned int wB[4] = {vB.x, vB.y, vB.z, vB.w};
                #pragma unroll
                for (int u = 0; u < 4; u++) {
                    float2 fA = bf2f(wA[u]);
                    float2 fB = bf2f(wB[u]);
                    int w16 = 4*g + u;
                    #pragma unroll
                    for (int h = 0; h < 2; h++) {
                        int tt = 2*w16 + h;
                        ull xA = packdup(h ? fA.y : fA.x);
                        ull xB = packdup(h ? fB.y : fB.x);
                        const ulonglong2* wm = (const ulonglong2*)(Wm2 + tt*16 + sq*4);
                        ulonglong2 w0 = wm[0], w1 = wm[1];
                        aA[0] = ffma2(xA, w0.x, aA[0]);
                        aA[1] = ffma2(xA, w0.y, aA[1]);
                        aA[2] = ffma2(xA, w1.x, aA[2]);
                        aA[3] = ffma2(xA, w1.y, aA[3]);
                        aB[0] = ffma2(xB, w0.x, aB[0]);
                        aB[1] = ffma2(xB, w0.y, aB[1]);
                        aB[2] = ffma2(xB, w1.x, aB[2]);
                        aB[3] = ffma2(xB, w1.y, aB[3]);
                    }
                }
            }
            unsigned int oA[4], oB[4];
            #pragma unroll
            for (int k = 0; k < 4; k++) {
                float2 MA = unpackf2(aA[k]);
                float2 MB = unpackf2(aB[k]);
                oA[k] = f2bf(0.5f*MA.x, 0.5f*MA.y);
                oB[k] = f2bf(0.5f*MB.x, 0.5f*MB.y);
            }
            *(uint4*)(g_G + growA + 32 + sbq) = make_uint4(oA[0], oA[1], oA[2], oA[3]);
            *(uint4*)(g_G + growB + 32 + sbq) = make_uint4(oB[0], oB[1], oB[2], oB[3]);
        }
    }
}

// ============================================================
// P2: coalesced rowsum gather + layer-2 positional terms + T2 partials.
// ============================================================
__global__ void __launch_bounds__(256) p2_kernel(const float* __restrict__ W2) {
    int ti = blockIdx.x, b = blockIdx.y, t = threadIdx.x;
    __shared__ float Ws3[NH*NH], Ws2s[NH*NH], Ws4[NH*NH];
    __shared__ float raS[16*33], dvS[16*33];
    __shared__ float totS[NH];

    for (int e = t; e < NH*NH; e += 256) {
        Ws3[e]  = W2[e*5 + 3];
        Ws2s[e] = W2[e*5 + 2];
        Ws4[e]  = W2[e*5 + 4];
    }

    int ii = t >> 4, sp = t & 15;
    float2 acc = make_float2(0.f, 0.f);
    const float* base = g_rp + (size_t)(b*NT + ti)*NT*512 + ii*NH + 2*sp;
    #pragma unroll
    for (int tj = 0; tj < NT; tj++) {
        float2 v = *(const float2*)(base + tj*512);
        acc.x += v.x; acc.y += v.y;
    }
    raS[ii*33 + 2*sp] = acc.x; raS[ii*33 + 2*sp + 1] = acc.y;
    {
        float2 dv = *(const float2*)(g_diag + ((size_t)b*NN + ti*16 + ii)*NH + 2*sp);
        dvS[ii*33 + 2*sp] = dv.x; dvS[ii*33 + 2*sp + 1] = dv.y;
    }
    __syncthreads();

    if (t < NH) {
        float s = 0.f;
        #pragma unroll
        for (int r = 0; r < 16; r++) s += raS[r*33 + t];
        totS[t] = s;
    }
    __syncthreads();
    if (t < NH) {
        float a = 0.f;
        #pragma unroll
        for (int q = 0; q < NH; q++) a = fmaf(totS[q], Ws4[q*NH + t], a);
        g_t2p[(b*NT + ti)*NH + t] = a;
    }

    const float inv_n = 1.0f/(float)NN;
    int s0 = t & 15;
    float r2a = 0.f, r2b = 0.f, d2a = 0.f, d2b = 0.f;
    #pragma unroll
    for (int q = 0; q < NH; q++) {
        float rq = raS[ii*33 + q]*inv_n;
        float dq = dvS[ii*33 + q];
        r2a = fmaf(rq, Ws3[q*NH + s0],      r2a);
        r2b = fmaf(rq, Ws3[q*NH + s0 + 16], r2b);
        d2a = fmaf(dq, Ws2s[q*NH + s0],      d2a);
        d2b = fmaf(dq, Ws2s[q*NH + s0 + 16], d2b);
    }
    size_t ro = ((size_t)b*NN + ti*16 + ii)*NH;
    g_R2 [ro + s0]      = r2a;
    g_R2 [ro + s0 + 16] = r2b;
    g_Dg2[ro + s0]      = d2a;
    g_Dg2[ro + s0 + 16] = d2b;
}

// ============================================================
// K2B: streaming epilogue. Positional rows padded to stride 36,
// loaded as float4 (kills the 16-way bs2 bank conflict); T2 folded
// into staging.
// ============================================================
__global__ void __launch_bounds__(256) k2b_kernel(const float* __restrict__ b2) {
    __shared__ float bs1[16*36], bs2[16*36], dgI[16*36];
    __shared__ float t2s[NH];
    __shared__ float red[256*33];
    __shared__ float part2[8*NH];

    int tp = blockIdx.x, b = blockIdx.y, t = threadIdx.x;
    int ti = 0, rr0 = tp;
    while (rr0 >= NT - ti) { rr0 -= NT - ti; ti++; }
    int tj = ti + rr0;
    int I = ti*TILE, J = tj*TILE;
    int bid = b*NTRI + tp;
    bool isdiag = (ti == tj);

    if (t < NH) {
        const float inv_n2 = 1.0f/((float)NN*(float)NN);
        float a = 0.f;
        #pragma unroll
        for (int k = 0; k < NT; k++) a += g_t2p[(b*NT + k)*NH + t];
        t2s[t] = b2[t] + a*inv_n2;
    }
    __syncthreads();
    for (int e = t; e < 512; e += 256) {
        int r = e >> 5, s = e & 31;
        float t2v = t2s[s];
        bs1[r*36 + s] = g_R2[((size_t)b*NN + I + r)*NH + s] + t2v;
        bs2[r*36 + s] = g_R2[((size_t)b*NN + J + r)*NH + s] + t2v;
        dgI[r*36 + s] = g_Dg2[((size_t)b*NN + I + r)*NH + s];
    }
    __syncthreads();

    int ii = t >> 4, jj = t & 15;
    bool dflag = isdiag && (ii == jj);
    const uint4* g = (const uint4*)(g_G + ((size_t)bid*256 + t)*64);
    uint4 qp[4], qm[4];
    #pragma unroll
    for (int v4 = 0; v4 < 4; v4++) { qp[v4] = g[v4]; qm[v4] = g[v4 + 4]; }

    const float4* b1r = (const float4*)(bs1 + ii*36);
    const float4* b2r = (const float4*)(bs2 + jj*36);

    #pragma unroll
    for (int v4 = 0; v4 < 4; v4++) {
        float4 ba0 = b1r[2*v4], ba1 = b1r[2*v4 + 1];
        float4 bb0 = b2r[2*v4], bb1 = b2r[2*v4 + 1];
        float b1a[8] = {ba0.x, ba0.y, ba0.z, ba0.w, ba1.x, ba1.y, ba1.z, ba1.w};
        float b2a[8] = {bb0.x, bb0.y, bb0.z, bb0.w, bb1.x, bb1.y, bb1.z, bb1.w};
        unsigned int up[4] = {qp[v4].x, qp[v4].y, qp[v4].z, qp[v4].w};
        unsigned int um[4] = {qm[v4].x, qm[v4].y, qm[v4].z, qm[v4].w};
        #pragma unroll
        for (int u = 0; u < 4; u++) {
            float2 fp = bf2f(up[u]);
            float2 fm = bf2f(um[u]);
            #pragma unroll
            for (int h = 0; h < 2; h++) {
                int m = 2*u + h;
                int s = v4*8 + m;
                float pv = h ? fp.y : fp.x;
                float mv = h ? fm.y : fm.x;
                float b1v = b1a[m];
                if (dflag) b1v += dgI[ii*36 + s];
                float c1 = fmaxf(pv + mv + b1v, 0.f);
                float c2 = fmaxf(pv - mv + b2a[m], 0.f);
                float v = c1 + c2;
                if (isdiag) v = (ii < jj) ? (c1 + c2) : ((ii == jj) ? c1 : 0.f);
                red[t*33 + s] = v;
            }
        }
    }
    __syncthreads();
    {
        int s = t & 31, c = t >> 5;
        float tsum = 0.f;
        #pragma unroll
        for (int r = 0; r < 32; r++) tsum += red[(c*32 + r)*33 + s];
        part2[c*NH + s] = tsum;
    }
    __syncthreads();
    if (t < NH) {
        float p = 0.f;
        #pragma unroll
        for (int c = 0; c < 8; c++) p += part2[c*NH + t];
        g_part[(size_t)bid*NH + t] = p;
    }
}

// ============================================================
// Final: parallel partial reduce + MLP 32->128->128->1.
// ============================================================
__global__ void __launch_bounds__(256) fin_kernel(const float* __restrict__ D1,
                                                  const float* __restrict__ db1,
                                                  const float* __restrict__ D2,
                                                  const float* __restrict__ db2,
                                                  const float* __restrict__ D3,
                                                  const float* __restrict__ db3,
                                                  float* __restrict__ out) {
    int b = blockIdx.x, tid = threadIdx.x;
    __shared__ float pp[8*NH];
    __shared__ float p[NH];
    __shared__ float m1[128];
    __shared__ float h2p[256];
    __shared__ float m2[128];
    __shared__ float wr[4];

    {
        int s = tid & 31, c = tid >> 5;
        float a = 0.f;
        #pragma unroll 4
        for (int k = c; k < NTRI; k += 8) a += g_part[(size_t)(b*NTRI + k)*NH + s];
        pp[tid] = a;
    }
    __syncthreads();
    if (tid < NH) {
        float t = 0.f;
        #pragma unroll
        for (int c = 0; c < 8; c++) t += pp[c*NH + tid];
        p[tid] = fmaxf(t, 0.f);
    }
    __syncthreads();
    if (tid < 128) {
        float a = db1[tid];
        #pragma unroll
        for (int q = 0; q < NH; q++) a = fmaf(p[q], D1[q*128 + tid], a);
        m1[tid] = fmaxf(a, 0.f);
    }
    __syncthreads();
    {
        int o = tid & 127, half = tid >> 7;
        float a = 0.f;
        #pragma unroll 16
        for (int e = half*64; e < half*64 + 64; e++)
            a = fmaf(m1[e], D2[e*128 + o], a);
        h2p[tid] = a;
    }
    __syncthreads();
    if (tid < 128) m2[tid] = fmaxf(h2p[tid] + h2p[128 + tid] + db2[tid], 0.f);
    __syncthreads();
    if (tid < 128) {
        float v = m2[tid] * D3[tid];
        #pragma unroll
        for (int o = 16; o; o >>= 1) v += __shfl_xor_sync(0xffffffffu, v, o);
        if ((tid & 31) == 0) wr[tid >> 5] = v;
    }
    __syncthreads();
    if (tid == 0) out[b] = wr[0] + wr[1] + wr[2] + wr[3] + db3[0];
}

extern "C" void kernel_launch(void* const* d_in, const int* in_sizes, int n_in,
                              void* d_out, int out_size) {
    const float* x   = (const float*)d_in[0];
    const float* W1  = (const float*)d_in[1];
    const float* b1  = (const float*)d_in[2];
    const float* W2  = (const float*)d_in[3];
    const float* b2  = (const float*)d_in[4];
    const float* D1  = (const float*)d_in[5];
    const float* db1 = (const float*)d_in[6];
    const float* D2  = (const float*)d_in[7];
    const float* db2 = (const float*)d_in[8];
    const float* D3  = (const float*)d_in[9];
    const float* db3 = (const float*)d_in[10];
    float* out = (float*)d_out;

    size_t k1f_smem = 60416;
    cudaFuncSetAttribute(k1f_kernel, cudaFuncAttributeMaxDynamicSharedMemorySize,
                         (int)k1f_smem);

    p1_kernel<<<dim3(NT, NB), 256>>>(x, W1, b1);                // 1
    k1f_kernel<<<dim3(NTRI, NB), 512, k1f_smem>>>(x, W1, W2);   // 2
    p2_kernel<<<dim3(NT, NB), 256>>>(W2);                       // 3
    k2b_kernel<<<dim3(NTRI, NB), 256>>>(b2);                    // 4 -> profiled
    fin_kernel<<<NB, 256>>>(D1, db1, D2, db2, D3, db3, out);    // 5
}

// round 14
// speedup vs baseline: 2.1443x; 1.0995x over previous
#include <cuda_runtime.h>
#include <cuda_bf16.h>
#include <cstdint>

#define NB   8
#define NN   256
#define NIN  16
#define NH   32
#define TILE 16
#define NT   (NN/TILE)          // 16
#define NTRI (NT*(NT+1)/2)      // 136
#define NBLK2 (NB*NTRI)         // 1088
#define STR  20                 // apS/amS row stride (words)

typedef unsigned long long ull;

// ---- packed f32x2 helpers ----
__device__ __forceinline__ ull packf2(float lo, float hi) {
    ull r; asm("mov.b64 %0, {%1, %2};" : "=l"(r) : "f"(lo), "f"(hi)); return r;
}
__device__ __forceinline__ ull packdup(float v) {
    ull r; asm("mov.b64 %0, {%1, %1};" : "=l"(r) : "f"(v)); return r;
}
__device__ __forceinline__ ull ffma2(ull a, ull b, ull c) {
    ull d; asm("fma.rn.f32x2 %0, %1, %2, %3;" : "=l"(d) : "l"(a), "l"(b), "l"(c)); return d;
}
__device__ __forceinline__ float2 unpackf2(ull v) {
    float lo, hi; asm("mov.b64 {%0, %1}, %2;" : "=f"(lo), "=f"(hi) : "l"(v));
    return make_float2(lo, hi);
}
__device__ __forceinline__ float2 bf2f(unsigned int u) {
    return __bfloat1622float2(*reinterpret_cast<__nv_bfloat162*>(&u));
}
__device__ __forceinline__ unsigned int f2bf(float a, float b) {
    __nv_bfloat162 h = __floats2bfloat162_rn(a, b);
    return *reinterpret_cast<unsigned int*>(&h);
}

// ---- scratch (device globals) ----
__device__ __nv_bfloat16 g_G[(size_t)NB*NTRI*256*64];   // 35.6 MB pair-form rows
__device__ float g_R1[NB*NN*NH];
__device__ float g_Dg1[NB*NN*NH];
__device__ float g_T1[NB*NH];
__device__ float g_rp[(size_t)NB*NT*NT*512];            // 4 MB rowsum partials
__device__ float g_diag[NB*NN*NH];
__device__ float g_R2[NB*NN*NH];
__device__ float g_Dg2[NB*NN*NH];
__device__ float g_t2p[NB*NT*NH];                       // per-tile T2 partials
__device__ float g_part[(size_t)NBLK2*NH];

// ============================================================
// P1: parallel positional precompute. grid (NT, NB).
// ============================================================
__global__ void __launch_bounds__(256) p1_kernel(const float* __restrict__ x,
                                                 const float* __restrict__ W1,
                                                 const float* __restrict__ b1) {
    int ti = blockIdx.x, b = blockIdx.y, t = threadIdx.x;
    __shared__ float xs[NN*17];
    __shared__ float Ws[NH*NH*5];
    __shared__ float part[16*16];
    __shared__ float Ss[NIN];

    const float4* xg = (const float4*)(x + (size_t)b*NN*NIN);
    for (int e = t; e < NN*NIN/4; e += 256) {
        float4 v = xg[e];
        int r = e >> 2, c0 = (e & 3)*4;
        float* dst = xs + r*17 + c0;
        dst[0] = v.x; dst[1] = v.y; dst[2] = v.z; dst[3] = v.w;
    }
    for (int e = t; e < NH*NH*5; e += 256) Ws[e] = W1[e];
    __syncthreads();

    {
        int ch = t >> 4, d = t & 15;
        float s = 0.f;
        #pragma unroll
        for (int r = 0; r < 16; r++) s += xs[(ch*16 + r)*17 + d];
        part[ch*16 + d] = s;
    }
    __syncthreads();
    if (t < NIN) {
        float s = 0.f;
        #pragma unroll
        for (int ch = 0; ch < 16; ch++) s += part[ch*16 + t];
        Ss[t] = s;
    }
    __syncthreads();

    const float inv_n = 1.0f/(float)NN, inv_n2 = inv_n*inv_n;
    #pragma unroll
    for (int it = 0; it < 2; it++) {
        int item = t + it*256;
        int r = item >> 5, s = item & 31;
        int i = ti*16 + r;
        float rv = 0.f, dg = 0.f;
        #pragma unroll
        for (int d = 0; d < NIN; d++) {
            float xi = xs[i*17 + d];
            const float* wd  = &Ws[(d*NH + s)*5];
            const float* wd2 = &Ws[((NIN+d)*NH + s)*5];
            rv += xi*wd[3] + xi*Ss[d]*wd2[3];
            dg += xi*(wd[0] + wd[1] + wd[2]) + xi*xi*wd2[2];
        }
        g_R1 [((size_t)b*NN + i)*NH + s] = rv*inv_n;
        g_Dg1[((size_t)b*NN + i)*NH + s] = dg;
    }
    if (ti == 0 && t < NH) {
        int s = t;
        float tv = b1[s];
        #pragma unroll
        for (int d = 0; d < NIN; d++) {
            tv += Ss[d]*inv_n2       * Ws[(d*NH + s)*5 + 4];
            tv += Ss[d]*Ss[d]*inv_n2 * Ws[((NIN+d)*NH + s)*5 + 4];
        }
        g_T1[b*NH + s] = tv;
    }
}

// ============================================================
// K1F: fused layer-1 + layer-2 GEMM (unchanged from R13).
// ============================================================
__global__ void __launch_bounds__(512, 2) k1f_kernel(const float* __restrict__ x,
                                                     const float* __restrict__ W1,
                                                     const float* __restrict__ W2) {
    extern __shared__ __align__(16) char smraw[];
    ull*   Wa2 = (ull*)smraw;                       // 256 ull
    ull*   Wp2 = Wa2 + 256;                         // 512 ull
    ull*   Wm2 = Wp2 + 512;                         // 512 ull
    float* xi   = (float*)(Wm2 + 512);              // 272
    float* xj   = xi + 272;                         // 272
    float* posI = xj + 272;                         // 576
    float* posJ = posI + 576;                       // 576
    float* dgs  = posJ + 576;                       // 576
    float* t1s  = dgs + 576;                        // 32
    unsigned int* apS = (unsigned int*)(t1s + 32);  // 256*20
    unsigned int* amS = apS + 256*STR;              // 256*20

    int tp = blockIdx.x, b = blockIdx.y, t = threadIdx.x;
    int ti = 0, rr0 = tp;
    while (rr0 >= NT - ti) { rr0 -= NT - ti; ti++; }
    int tj = ti + rr0;
    int I = ti*TILE, J = tj*TILE;
    int bid = b*NTRI + tp;
    bool isdiag = (ti == tj);

    if (t < 256) {
        int r = t >> 4, c = t & 15;
        xi[r*17 + c] = x[(size_t)b*NN*NIN + (I+r)*NIN + c];
        int d = r, k = c, s0 = 2*k;
        float a0 = W1[((NIN+d)*NH + s0  )*5 + 0] + W1[((NIN+d)*NH + s0  )*5 + 1];
        float a1 = W1[((NIN+d)*NH + s0+1)*5 + 0] + W1[((NIN+d)*NH + s0+1)*5 + 1];
        Wa2[t] = packf2(a0, a1);
    } else {
        int e = t - 256;
        int r = e >> 4, c = e & 15;
        xj[r*17 + c] = x[(size_t)b*NN*NIN + (J+r)*NIN + c];
    }
    {
        int e = t;
        int tt = e >> 4, k = e & 15, s0 = 2*k;
        float w00 = W2[(tt*NH + s0  )*5 + 0], w01 = W2[(tt*NH + s0  )*5 + 1];
        float w10 = W2[(tt*NH + s0+1)*5 + 0], w11 = W2[(tt*NH + s0+1)*5 + 1];
        Wp2[e] = packf2(w00 + w01, w10 + w11);
        Wm2[e] = packf2(w00 - w01, w10 - w11);
    }
    {
        int e = t;
        int r = e >> 5, s = e & 31;
        posI[r*36 + s] = g_R1 [((size_t)b*NN + I + r)*NH + s];
        posJ[r*36 + s] = g_R1 [((size_t)b*NN + J + r)*NH + s];
        dgs [r*36 + s] = g_Dg1[((size_t)b*NN + I + r)*NH + s];
    }
    if (t < NH) t1s[t] = g_T1[b*NH + t];
    __syncthreads();

    // ---- phase 1 ----
    {
        int p = t & 255, sh1 = t >> 8;
        int ii = p >> 4, jj = p & 15;
        int sb1 = sh1*16;
        bool dgflag = isdiag && (ii == jj);

        ull acc2[8];
        #pragma unroll
        for (int k = 0; k < 8; k++) acc2[k] = 0ull;
        #pragma unroll
        for (int d = 0; d < NIN; d++) {
            float zd = xi[ii*17 + d] * xj[jj*17 + d];
            ull zdup = packdup(zd);
            const ulonglong2* w = (const ulonglong2*)(Wa2 + d*16 + sh1*8);
            #pragma unroll
            for (int k4 = 0; k4 < 4; k4++) {
                ulonglong2 ww = w[k4];
                acc2[2*k4]   = ffma2(zdup, ww.x, acc2[2*k4]);
                acc2[2*k4+1] = ffma2(zdup, ww.y, acc2[2*k4+1]);
            }
        }

        float pI[16], pJ[16];
        {
            const float4* pIr = (const float4*)(posI + ii*36 + sb1);
            const float4* pJr = (const float4*)(posJ + jj*36 + sb1);
            #pragma unroll
            for (int q = 0; q < 4; q++) {
                float4 a = pIr[q]; float4 c = pJr[q];
                pI[4*q] = a.x; pI[4*q+1] = a.y; pI[4*q+2] = a.z; pI[4*q+3] = a.w;
                pJ[4*q] = c.x; pJ[4*q+1] = c.y; pJ[4*q+2] = c.z; pJ[4*q+3] = c.w;
            }
        }

        unsigned int oa[8], om[8];
        #pragma unroll
        for (int k = 0; k < 8; k++) {
            float2 m = unpackf2(acc2[k]);
            int s0 = sb1 + 2*k, s1 = s0 + 1;
            float e0 = dgflag ? dgs[ii*36 + s0] : 0.f;
            float e1 = dgflag ? dgs[ii*36 + s1] : 0.f;
            float t0 = t1s[s0], t1v = t1s[s1];
            float c1lo = fmaxf(m.x + pI[2*k]   + t0 + e0, 0.f);
            float c1hi = fmaxf(m.y + pI[2*k+1] + t1v + e1, 0.f);
            float c2lo = fmaxf(m.x + pJ[2*k]   + t0 + e0, 0.f);
            float c2hi = fmaxf(m.y + pJ[2*k+1] + t1v + e1, 0.f);
            oa[k] = f2bf(c1lo + c2lo, c1hi + c2hi);
            om[k] = f2bf(c1lo - c2lo, c1hi - c2hi);
        }
        *(uint4*)(apS + p*STR + sh1*8)     = make_uint4(oa[0], oa[1], oa[2], oa[3]);
        *(uint4*)(apS + p*STR + sh1*8 + 4) = make_uint4(oa[4], oa[5], oa[6], oa[7]);
        *(uint4*)(amS + p*STR + sh1*8)     = make_uint4(om[0], om[1], om[2], om[3]);
        *(uint4*)(amS + p*STR + sh1*8 + 4) = make_uint4(om[4], om[5], om[6], om[7]);
    }
    __syncthreads();

    // ---- rowsum partials + diag ----
    {
        int side = t >> 8, e = t & 255;
        int r = e >> 4, w16 = e & 15;
        if (side == 0) {
            float lo = 0.f, hi = 0.f;
            #pragma unroll
            for (int q = 0; q < 16; q++) {
                float2 fa = bf2f(apS[(r*16 + q)*STR + w16]);
                float2 fm = bf2f(amS[(r*16 + q)*STR + w16]);
                lo += fa.x + fm.x;
                hi += fa.y + fm.y;
            }
            *(float2*)(g_rp + ((size_t)((b*NT + ti)*NT + tj))*512 + r*NH + 2*w16)
                = make_float2(0.5f*lo, 0.5f*hi);
        } else if (!isdiag) {
            float lo = 0.f, hi = 0.f;
            #pragma unroll
            for (int q = 0; q < 16; q++) {
                float2 fa = bf2f(apS[(q*16 + r)*STR + w16]);
                float2 fm = bf2f(amS[(q*16 + r)*STR + w16]);
                lo += fa.x - fm.x;
                hi += fa.y - fm.y;
            }
            *(float2*)(g_rp + ((size_t)((b*NT + tj)*NT + ti))*512 + r*NH + 2*w16)
                = make_float2(0.5f*lo, 0.5f*hi);
        } else {
            float2 fa = bf2f(apS[(r*16 + r)*STR + w16]);
            float2 fm = bf2f(amS[(r*16 + r)*STR + w16]);
            *(float2*)(g_diag + ((size_t)b*NN + I + r)*NH + 2*w16)
                = make_float2(0.5f*(fa.x + fm.x), 0.5f*(fa.y + fm.y));
        }
    }

    // ---- phase 2: GEMM ----
    {
        int duo = t & 127, sq = t >> 7;
        int sbq = sq*8;
        const uint4* pa4A = (const uint4*)(apS + duo*STR);
        const uint4* pa4B = (const uint4*)(apS + (duo + 128)*STR);
        const uint4* ma4A = (const uint4*)(amS + duo*STR);
        const uint4* ma4B = (const uint4*)(amS + (duo + 128)*STR);
        size_t growA = ((size_t)bid*256 + duo)*64;
        size_t growB = ((size_t)bid*256 + duo + 128)*64;

        {   // P pass
            ull aA[4], aB[4];
            #pragma unroll
            for (int k = 0; k < 4; k++) { aA[k] = 0ull; aB[k] = 0ull; }
            #pragma unroll
            for (int g = 0; g < 4; g++) {
                uint4 vA = pa4A[g], vB = pa4B[g];
                unsigned int wA[4] = {vA.x, vA.y, vA.z, vA.w};
                unsigned int wB[4] = {vB.x, vB.y, vB.z, vB.w};
                #pragma unroll
                for (int u = 0; u < 4; u++) {
                    float2 fA = bf2f(wA[u]);
                    float2 fB = bf2f(wB[u]);
                    int w16 = 4*g + u;
                    #pragma unroll
                    for (int h = 0; h < 2; h++) {
                        int tt = 2*w16 + h;
                        ull xA = packdup(h ? fA.y : fA.x);
                        ull xB = packdup(h ? fB.y : fB.x);
                        const ulonglong2* wp = (const ulonglong2*)(Wp2 + tt*16 + sq*4);
                        ulonglong2 w0 = wp[0], w1 = wp[1];
                        aA[0] = ffma2(xA, w0.x, aA[0]);
                        aA[1] = ffma2(xA, w0.y, aA[1]);
                        aA[2] = ffma2(xA, w1.x, aA[2]);
                        aA[3] = ffma2(xA, w1.y, aA[3]);
                        aB[0] = ffma2(xB, w0.x, aB[0]);
                        aB[1] = ffma2(xB, w0.y, aB[1]);
                        aB[2] = ffma2(xB, w1.x, aB[2]);
                        aB[3] = ffma2(xB, w1.y, aB[3]);
                    }
                }
            }
            unsigned int oA[4], oB[4];
            #pragma unroll
            for (int k = 0; k < 4; k++) {
                float2 PA = unpackf2(aA[k]);
                float2 PB = unpackf2(aB[k]);
                oA[k] = f2bf(0.5f*PA.x, 0.5f*PA.y);
                oB[k] = f2bf(0.5f*PB.x, 0.5f*PB.y);
            }
            *(uint4*)(g_G + growA + sbq) = make_uint4(oA[0], oA[1], oA[2], oA[3]);
            *(uint4*)(g_G + growB + sbq) = make_uint4(oB[0], oB[1], oB[2], oB[3]);
        }
        {   // M pass
            ull aA[4], aB[4];
            #pragma unroll
            for (int k = 0; k < 4; k++) { aA[k] = 0ull; aB[k] = 0ull; }
            #pragma unroll
            for (int g = 0; g < 4; g++) {
                uint4 vA = ma4A[g], vB = ma4B[g];
                unsigned int wA[4] = {vA.x, vA.y, vA.z, vA.w};
                unsigned int wB[4] = {vB.x, vB.y, vB.z, vB.w};
                #pragma unroll
                for (int u = 0; u < 4; u++) {
                    float2 fA = bf2f(wA[u]);
                    float2 fB = bf2f(wB[u]);
                    int w16 = 4*g + u;
                    #pragma unroll
                    for (int h = 0; h < 2; h++) {
                        int tt = 2*w16 + h;
                        ull xA = packdup(h ? fA.y : fA.x);
                        ull xB = packdup(h ? fB.y : fB.x);
                        const ulonglong2* wm = (const ulonglong2*)(Wm2 + tt*16 + sq*4);
                        ulonglong2 w0 = wm[0], w1 = wm[1];
                        aA[0] = ffma2(xA, w0.x, aA[0]);
                        aA[1] = ffma2(xA, w0.y, aA[1]);
                        aA[2] = ffma2(xA, w1.x, aA[2]);
                        aA[3] = ffma2(xA, w1.y, aA[3]);
                        aB[0] = ffma2(xB, w0.x, aB[0]);
                        aB[1] = ffma2(xB, w0.y, aB[1]);
                        aB[2] = ffma2(xB, w1.x, aB[2]);
                        aB[3] = ffma2(xB, w1.y, aB[3]);
                    }
                }
            }
            unsigned int oA[4], oB[4];
            #pragma unroll
            for (int k = 0; k < 4; k++) {
                float2 MA = unpackf2(aA[k]);
                float2 MB = unpackf2(aB[k]);
                oA[k] = f2bf(0.5f*MA.x, 0.5f*MA.y);
                oB[k] = f2bf(0.5f*MB.x, 0.5f*MB.y);
            }
            *(uint4*)(g_G + growA + 32 + sbq) = make_uint4(oA[0], oA[1], oA[2], oA[3]);
            *(uint4*)(g_G + growB + 32 + sbq) = make_uint4(oB[0], oB[1], oB[2], oB[3]);
        }
    }
}

// ============================================================
// P2: coalesced rowsum gather + layer-2 positional terms + T2 partials.
// ============================================================
__global__ void __launch_bounds__(256) p2_kernel(const float* __restrict__ W2) {
    int ti = blockIdx.x, b = blockIdx.y, t = threadIdx.x;
    __shared__ float Ws3[NH*NH], Ws2s[NH*NH], Ws4[NH*NH];
    __shared__ float raS[16*33], dvS[16*33];
    __shared__ float totS[NH];

    for (int e = t; e < NH*NH; e += 256) {
        Ws3[e]  = W2[e*5 + 3];
        Ws2s[e] = W2[e*5 + 2];
        Ws4[e]  = W2[e*5 + 4];
    }

    int ii = t >> 4, sp = t & 15;
    float2 acc = make_float2(0.f, 0.f);
    const float* base = g_rp + (size_t)(b*NT + ti)*NT*512 + ii*NH + 2*sp;
    #pragma unroll
    for (int tj = 0; tj < NT; tj++) {
        float2 v = *(const float2*)(base + tj*512);
        acc.x += v.x; acc.y += v.y;
    }
    raS[ii*33 + 2*sp] = acc.x; raS[ii*33 + 2*sp + 1] = acc.y;
    {
        float2 dv = *(const float2*)(g_diag + ((size_t)b*NN + ti*16 + ii)*NH + 2*sp);
        dvS[ii*33 + 2*sp] = dv.x; dvS[ii*33 + 2*sp + 1] = dv.y;
    }
    __syncthreads();

    if (t < NH) {
        float s = 0.f;
        #pragma unroll
        for (int r = 0; r < 16; r++) s += raS[r*33 + t];
        totS[t] = s;
    }
    __syncthreads();
    if (t < NH) {
        float a = 0.f;
        #pragma unroll
        for (int q = 0; q < NH; q++) a = fmaf(totS[q], Ws4[q*NH + t], a);
        g_t2p[(b*NT + ti)*NH + t] = a;
    }

    const float inv_n = 1.0f/(float)NN;
    int s0 = t & 15;
    float r2a = 0.f, r2b = 0.f, d2a = 0.f, d2b = 0.f;
    #pragma unroll
    for (int q = 0; q < NH; q++) {
        float rq = raS[ii*33 + q]*inv_n;
        float dq = dvS[ii*33 + q];
        r2a = fmaf(rq, Ws3[q*NH + s0],      r2a);
        r2b = fmaf(rq, Ws3[q*NH + s0 + 16], r2b);
        d2a = fmaf(dq, Ws2s[q*NH + s0],      d2a);
        d2b = fmaf(dq, Ws2s[q*NH + s0 + 16], d2b);
    }
    size_t ro = ((size_t)b*NN + ti*16 + ii)*NH;
    g_R2 [ro + s0]      = r2a;
    g_R2 [ro + s0 + 16] = r2b;
    g_Dg2[ro + s0]      = d2a;
    g_Dg2[ro + s0 + 16] = d2b;
}

// ============================================================
// K2B: register-accumulating epilogue. thread = (ii=pg, s-pair s2);
// walks jj=0..15 accumulating pooled sums in registers. One tiny
// 16x32 partial array + one barrier replaces the 256x33 reduction.
// ============================================================
__global__ void __launch_bounds__(256) k2b_kernel(const float* __restrict__ b2) {
    __shared__ float bs1[16*36], bs2[16*36], dgI[16*36];
    __shared__ float t2s[NH];
    __shared__ float red[16*34];

    int tp = blockIdx.x, b = blockIdx.y, t = threadIdx.x;
    int ti = 0, rr0 = tp;
    while (rr0 >= NT - ti) { rr0 -= NT - ti; ti++; }
    int tj = ti + rr0;
    int I = ti*TILE, J = tj*TILE;
    int bid = b*NTRI + tp;
    bool isdiag = (ti == tj);

    if (t < NH) {
        const float inv_n2 = 1.0f/((float)NN*(float)NN);
        float a = 0.f;
        #pragma unroll
        for (int k = 0; k < NT; k++) a += g_t2p[(b*NT + k)*NH + t];
        t2s[t] = b2[t] + a*inv_n2;
    }
    __syncthreads();
    for (int e = t; e < 512; e += 256) {
        int r = e >> 5, s = e & 31;
        float t2v = t2s[s];
        bs1[r*36 + s] = g_R2[((size_t)b*NN + I + r)*NH + s] + t2v;
        bs2[r*36 + s] = g_R2[((size_t)b*NN + J + r)*NH + s] + t2v;
        dgI[r*36 + s] = g_Dg2[((size_t)b*NN + I + r)*NH + s];
    }
    __syncthreads();

    int pg = t >> 4, s2 = t & 15;     // ii = pg, s values {2*s2, 2*s2+1}
    const unsigned int* Gu = (const unsigned int*)(g_G + (size_t)bid*256*64);
    float2 b1v = *(const float2*)(bs1 + pg*36 + 2*s2);
    float2 dgv = make_float2(0.f, 0.f);
    if (isdiag) dgv = *(const float2*)(dgI + pg*36 + 2*s2);

    float slo = 0.f, shi = 0.f;
    #pragma unroll
    for (int q = 0; q < 16; q++) {
        int p = pg*16 + q;
        unsigned int up = Gu[p*32 + s2];
        unsigned int um = Gu[p*32 + 16 + s2];
        float2 fp = bf2f(up);
        float2 fm = bf2f(um);
        float2 b2v = *(const float2*)(bs2 + q*36 + 2*s2);
        bool dflag = isdiag && (pg == q);
        {
            float base1 = b1v.x + (dflag ? dgv.x : 0.f);
            float c1 = fmaxf(fp.x + fm.x + base1, 0.f);
            float c2 = fmaxf(fp.x - fm.x + b2v.x, 0.f);
            float v = c1 + c2;
            if (isdiag) v = (pg < q) ? (c1 + c2) : (dflag ? c1 : 0.f);
            slo += v;
        }
        {
            float base1 = b1v.y + (dflag ? dgv.y : 0.f);
            float c1 = fmaxf(fp.y + fm.y + base1, 0.f);
            float c2 = fmaxf(fp.y - fm.y + b2v.y, 0.f);
            float v = c1 + c2;
            if (isdiag) v = (pg < q) ? (c1 + c2) : (dflag ? c1 : 0.f);
            shi += v;
        }
    }
    *(float2*)(red + pg*34 + 2*s2) = make_float2(slo, shi);
    __syncthreads();
    if (t < NH) {
        float p = 0.f;
        #pragma unroll
        for (int pg2 = 0; pg2 < 16; pg2++) p += red[pg2*34 + t];
        g_part[(size_t)bid*NH + t] = p;
    }
}

// ============================================================
// Final: parallel partial reduce + MLP 32->128->128->1.
// ============================================================
__global__ void __launch_bounds__(256) fin_kernel(const float* __restrict__ D1,
                                                  const float* __restrict__ db1,
                                                  const float* __restrict__ D2,
                                                  const float* __restrict__ db2,
                                                  const float* __restrict__ D3,
                                                  const float* __restrict__ db3,
                                                  float* __restrict__ out) {
    int b = blockIdx.x, tid = threadIdx.x;
    __shared__ float pp[8*NH];
    __shared__ float p[NH];
    __shared__ float m1[128];
    __shared__ float h2p[256];
    __shared__ float m2[128];
    __shared__ float wr[4];

    {
        int s = tid & 31, c = tid >> 5;
        float a = 0.f;
        #pragma unroll 4
        for (int k = c; k < NTRI; k += 8) a += g_part[(size_t)(b*NTRI + k)*NH + s];
        pp[tid] = a;
    }
    __syncthreads();
    if (tid < NH) {
        float t = 0.f;
        #pragma unroll
        for (int c = 0; c < 8; c++) t += pp[c*NH + tid];
        p[tid] = fmaxf(t, 0.f);
    }
    __syncthreads();
    if (tid < 128) {
        float a = db1[tid];
        #pragma unroll
        for (int q = 0; q < NH; q++) a = fmaf(p[q], D1[q*128 + tid], a);
        m1[tid] = fmaxf(a, 0.f);
    }
    __syncthreads();
    {
        int o = tid & 127, half = tid >> 7;
        float a = 0.f;
        #pragma unroll 16
        for (int e = half*64; e < half*64 + 64; e++)
            a = fmaf(m1[e], D2[e*128 + o], a);
        h2p[tid] = a;
    }
    __syncthreads();
    if (tid < 128) m2[tid] = fmaxf(h2p[tid] + h2p[128 + tid] + db2[tid], 0.f);
    __syncthreads();
    if (tid < 128) {
        float v = m2[tid] * D3[tid];
        #pragma unroll
        for (int o = 16; o; o >>= 1) v += __shfl_xor_sync(0xffffffffu, v, o);
        if ((tid & 31) == 0) wr[tid >> 5] = v;
    }
    __syncthreads();
    if (tid == 0) out[b] = wr[0] + wr[1] + wr[2] + wr[3] + db3[0];
}

extern "C" void kernel_launch(void* const* d_in, const int* in_sizes, int n_in,
                              void* d_out, int out_size) {
    const float* x   = (const float*)d_in[0];
    const float* W1  = (const float*)d_in[1];
    const float* b1  = (const float*)d_in[2];
    const float* W2  = (const float*)d_in[3];
    const float* b2  = (const float*)d_in[4];
    const float* D1  = (const float*)d_in[5];
    const float* db1 = (const float*)d_in[6];
    const float* D2  = (const float*)d_in[7];
    const float* db2 = (const float*)d_in[8];
    const float* D3  = (const float*)d_in[9];
    const float* db3 = (const float*)d_in[10];
    float* out = (float*)d_out;

    size_t k1f_smem = 60416;
    cudaFuncSetAttribute(k1f_kernel, cudaFuncAttributeMaxDynamicSharedMemorySize,
                         (int)k1f_smem);

    p1_kernel<<<dim3(NT, NB), 256>>>(x, W1, b1);                // 1
    k1f_kernel<<<dim3(NTRI, NB), 512, k1f_smem>>>(x, W1, W2);   // 2
    p2_kernel<<<dim3(NT, NB), 256>>>(W2);                       // 3
    k2b_kernel<<<dim3(NTRI, NB), 256>>>(b2);                    // 4 -> profiled
    fin_kernel<<<NB, 256>>>(D1, db1, D2, db2, D3, db3, out);    // 5
}

// round 15
// speedup vs baseline: 2.5035x; 1.1676x over previous
#include <cuda_runtime.h>
#include <cuda_bf16.h>
#include <cstdint>

#define NB   8
#define NN   256
#define NIN  16
#define NH   32
#define TILE 16
#define NT   (NN/TILE)          // 16
#define NTRI (NT*(NT+1)/2)      // 136
#define NBLK2 (NB*NTRI)         // 1088
#define STR  20                 // apS/amS row stride (u32 words): 80B

typedef unsigned long long ull;

// ---- packed f32x2 helpers ----
__device__ __forceinline__ ull packf2(float lo, float hi) {
    ull r; asm("mov.b64 %0, {%1, %2};" : "=l"(r) : "f"(lo), "f"(hi)); return r;
}
__device__ __forceinline__ ull packdup(float v) {
    ull r; asm("mov.b64 %0, {%1, %1};" : "=l"(r) : "f"(v)); return r;
}
__device__ __forceinline__ ull ffma2(ull a, ull b, ull c) {
    ull d; asm("fma.rn.f32x2 %0, %1, %2, %3;" : "=l"(d) : "l"(a), "l"(b), "l"(c)); return d;
}
__device__ __forceinline__ float2 unpackf2(ull v) {
    float lo, hi; asm("mov.b64 {%0, %1}, %2;" : "=f"(lo), "=f"(hi) : "l"(v));
    return make_float2(lo, hi);
}
__device__ __forceinline__ float2 bf2f(unsigned int u) {
    return __bfloat1622float2(*reinterpret_cast<__nv_bfloat162*>(&u));
}
__device__ __forceinline__ unsigned int f2bf(float a, float b) {
    __nv_bfloat162 h = __floats2bfloat162_rn(a, b);
    return *reinterpret_cast<unsigned int*>(&h);
}
__device__ __forceinline__ uint32_t smem_u32(const void* p) {
    uint32_t a;
    asm("{ .reg .u64 t; cvta.to.shared.u64 t, %1; cvt.u32.u64 %0, t; }" : "=r"(a) : "l"(p));
    return a;
}
__device__ __forceinline__ void ldsm_x4(uint32_t* r, uint32_t addr) {
    asm volatile("ldmatrix.sync.aligned.m8n8.x4.shared.b16 {%0,%1,%2,%3}, [%4];"
                 : "=r"(r[0]), "=r"(r[1]), "=r"(r[2]), "=r"(r[3]) : "r"(addr));
}
__device__ __forceinline__ void ldsm_x2t(uint32_t& r0, uint32_t& r1, uint32_t addr) {
    asm volatile("ldmatrix.sync.aligned.m8n8.x2.trans.shared.b16 {%0,%1}, [%2];"
                 : "=r"(r0), "=r"(r1) : "r"(addr));
}
__device__ __forceinline__ void mma16816(float* d, const uint32_t* a,
                                         uint32_t b0, uint32_t b1) {
    asm volatile(
        "mma.sync.aligned.m16n8k16.row.col.f32.bf16.bf16.f32 "
        "{%0,%1,%2,%3}, {%4,%5,%6,%7}, {%8,%9}, {%0,%1,%2,%3};"
        : "+f"(d[0]), "+f"(d[1]), "+f"(d[2]), "+f"(d[3])
        : "r"(a[0]), "r"(a[1]), "r"(a[2]), "r"(a[3]), "r"(b0), "r"(b1));
}

// ---- scratch (device globals) ----
__device__ __nv_bfloat16 g_G[(size_t)NB*NTRI*256*64];   // 35.6 MB pair-form rows
__device__ float g_R1[NB*NN*NH];
__device__ float g_Dg1[NB*NN*NH];
__device__ float g_T1[NB*NH];
__device__ float g_rp[(size_t)NB*NT*NT*512];            // 4 MB rowsum partials
__device__ float g_diag[NB*NN*NH];
__device__ float g_R2[NB*NN*NH];
__device__ float g_Dg2[NB*NN*NH];
__device__ float g_t2p[NB*NT*NH];                       // per-tile T2 partials
__device__ float g_part[(size_t)NBLK2*NH];

// ============================================================
// P1: parallel positional precompute. grid (NT, NB).
// ============================================================
__global__ void __launch_bounds__(256) p1_kernel(const float* __restrict__ x,
                                                 const float* __restrict__ W1,
                                                 const float* __restrict__ b1) {
    int ti = blockIdx.x, b = blockIdx.y, t = threadIdx.x;
    __shared__ float xs[NN*17];
    __shared__ float Ws[NH*NH*5];
    __shared__ float part[16*16];
    __shared__ float Ss[NIN];

    const float4* xg = (const float4*)(x + (size_t)b*NN*NIN);
    for (int e = t; e < NN*NIN/4; e += 256) {
        float4 v = xg[e];
        int r = e >> 2, c0 = (e & 3)*4;
        float* dst = xs + r*17 + c0;
        dst[0] = v.x; dst[1] = v.y; dst[2] = v.z; dst[3] = v.w;
    }
    for (int e = t; e < NH*NH*5; e += 256) Ws[e] = W1[e];
    __syncthreads();

    {
        int ch = t >> 4, d = t & 15;
        float s = 0.f;
        #pragma unroll
        for (int r = 0; r < 16; r++) s += xs[(ch*16 + r)*17 + d];
        part[ch*16 + d] = s;
    }
    __syncthreads();
    if (t < NIN) {
        float s = 0.f;
        #pragma unroll
        for (int ch = 0; ch < 16; ch++) s += part[ch*16 + t];
        Ss[t] = s;
    }
    __syncthreads();

    const float inv_n = 1.0f/(float)NN, inv_n2 = inv_n*inv_n;
    #pragma unroll
    for (int it = 0; it < 2; it++) {
        int item = t + it*256;
        int r = item >> 5, s = item & 31;
        int i = ti*16 + r;
        float rv = 0.f, dg = 0.f;
        #pragma unroll
        for (int d = 0; d < NIN; d++) {
            float xi = xs[i*17 + d];
            const float* wd  = &Ws[(d*NH + s)*5];
            const float* wd2 = &Ws[((NIN+d)*NH + s)*5];
            rv += xi*wd[3] + xi*Ss[d]*wd2[3];
            dg += xi*(wd[0] + wd[1] + wd[2]) + xi*xi*wd2[2];
        }
        g_R1 [((size_t)b*NN + i)*NH + s] = rv*inv_n;
        g_Dg1[((size_t)b*NN + i)*NH + s] = dg;
    }
    if (ti == 0 && t < NH) {
        int s = t;
        float tv = b1[s];
        #pragma unroll
        for (int d = 0; d < NIN; d++) {
            tv += Ss[d]*inv_n2       * Ws[(d*NH + s)*5 + 4];
            tv += Ss[d]*Ss[d]*inv_n2 * Ws[((NIN+d)*NH + s)*5 + 4];
        }
        g_T1[b*NH + s] = tv;
    }
}

// ============================================================
// K1F: fused layer-1 (FFMA2) + layer-2 GEMM (tensor-core mma.m16n8k16).
// ============================================================
__global__ void __launch_bounds__(512, 2) k1f_kernel(const float* __restrict__ x,
                                                     const float* __restrict__ W1,
                                                     const float* __restrict__ W2) {
    extern __shared__ __align__(16) char smraw[];
    ull*   Wa2 = (ull*)smraw;                        // 256 ull  @0
    unsigned int* Wpb = (unsigned int*)(Wa2 + 256);  // 32x16 u32 (bf16[32][32]) @2048
    unsigned int* Wmb = Wpb + 512;                   // @4096
    float* xi   = (float*)(Wmb + 512);               // 272 @6144
    float* xj   = xi + 272;                          // 272
    float* posI = xj + 272;                          // 576
    float* posJ = posI + 576;                        // 576
    float* dgs  = posJ + 576;                        // 576
    float* t1s  = dgs + 576;                         // 32
    unsigned int* apS = (unsigned int*)(t1s + 32);   // 256*20 u32
    unsigned int* amS = apS + 256*STR;               // 256*20 u32
    // total = 6144 + 2176 + 6912 + 128 + 40960 = 56320 B

    int tp = blockIdx.x, b = blockIdx.y, t = threadIdx.x;
    int ti = 0, rr0 = tp;
    while (rr0 >= NT - ti) { rr0 -= NT - ti; ti++; }
    int tj = ti + rr0;
    int I = ti*TILE, J = tj*TILE;
    int bid = b*NTRI + tp;
    bool isdiag = (ti == tj);

    if (t < 256) {
        int r = t >> 4, c = t & 15;
        xi[r*17 + c] = x[(size_t)b*NN*NIN + (I+r)*NIN + c];
        int d = r, k = c, s0 = 2*k;
        float a0 = W1[((NIN+d)*NH + s0  )*5 + 0] + W1[((NIN+d)*NH + s0  )*5 + 1];
        float a1 = W1[((NIN+d)*NH + s0+1)*5 + 0] + W1[((NIN+d)*NH + s0+1)*5 + 1];
        Wa2[t] = packf2(a0, a1);
    } else {
        int e = t - 256;
        int r = e >> 4, c = e & 15;
        xj[r*17 + c] = x[(size_t)b*NN*NIN + (J+r)*NIN + c];
    }
    {
        int e = t;                    // 0..511
        int tt = e >> 4, k = e & 15, s0 = 2*k;
        float w00 = W2[(tt*NH + s0  )*5 + 0], w01 = W2[(tt*NH + s0  )*5 + 1];
        float w10 = W2[(tt*NH + s0+1)*5 + 0], w11 = W2[(tt*NH + s0+1)*5 + 1];
        Wpb[tt*16 + k] = f2bf(w00 + w01, w10 + w11);
        Wmb[tt*16 + k] = f2bf(w00 - w01, w10 - w11);
    }
    {
        int e = t;
        int r = e >> 5, s = e & 31;
        posI[r*36 + s] = g_R1 [((size_t)b*NN + I + r)*NH + s];
        posJ[r*36 + s] = g_R1 [((size_t)b*NN + J + r)*NH + s];
        dgs [r*36 + s] = g_Dg1[((size_t)b*NN + I + r)*NH + s];
    }
    if (t < NH) t1s[t] = g_T1[b*NH + t];
    __syncthreads();

    // ---- phase 1: layer-1, 512 threads = (pair p, s-half sh1) ----
    {
        int p = t & 255, sh1 = t >> 8;
        int ii = p >> 4, jj = p & 15;
        int sb1 = sh1*16;
        bool dgflag = isdiag && (ii == jj);

        ull acc2[8];
        #pragma unroll
        for (int k = 0; k < 8; k++) acc2[k] = 0ull;
        #pragma unroll
        for (int d = 0; d < NIN; d++) {
            float zd = xi[ii*17 + d] * xj[jj*17 + d];
            ull zdup = packdup(zd);
            const ulonglong2* w = (const ulonglong2*)(Wa2 + d*16 + sh1*8);
            #pragma unroll
            for (int k4 = 0; k4 < 4; k4++) {
                ulonglong2 ww = w[k4];
                acc2[2*k4]   = ffma2(zdup, ww.x, acc2[2*k4]);
                acc2[2*k4+1] = ffma2(zdup, ww.y, acc2[2*k4+1]);
            }
        }

        float pI[16], pJ[16];
        {
            const float4* pIr = (const float4*)(posI + ii*36 + sb1);
            const float4* pJr = (const float4*)(posJ + jj*36 + sb1);
            #pragma unroll
            for (int q = 0; q < 4; q++) {
                float4 a = pIr[q]; float4 c = pJr[q];
                pI[4*q] = a.x; pI[4*q+1] = a.y; pI[4*q+2] = a.z; pI[4*q+3] = a.w;
                pJ[4*q] = c.x; pJ[4*q+1] = c.y; pJ[4*q+2] = c.z; pJ[4*q+3] = c.w;
            }
        }

        unsigned int oa[8], om[8];
        #pragma unroll
        for (int k = 0; k < 8; k++) {
            float2 m = unpackf2(acc2[k]);
            int s0 = sb1 + 2*k, s1 = s0 + 1;
            float e0 = dgflag ? dgs[ii*36 + s0] : 0.f;
            float e1 = dgflag ? dgs[ii*36 + s1] : 0.f;
            float t0 = t1s[s0], t1v = t1s[s1];
            float c1lo = fmaxf(m.x + pI[2*k]   + t0 + e0, 0.f);
            float c1hi = fmaxf(m.y + pI[2*k+1] + t1v + e1, 0.f);
            float c2lo = fmaxf(m.x + pJ[2*k]   + t0 + e0, 0.f);
            float c2hi = fmaxf(m.y + pJ[2*k+1] + t1v + e1, 0.f);
            oa[k] = f2bf(c1lo + c2lo, c1hi + c2hi);
            om[k] = f2bf(c1lo - c2lo, c1hi - c2hi);
        }
        *(uint4*)(apS + p*STR + sh1*8)     = make_uint4(oa[0], oa[1], oa[2], oa[3]);
        *(uint4*)(apS + p*STR + sh1*8 + 4) = make_uint4(oa[4], oa[5], oa[6], oa[7]);
        *(uint4*)(amS + p*STR + sh1*8)     = make_uint4(om[0], om[1], om[2], om[3]);
        *(uint4*)(amS + p*STR + sh1*8 + 4) = make_uint4(om[4], om[5], om[6], om[7]);
    }
    __syncthreads();

    // ---- rowsum partials + diag ----
    {
        int side = t >> 8, e = t & 255;
        int r = e >> 4, w16 = e & 15;
        if (side == 0) {
            float lo = 0.f, hi = 0.f;
            #pragma unroll
            for (int q = 0; q < 16; q++) {
                float2 fa = bf2f(apS[(r*16 + q)*STR + w16]);
                float2 fm = bf2f(amS[(r*16 + q)*STR + w16]);
                lo += fa.x + fm.x;
                hi += fa.y + fm.y;
            }
            *(float2*)(g_rp + ((size_t)((b*NT + ti)*NT + tj))*512 + r*NH + 2*w16)
                = make_float2(0.5f*lo, 0.5f*hi);
        } else if (!isdiag) {
            float lo = 0.f, hi = 0.f;
            #pragma unroll
            for (int q = 0; q < 16; q++) {
                float2 fa = bf2f(apS[(q*16 + r)*STR + w16]);
                float2 fm = bf2f(amS[(q*16 + r)*STR + w16]);
                lo += fa.x - fm.x;
                hi += fa.y - fm.y;
            }
            *(float2*)(g_rp + ((size_t)((b*NT + tj)*NT + ti))*512 + r*NH + 2*w16)
                = make_float2(0.5f*lo, 0.5f*hi);
        } else {
            float2 fa = bf2f(apS[(r*16 + r)*STR + w16]);
            float2 fm = bf2f(amS[(r*16 + r)*STR + w16]);
            *(float2*)(g_diag + ((size_t)b*NN + I + r)*NH + 2*w16)
                = make_float2(0.5f*(fa.x + fm.x), 0.5f*(fa.y + fm.y));
        }
    }

    // ---- phase 2: tensor-core GEMM. warp = 16 pairs; 2 forms x 4 nt x 2 kc ----
    {
        int lane = t & 31, w = t >> 5;
        int p0 = w*16;
        uint32_t aBase = smem_u32(apS) + (uint32_t)((p0 + (lane & 15))*80 + (lane >> 4)*16);
        uint32_t amOff = (uint32_t)(256*STR*4);   // byte offset apS -> amS
        uint32_t wpBase = smem_u32(Wpb) + (uint32_t)((lane & 15)*64);
        uint32_t wmOff = 2048u;                   // byte offset Wpb -> Wmb

        #pragma unroll
        for (int form = 0; form < 2; form++) {
            uint32_t aAddr = aBase + (form ? amOff : 0u);
            uint32_t wAddr = wpBase + (form ? wmOff : 0u);
            uint32_t A0[4], A1[4];
            ldsm_x4(A0, aAddr);          // k 0-15
            ldsm_x4(A1, aAddr + 32);     // k 16-31
            float d[4][4];
            #pragma unroll
            for (int nt = 0; nt < 4; nt++) {
                d[nt][0] = 0.f; d[nt][1] = 0.f; d[nt][2] = 0.f; d[nt][3] = 0.f;
                uint32_t b0, b1, b2, b3;
                ldsm_x2t(b0, b1, wAddr + nt*16);            // k 0-15
                ldsm_x2t(b2, b3, wAddr + 16*64 + nt*16);    // k 16-31
                mma16816(d[nt], A0, b0, b1);
                mma16816(d[nt], A1, b2, b3);
            }
            int rowA = lane >> 2;
            size_t gbA = ((size_t)bid*256 + p0 + rowA)*64 + form*32;
            size_t gbB = gbA + 8*64;
            unsigned int* GA = (unsigned int*)(g_G + gbA);
            unsigned int* GB = (unsigned int*)(g_G + gbB);
            #pragma unroll
            for (int nt = 0; nt < 4; nt++) {
                int col = nt*8 + (lane & 3)*2;
                GA[col >> 1] = f2bf(0.5f*d[nt][0], 0.5f*d[nt][1]);
                GB[col >> 1] = f2bf(0.5f*d[nt][2], 0.5f*d[nt][3]);
            }
        }
    }
}

// ============================================================
// P2: coalesced rowsum gather + layer-2 positional terms + T2 partials.
// ============================================================
__global__ void __launch_bounds__(256) p2_kernel(const float* __restrict__ W2) {
    int ti = blockIdx.x, b = blockIdx.y, t = threadIdx.x;
    __shared__ float Ws3[NH*NH], Ws2s[NH*NH], Ws4[NH*NH];
    __shared__ float raS[16*33], dvS[16*33];
    __shared__ float totS[NH];

    for (int e = t; e < NH*NH; e += 256) {
        Ws3[e]  = W2[e*5 + 3];
        Ws2s[e] = W2[e*5 + 2];
        Ws4[e]  = W2[e*5 + 4];
    }

    int ii = t >> 4, sp = t & 15;
    float2 acc = make_float2(0.f, 0.f);
    const float* base = g_rp + (size_t)(b*NT + ti)*NT*512 + ii*NH + 2*sp;
    #pragma unroll
    for (int tj = 0; tj < NT; tj++) {
        float2 v = *(const float2*)(base + tj*512);
        acc.x += v.x; acc.y += v.y;
    }
    raS[ii*33 + 2*sp] = acc.x; raS[ii*33 + 2*sp + 1] = acc.y;
    {
        float2 dv = *(const float2*)(g_diag + ((size_t)b*NN + ti*16 + ii)*NH + 2*sp);
        dvS[ii*33 + 2*sp] = dv.x; dvS[ii*33 + 2*sp + 1] = dv.y;
    }
    __syncthreads();

    if (t < NH) {
        float s = 0.f;
        #pragma unroll
        for (int r = 0; r < 16; r++) s += raS[r*33 + t];
        totS[t] = s;
    }
    __syncthreads();
    if (t < NH) {
        float a = 0.f;
        #pragma unroll
        for (int q = 0; q < NH; q++) a = fmaf(totS[q], Ws4[q*NH + t], a);
        g_t2p[(b*NT + ti)*NH + t] = a;
    }

    const float inv_n = 1.0f/(float)NN;
    int s0 = t & 15;
    float r2a = 0.f, r2b = 0.f, d2a = 0.f, d2b = 0.f;
    #pragma unroll
    for (int q = 0; q < NH; q++) {
        float rq = raS[ii*33 + q]*inv_n;
        float dq = dvS[ii*33 + q];
        r2a = fmaf(rq, Ws3[q*NH + s0],      r2a);
        r2b = fmaf(rq, Ws3[q*NH + s0 + 16], r2b);
        d2a = fmaf(dq, Ws2s[q*NH + s0],      d2a);
        d2b = fmaf(dq, Ws2s[q*NH + s0 + 16], d2b);
    }
    size_t ro = ((size_t)b*NN + ti*16 + ii)*NH;
    g_R2 [ro + s0]      = r2a;
    g_R2 [ro + s0 + 16] = r2b;
    g_Dg2[ro + s0]      = d2a;
    g_Dg2[ro + s0 + 16] = d2b;
}

// ============================================================
// K2B: register-accumulating epilogue, uint2-vectorized G loads.
// thread = (pg, s-quad sq, q-half qh).
// ============================================================
__global__ void __launch_bounds__(256) k2b_kernel(const float* __restrict__ b2) {
    __shared__ float bs1[16*36], bs2[16*36], dgI[16*36];
    __shared__ float t2s[NH];
    __shared__ float red[2*16*36];

    int tp = blockIdx.x, b = blockIdx.y, t = threadIdx.x;
    int ti = 0, rr0 = tp;
    while (rr0 >= NT - ti) { rr0 -= NT - ti; ti++; }
    int tj = ti + rr0;
    int I = ti*TILE, J = tj*TILE;
    int bid = b*NTRI + tp;
    bool isdiag = (ti == tj);

    if (t < NH) {
        const float inv_n2 = 1.0f/((float)NN*(float)NN);
        float a = 0.f;
        #pragma unroll
        for (int k = 0; k < NT; k++) a += g_t2p[(b*NT + k)*NH + t];
        t2s[t] = b2[t] + a*inv_n2;
    }
    __syncthreads();
    for (int e = t; e < 512; e += 256) {
        int r = e >> 5, s = e & 31;
        float t2v = t2s[s];
        bs1[r*36 + s] = g_R2[((size_t)b*NN + I + r)*NH + s] + t2v;
        bs2[r*36 + s] = g_R2[((size_t)b*NN + J + r)*NH + s] + t2v;
        dgI[r*36 + s] = g_Dg2[((size_t)b*NN + I + r)*NH + s];
    }
    __syncthreads();

    int pg = t >> 4, sq = (t >> 1) & 7, qh = t & 1;
    const uint2* Gu2 = (const uint2*)(g_G + (size_t)bid*256*64);
    float4 b1v = *(const float4*)(bs1 + pg*36 + 4*sq);
    float4 dgv = make_float4(0.f, 0.f, 0.f, 0.f);
    if (isdiag) dgv = *(const float4*)(dgI + pg*36 + 4*sq);

    float a0 = 0.f, a1 = 0.f, a2 = 0.f, a3 = 0.f;
    #pragma unroll
    for (int qq = 0; qq < 8; qq++) {
        int q = qh*8 + qq;
        int p = pg*16 + q;
        uint2 up = Gu2[p*16 + sq];
        uint2 um = Gu2[p*16 + 8 + sq];
        float4 b2v = *(const float4*)(bs2 + q*36 + 4*sq);
        bool dflag = isdiag && (pg == q);
        float2 fp0 = bf2f(up.x), fp1 = bf2f(up.y);
        float2 fm0 = bf2f(um.x), fm1 = bf2f(um.y);
        {
            float c1 = fmaxf(fp0.x + fm0.x + b1v.x + (dflag ? dgv.x : 0.f), 0.f);
            float c2 = fmaxf(fp0.x - fm0.x + b2v.x, 0.f);
            float v = c1 + c2;
            if (isdiag) v = (pg < q) ? (c1 + c2) : (dflag ? c1 : 0.f);
            a0 += v;
        }
        {
            float c1 = fmaxf(fp0.y + fm0.y + b1v.y + (dflag ? dgv.y : 0.f), 0.f);
            float c2 = fmaxf(fp0.y - fm0.y + b2v.y, 0.f);
            float v = c1 + c2;
            if (isdiag) v = (pg < q) ? (c1 + c2) : (dflag ? c1 : 0.f);
            a1 += v;
        }
        {
            float c1 = fmaxf(fp1.x + fm1.x + b1v.z + (dflag ? dgv.z : 0.f), 0.f);
            float c2 = fmaxf(fp1.x - fm1.x + b2v.z, 0.f);
            float v = c1 + c2;
            if (isdiag) v = (pg < q) ? (c1 + c2) : (dflag ? c1 : 0.f);
            a2 += v;
        }
        {
            float c1 = fmaxf(fp1.y + fm1.y + b1v.w + (dflag ? dgv.w : 0.f), 0.f);
            float c2 = fmaxf(fp1.y - fm1.y + b2v.w, 0.f);
            float v = c1 + c2;
            if (isdiag) v = (pg < q) ? (c1 + c2) : (dflag ? c1 : 0.f);
            a3 += v;
        }
    }
    *(float4*)(red + qh*16*36 + pg*36 + 4*sq) = make_float4(a0, a1, a2, a3);
    __syncthreads();
    if (t < NH) {
        float p = 0.f;
        #pragma unroll
        for (int pg2 = 0; pg2 < 16; pg2++)
            p += red[pg2*36 + t] + red[16*36 + pg2*36 + t];
        g_part[(size_t)bid*NH + t] = p;
    }
}

// ============================================================
// Final: parallel partial reduce + MLP 32->128->128->1.
// ============================================================
__global__ void __launch_bounds__(256) fin_kernel(const float* __restrict__ D1,
                                                  const float* __restrict__ db1,
                                                  const float* __restrict__ D2,
                                                  const float* __restrict__ db2,
                                                  const float* __restrict__ D3,
                                                  const float* __restrict__ db3,
                                                  float* __restrict__ out) {
    int b = blockIdx.x, tid = threadIdx.x;
    __shared__ float pp[8*NH];
    __shared__ float p[NH];
    __shared__ float m1[128];
    __shared__ float h2p[256];
    __shared__ float m2[128];
    __shared__ float wr[4];

    {
        int s = tid & 31, c = tid >> 5;
        float a = 0.f;
        #pragma unroll 4
        for (int k = c; k < NTRI; k += 8) a += g_part[(size_t)(b*NTRI + k)*NH + s];
        pp[tid] = a;
    }
    __syncthreads();
    if (tid < NH) {
        float t = 0.f;
        #pragma unroll
        for (int c = 0; c < 8; c++) t += pp[c*NH + tid];
        p[tid] = fmaxf(t, 0.f);
    }
    __syncthreads();
    if (tid < 128) {
        float a = db1[tid];
        #pragma unroll
        for (int q = 0; q < NH; q++) a = fmaf(p[q], D1[q*128 + tid], a);
        m1[tid] = fmaxf(a, 0.f);
    }
    __syncthreads();
    {
        int o = tid & 127, half = tid >> 7;
        float a = 0.f;
        #pragma unroll 16
        for (int e = half*64; e < half*64 + 64; e++)
            a = fmaf(m1[e], D2[e*128 + o], a);
        h2p[tid] = a;
    }
    __syncthreads();
    if (tid < 128) m2[tid] = fmaxf(h2p[tid] + h2p[128 + tid] + db2[tid], 0.f);
    __syncthreads();
    if (tid < 128) {
        float v = m2[tid] * D3[tid];
        #pragma unroll
        for (int o = 16; o; o >>= 1) v += __shfl_xor_sync(0xffffffffu, v, o);
        if ((tid & 31) == 0) wr[tid >> 5] = v;
    }
    __syncthreads();
    if (tid == 0) out[b] = wr[0] + wr[1] + wr[2] + wr[3] + db3[0];
}

extern "C" void kernel_launch(void* const* d_in, const int* in_sizes, int n_in,
                              void* d_out, int out_size) {
    const float* x   = (const float*)d_in[0];
    const float* W1  = (const float*)d_in[1];
    const float* b1  = (const float*)d_in[2];
    const float* W2  = (const float*)d_in[3];
    const float* b2  = (const float*)d_in[4];
    const float* D1  = (const float*)d_in[5];
    const float* db1 = (const float*)d_in[6];
    const float* D2  = (const float*)d_in[7];
    const float* db2 = (const float*)d_in[8];
    const float* D3  = (const float*)d_in[9];
    const float* db3 = (const float*)d_in[10];
    float* out = (float*)d_out;

    size_t k1f_smem = 56320;
    cudaFuncSetAttribute(k1f_kernel, cudaFuncAttributeMaxDynamicSharedMemorySize,
                         (int)k1f_smem);

    p1_kernel<<<dim3(NT, NB), 256>>>(x, W1, b1);                // 1
    k1f_kernel<<<dim3(NTRI, NB), 512, k1f_smem>>>(x, W1, W2);   // 2
    p2_kernel<<<dim3(NT, NB), 256>>>(W2);                       // 3
    k2b_kernel<<<dim3(NTRI, NB), 256>>>(b2);                    // 4 -> profiled
    fin_kernel<<<NB, 256>>>(D1, db1, D2, db2, D3, db3, out);    // 5
}

// round 16
// speedup vs baseline: 2.7364x; 1.0930x over previous
#include <cuda_runtime.h>
#include <cuda_bf16.h>
#include <cstdint>

#define NB   8
#define NN   256
#define NIN  16
#define NH   32
#define TILE 16
#define NT   (NN/TILE)          // 16
#define NTRI (NT*(NT+1)/2)      // 136
#define NBLK2 (NB*NTRI)         // 1088
#define STR  20                 // apS/amS row stride (u32 words): 80B

typedef unsigned long long ull;

__device__ __forceinline__ float2 bf2f(unsigned int u) {
    return __bfloat1622float2(*reinterpret_cast<__nv_bfloat162*>(&u));
}
__device__ __forceinline__ unsigned int f2bf(float a, float b) {
    __nv_bfloat162 h = __floats2bfloat162_rn(a, b);
    return *reinterpret_cast<unsigned int*>(&h);
}
__device__ __forceinline__ uint32_t smem_u32(const void* p) {
    uint32_t a;
    asm("{ .reg .u64 t; cvta.to.shared.u64 t, %1; cvt.u32.u64 %0, t; }" : "=r"(a) : "l"(p));
    return a;
}
__device__ __forceinline__ void ldsm_x4(uint32_t* r, uint32_t addr) {
    asm volatile("ldmatrix.sync.aligned.m8n8.x4.shared.b16 {%0,%1,%2,%3}, [%4];"
                 : "=r"(r[0]), "=r"(r[1]), "=r"(r[2]), "=r"(r[3]) : "r"(addr));
}
__device__ __forceinline__ void ldsm_x2t(uint32_t& r0, uint32_t& r1, uint32_t addr) {
    asm volatile("ldmatrix.sync.aligned.m8n8.x2.trans.shared.b16 {%0,%1}, [%2];"
                 : "=r"(r0), "=r"(r1) : "r"(addr));
}
__device__ __forceinline__ void mma16816(float* d, const uint32_t* a,
                                         uint32_t b0, uint32_t b1) {
    asm volatile(
        "mma.sync.aligned.m16n8k16.row.col.f32.bf16.bf16.f32 "
        "{%0,%1,%2,%3}, {%4,%5,%6,%7}, {%8,%9}, {%0,%1,%2,%3};"
        : "+f"(d[0]), "+f"(d[1]), "+f"(d[2]), "+f"(d[3])
        : "r"(a[0]), "r"(a[1]), "r"(a[2]), "r"(a[3]), "r"(b0), "r"(b1));
}

// ---- scratch (device globals) ----
__device__ __nv_bfloat16 g_G[(size_t)NB*NTRI*256*64];   // 35.6 MB pair-form rows
__device__ float g_R1[NB*NN*NH];
__device__ float g_Dg1[NB*NN*NH];
__device__ float g_T1[NB*NH];
__device__ float g_rp[(size_t)NB*NT*NT*512];            // 4 MB rowsum partials
__device__ float g_diag[NB*NN*NH];
__device__ float g_R2[NB*NN*NH];
__device__ float g_Dg2[NB*NN*NH];
__device__ float g_t2p[NB*NT*NH];                       // per-tile T2 partials
__device__ float g_part[(size_t)NBLK2*NH];

// ============================================================
// P1: parallel positional precompute. grid (NT, NB).
// ============================================================
__global__ void __launch_bounds__(256) p1_kernel(const float* __restrict__ x,
                                                 const float* __restrict__ W1,
                                                 const float* __restrict__ b1) {
    int ti = blockIdx.x, b = blockIdx.y, t = threadIdx.x;
    __shared__ float xs[NN*17];
    __shared__ float Ws[NH*NH*5];
    __shared__ float part[16*16];
    __shared__ float Ss[NIN];

    const float4* xg = (const float4*)(x + (size_t)b*NN*NIN);
    for (int e = t; e < NN*NIN/4; e += 256) {
        float4 v = xg[e];
        int r = e >> 2, c0 = (e & 3)*4;
        float* dst = xs + r*17 + c0;
        dst[0] = v.x; dst[1] = v.y; dst[2] = v.z; dst[3] = v.w;
    }
    for (int e = t; e < NH*NH*5; e += 256) Ws[e] = W1[e];
    __syncthreads();

    {
        int ch = t >> 4, d = t & 15;
        float s = 0.f;
        #pragma unroll
        for (int r = 0; r < 16; r++) s += xs[(ch*16 + r)*17 + d];
        part[ch*16 + d] = s;
    }
    __syncthreads();
    if (t < NIN) {
        float s = 0.f;
        #pragma unroll
        for (int ch = 0; ch < 16; ch++) s += part[ch*16 + t];
        Ss[t] = s;
    }
    __syncthreads();

    const float inv_n = 1.0f/(float)NN, inv_n2 = inv_n*inv_n;
    #pragma unroll
    for (int it = 0; it < 2; it++) {
        int item = t + it*256;
        int r = item >> 5, s = item & 31;
        int i = ti*16 + r;
        float rv = 0.f, dg = 0.f;
        #pragma unroll
        for (int d = 0; d < NIN; d++) {
            float xi = xs[i*17 + d];
            const float* wd  = &Ws[(d*NH + s)*5];
            const float* wd2 = &Ws[((NIN+d)*NH + s)*5];
            rv += xi*wd[3] + xi*Ss[d]*wd2[3];
            dg += xi*(wd[0] + wd[1] + wd[2]) + xi*xi*wd2[2];
        }
        g_R1 [((size_t)b*NN + i)*NH + s] = rv*inv_n;
        g_Dg1[((size_t)b*NN + i)*NH + s] = dg;
    }
    if (ti == 0 && t < NH) {
        int s = t;
        float tv = b1[s];
        #pragma unroll
        for (int d = 0; d < NIN; d++) {
            tv += Ss[d]*inv_n2       * Ws[(d*NH + s)*5 + 4];
            tv += Ss[d]*Ss[d]*inv_n2 * Ws[((NIN+d)*NH + s)*5 + 4];
        }
        g_T1[b*NH + s] = tv;
    }
}

// ============================================================
// K1F: both layers on tensor cores.
// Phase 1: A-fragment built in registers (z = xi*xj), B = Wa bf16,
//          epilogue (positional+relu+pair-pack) in fragment layout.
// Phase 2: layer-2 GEMM (as R15).
// ============================================================
__global__ void __launch_bounds__(512, 2) k1f_kernel(const float* __restrict__ x,
                                                     const float* __restrict__ W1,
                                                     const float* __restrict__ W2) {
    extern __shared__ __align__(16) char smraw[];
    unsigned int* Wab = (unsigned int*)smraw;        // 16x16 u32 (bf16[16][32]) @0
    unsigned int* Wpb = Wab + 256;                   // 32x16 u32 @1024
    unsigned int* Wmb = Wpb + 512;                   // @3072
    float* xi   = (float*)(Wmb + 512);               // 272 @5120
    float* xj   = xi + 272;                          // 272
    float* posI = xj + 272;                          // 576
    float* posJ = posI + 576;                        // 576
    float* dgs  = posJ + 576;                        // 576
    float* t1s  = dgs + 576;                         // 32
    unsigned int* apS = (unsigned int*)(t1s + 32);   // 256*20 u32
    unsigned int* amS = apS + 256*STR;               // 256*20 u32
    // total = 5120 + 9216 + 40960 = 55296 B

    int tp = blockIdx.x, b = blockIdx.y, t = threadIdx.x;
    int ti = 0, rr0 = tp;
    while (rr0 >= NT - ti) { rr0 -= NT - ti; ti++; }
    int tj = ti + rr0;
    int I = ti*TILE, J = tj*TILE;
    int bid = b*NTRI + tp;
    bool isdiag = (ti == tj);

    if (t < 256) {
        int r = t >> 4, c = t & 15;
        xi[r*17 + c] = x[(size_t)b*NN*NIN + (I+r)*NIN + c];
        int d = r, k = c, s0 = 2*k;    // Wab row d (k-dim), word k
        float a0 = W1[((NIN+d)*NH + s0  )*5 + 0] + W1[((NIN+d)*NH + s0  )*5 + 1];
        float a1 = W1[((NIN+d)*NH + s0+1)*5 + 0] + W1[((NIN+d)*NH + s0+1)*5 + 1];
        Wab[d*16 + k] = f2bf(a0, a1);
    } else {
        int e = t - 256;
        int r = e >> 4, c = e & 15;
        xj[r*17 + c] = x[(size_t)b*NN*NIN + (J+r)*NIN + c];
    }
    {
        int e = t;                    // 0..511
        int tt = e >> 4, k = e & 15, s0 = 2*k;
        float w00 = W2[(tt*NH + s0  )*5 + 0], w01 = W2[(tt*NH + s0  )*5 + 1];
        float w10 = W2[(tt*NH + s0+1)*5 + 0], w11 = W2[(tt*NH + s0+1)*5 + 1];
        Wpb[tt*16 + k] = f2bf(w00 + w01, w10 + w11);
        Wmb[tt*16 + k] = f2bf(w00 - w01, w10 - w11);
    }
    {
        int e = t;
        int r = e >> 5, s = e & 31;
        posI[r*36 + s] = g_R1 [((size_t)b*NN + I + r)*NH + s];
        posJ[r*36 + s] = g_R1 [((size_t)b*NN + J + r)*NH + s];
        dgs [r*36 + s] = g_Dg1[((size_t)b*NN + I + r)*NH + s];
    }
    if (t < NH) t1s[t] = g_T1[b*NH + t];
    __syncthreads();

    // ---- phase 1: layer-1 via MMA, A built in registers ----
    {
        int lane = t & 31, w = t >> 5;
        int p0 = w*16;
        int row = lane >> 2;
        int p1 = p0 + row, p2 = p1 + 8;
        int ii1 = p1 >> 4, jj1 = p1 & 15;
        int ii2 = p2 >> 4, jj2 = p2 & 15;
        int k0 = (lane & 3)*2;

        uint32_t A[4];
        A[0] = f2bf(xi[ii1*17 + k0]     * xj[jj1*17 + k0],
                    xi[ii1*17 + k0 + 1] * xj[jj1*17 + k0 + 1]);
        A[1] = f2bf(xi[ii2*17 + k0]     * xj[jj2*17 + k0],
                    xi[ii2*17 + k0 + 1] * xj[jj2*17 + k0 + 1]);
        A[2] = f2bf(xi[ii1*17 + k0 + 8] * xj[jj1*17 + k0 + 8],
                    xi[ii1*17 + k0 + 9] * xj[jj1*17 + k0 + 9]);
        A[3] = f2bf(xi[ii2*17 + k0 + 8] * xj[jj2*17 + k0 + 8],
                    xi[ii2*17 + k0 + 9] * xj[jj2*17 + k0 + 9]);

        uint32_t waBase = smem_u32(Wab) + (uint32_t)((lane & 15)*64);
        bool dg1 = isdiag && (ii1 == jj1);
        bool dg2 = isdiag && (ii2 == jj2);

        #pragma unroll
        for (int nt = 0; nt < 4; nt++) {
            float dd[4] = {0.f, 0.f, 0.f, 0.f};
            uint32_t b0, b1;
            ldsm_x2t(b0, b1, waBase + nt*16);
            mma16816(dd, A, b0, b1);
            int s0 = nt*8 + (lane & 3)*2;
            float2 t1v = *(const float2*)(t1s + s0);
            {   // row p1
                float2 pIv = *(const float2*)(posI + ii1*36 + s0);
                float2 pJv = *(const float2*)(posJ + jj1*36 + s0);
                float e0 = 0.f, e1 = 0.f;
                if (dg1) { float2 dv = *(const float2*)(dgs + ii1*36 + s0); e0 = dv.x; e1 = dv.y; }
                float c1lo = fmaxf(dd[0] + pIv.x + t1v.x + e0, 0.f);
                float c1hi = fmaxf(dd[1] + pIv.y + t1v.y + e1, 0.f);
                float c2lo = fmaxf(dd[0] + pJv.x + t1v.x + e0, 0.f);
                float c2hi = fmaxf(dd[1] + pJv.y + t1v.y + e1, 0.f);
                apS[p1*STR + (s0 >> 1)] = f2bf(c1lo + c2lo, c1hi + c2hi);
                amS[p1*STR + (s0 >> 1)] = f2bf(c1lo - c2lo, c1hi - c2hi);
            }
            {   // row p2
                float2 pIv = *(const float2*)(posI + ii2*36 + s0);
                float2 pJv = *(const float2*)(posJ + jj2*36 + s0);
                float e0 = 0.f, e1 = 0.f;
                if (dg2) { float2 dv = *(const float2*)(dgs + ii2*36 + s0); e0 = dv.x; e1 = dv.y; }
                float c1lo = fmaxf(dd[2] + pIv.x + t1v.x + e0, 0.f);
                float c1hi = fmaxf(dd[3] + pIv.y + t1v.y + e1, 0.f);
                float c2lo = fmaxf(dd[2] + pJv.x + t1v.x + e0, 0.f);
                float c2hi = fmaxf(dd[3] + pJv.y + t1v.y + e1, 0.f);
                apS[p2*STR + (s0 >> 1)] = f2bf(c1lo + c2lo, c1hi + c2hi);
                amS[p2*STR + (s0 >> 1)] = f2bf(c1lo - c2lo, c1hi - c2hi);
            }
        }
    }
    __syncthreads();

    // ---- rowsum partials + diag ----
    {
        int side = t >> 8, e = t & 255;
        int r = e >> 4, w16 = e & 15;
        if (side == 0) {
            float lo = 0.f, hi = 0.f;
            #pragma unroll
            for (int q = 0; q < 16; q++) {
                float2 fa = bf2f(apS[(r*16 + q)*STR + w16]);
                float2 fm = bf2f(amS[(r*16 + q)*STR + w16]);
                lo += fa.x + fm.x;
                hi += fa.y + fm.y;
            }
            *(float2*)(g_rp + ((size_t)((b*NT + ti)*NT + tj))*512 + r*NH + 2*w16)
                = make_float2(0.5f*lo, 0.5f*hi);
        } else if (!isdiag) {
            float lo = 0.f, hi = 0.f;
            #pragma unroll
            for (int q = 0; q < 16; q++) {
                float2 fa = bf2f(apS[(q*16 + r)*STR + w16]);
                float2 fm = bf2f(amS[(q*16 + r)*STR + w16]);
                lo += fa.x - fm.x;
                hi += fa.y - fm.y;
            }
            *(float2*)(g_rp + ((size_t)((b*NT + tj)*NT + ti))*512 + r*NH + 2*w16)
                = make_float2(0.5f*lo, 0.5f*hi);
        } else {
            float2 fa = bf2f(apS[(r*16 + r)*STR + w16]);
            float2 fm = bf2f(amS[(r*16 + r)*STR + w16]);
            *(float2*)(g_diag + ((size_t)b*NN + I + r)*NH + 2*w16)
                = make_float2(0.5f*(fa.x + fm.x), 0.5f*(fa.y + fm.y));
        }
    }

    // ---- phase 2: tensor-core layer-2 GEMM ----
    {
        int lane = t & 31, w = t >> 5;
        int p0 = w*16;
        uint32_t aBase = smem_u32(apS) + (uint32_t)((p0 + (lane & 15))*80 + (lane >> 4)*16);
        uint32_t amOff = (uint32_t)(256*STR*4);
        uint32_t wpBase = smem_u32(Wpb) + (uint32_t)((lane & 15)*64);
        uint32_t wmOff = 2048u;

        #pragma unroll
        for (int form = 0; form < 2; form++) {
            uint32_t aAddr = aBase + (form ? amOff : 0u);
            uint32_t wAddr = wpBase + (form ? wmOff : 0u);
            uint32_t A0[4], A1[4];
            ldsm_x4(A0, aAddr);
            ldsm_x4(A1, aAddr + 32);
            float d[4][4];
            #pragma unroll
            for (int nt = 0; nt < 4; nt++) {
                d[nt][0] = 0.f; d[nt][1] = 0.f; d[nt][2] = 0.f; d[nt][3] = 0.f;
                uint32_t b0, b1, b2, b3;
                ldsm_x2t(b0, b1, wAddr + nt*16);
                ldsm_x2t(b2, b3, wAddr + 16*64 + nt*16);
                mma16816(d[nt], A0, b0, b1);
                mma16816(d[nt], A1, b2, b3);
            }
            int rowA = lane >> 2;
            size_t gbA = ((size_t)bid*256 + p0 + rowA)*64 + form*32;
            size_t gbB = gbA + 8*64;
            unsigned int* GA = (unsigned int*)(g_G + gbA);
            unsigned int* GB = (unsigned int*)(g_G + gbB);
            #pragma unroll
            for (int nt = 0; nt < 4; nt++) {
                int col = nt*8 + (lane & 3)*2;
                GA[col >> 1] = f2bf(0.5f*d[nt][0], 0.5f*d[nt][1]);
                GB[col >> 1] = f2bf(0.5f*d[nt][2], 0.5f*d[nt][3]);
            }
        }
    }
}

// ============================================================
// P2: coalesced rowsum gather + layer-2 positional terms + T2 partials.
// ============================================================
__global__ void __launch_bounds__(256) p2_kernel(const float* __restrict__ W2) {
    int ti = blockIdx.x, b = blockIdx.y, t = threadIdx.x;
    __shared__ float Ws3[NH*NH], Ws2s[NH*NH], Ws4[NH*NH];
    __shared__ float raS[16*33], dvS[16*33];
    __shared__ float totS[NH];

    for (int e = t; e < NH*NH; e += 256) {
        Ws3[e]  = W2[e*5 + 3];
        Ws2s[e] = W2[e*5 + 2];
        Ws4[e]  = W2[e*5 + 4];
    }

    int ii = t >> 4, sp = t & 15;
    float2 acc = make_float2(0.f, 0.f);
    const float* base = g_rp + (size_t)(b*NT + ti)*NT*512 + ii*NH + 2*sp;
    #pragma unroll
    for (int tj = 0; tj < NT; tj++) {
        float2 v = *(const float2*)(base + tj*512);
        acc.x += v.x; acc.y += v.y;
    }
    raS[ii*33 + 2*sp] = acc.x; raS[ii*33 + 2*sp + 1] = acc.y;
    {
        float2 dv = *(const float2*)(g_diag + ((size_t)b*NN + ti*16 + ii)*NH + 2*sp);
        dvS[ii*33 + 2*sp] = dv.x; dvS[ii*33 + 2*sp + 1] = dv.y;
    }
    __syncthreads();

    if (t < NH) {
        float s = 0.f;
        #pragma unroll
        for (int r = 0; r < 16; r++) s += raS[r*33 + t];
        totS[t] = s;
    }
    __syncthreads();
    if (t < NH) {
        float a = 0.f;
        #pragma unroll
        for (int q = 0; q < NH; q++) a = fmaf(totS[q], Ws4[q*NH + t], a);
        g_t2p[(b*NT + ti)*NH + t] = a;
    }

    const float inv_n = 1.0f/(float)NN;
    int s0 = t & 15;
    float r2a = 0.f, r2b = 0.f, d2a = 0.f, d2b = 0.f;
    #pragma unroll
    for (int q = 0; q < NH; q++) {
        float rq = raS[ii*33 + q]*inv_n;
        float dq = dvS[ii*33 + q];
        r2a = fmaf(rq, Ws3[q*NH + s0],      r2a);
        r2b = fmaf(rq, Ws3[q*NH + s0 + 16], r2b);
        d2a = fmaf(dq, Ws2s[q*NH + s0],      d2a);
        d2b = fmaf(dq, Ws2s[q*NH + s0 + 16], d2b);
    }
    size_t ro = ((size_t)b*NN + ti*16 + ii)*NH;
    g_R2 [ro + s0]      = r2a;
    g_R2 [ro + s0 + 16] = r2b;
    g_Dg2[ro + s0]      = d2a;
    g_Dg2[ro + s0 + 16] = d2b;
}

// ============================================================
// K2B: register-accumulating epilogue, uint2-vectorized G loads.
// ============================================================
__global__ void __launch_bounds__(256) k2b_kernel(const float* __restrict__ b2) {
    __shared__ float bs1[16*36], bs2[16*36], dgI[16*36];
    __shared__ float t2s[NH];
    __shared__ float red[2*16*36];

    int tp = blockIdx.x, b = blockIdx.y, t = threadIdx.x;
    int ti = 0, rr0 = tp;
    while (rr0 >= NT - ti) { rr0 -= NT - ti; ti++; }
    int tj = ti + rr0;
    int I = ti*TILE, J = tj*TILE;
    int bid = b*NTRI + tp;
    bool isdiag = (ti == tj);

    if (t < NH) {
        const float inv_n2 = 1.0f/((float)NN*(float)NN);
        float a = 0.f;
        #pragma unroll
        for (int k = 0; k < NT; k++) a += g_t2p[(b*NT + k)*NH + t];
        t2s[t] = b2[t] + a*inv_n2;
    }
    __syncthreads();
    for (int e = t; e < 512; e += 256) {
        int r = e >> 5, s = e & 31;
        float t2v = t2s[s];
        bs1[r*36 + s] = g_R2[((size_t)b*NN + I + r)*NH + s] + t2v;
        bs2[r*36 + s] = g_R2[((size_t)b*NN + J + r)*NH + s] + t2v;
        dgI[r*36 + s] = g_Dg2[((size_t)b*NN + I + r)*NH + s];
    }
    __syncthreads();

    int pg = t >> 4, sq = (t >> 1) & 7, qh = t & 1;
    const uint2* Gu2 = (const uint2*)(g_G + (size_t)bid*256*64);
    float4 b1v = *(const float4*)(bs1 + pg*36 + 4*sq);
    float4 dgv = make_float4(0.f, 0.f, 0.f, 0.f);
    if (isdiag) dgv = *(const float4*)(dgI + pg*36 + 4*sq);

    float a0 = 0.f, a1 = 0.f, a2 = 0.f, a3 = 0.f;
    #pragma unroll
    for (int qq = 0; qq < 8; qq++) {
        int q = qh*8 + qq;
        int p = pg*16 + q;
        uint2 up = Gu2[p*16 + sq];
        uint2 um = Gu2[p*16 + 8 + sq];
        float4 b2v = *(const float4*)(bs2 + q*36 + 4*sq);
        bool dflag = isdiag && (pg == q);
        float2 fp0 = bf2f(up.x), fp1 = bf2f(up.y);
        float2 fm0 = bf2f(um.x), fm1 = bf2f(um.y);
        {
            float c1 = fmaxf(fp0.x + fm0.x + b1v.x + (dflag ? dgv.x : 0.f), 0.f);
            float c2 = fmaxf(fp0.x - fm0.x + b2v.x, 0.f);
            float v = c1 + c2;
            if (isdiag) v = (pg < q) ? (c1 + c2) : (dflag ? c1 : 0.f);
            a0 += v;
        }
        {
            float c1 = fmaxf(fp0.y + fm0.y + b1v.y + (dflag ? dgv.y : 0.f), 0.f);
            float c2 = fmaxf(fp0.y - fm0.y + b2v.y, 0.f);
            float v = c1 + c2;
            if (isdiag) v = (pg < q) ? (c1 + c2) : (dflag ? c1 : 0.f);
            a1 += v;
        }
        {
            float c1 = fmaxf(fp1.x + fm1.x + b1v.z + (dflag ? dgv.z : 0.f), 0.f);
            float c2 = fmaxf(fp1.x - fm1.x + b2v.z, 0.f);
            float v = c1 + c2;
            if (isdiag) v = (pg < q) ? (c1 + c2) : (dflag ? c1 : 0.f);
            a2 += v;
        }
        {
            float c1 = fmaxf(fp1.y + fm1.y + b1v.w + (dflag ? dgv.w : 0.f), 0.f);
            float c2 = fmaxf(fp1.y - fm1.y + b2v.w, 0.f);
            float v = c1 + c2;
            if (isdiag) v = (pg < q) ? (c1 + c2) : (dflag ? c1 : 0.f);
            a3 += v;
        }
    }
    *(float4*)(red + qh*16*36 + pg*36 + 4*sq) = make_float4(a0, a1, a2, a3);
    __syncthreads();
    if (t < NH) {
        float p = 0.f;
        #pragma unroll
        for (int pg2 = 0; pg2 < 16; pg2++)
            p += red[pg2*36 + t] + red[16*36 + pg2*36 + t];
        g_part[(size_t)bid*NH + t] = p;
    }
}

// ============================================================
// Final: parallel partial reduce + MLP 32->128->128->1.
// ============================================================
__global__ void __launch_bounds__(256) fin_kernel(const float* __restrict__ D1,
                                                  const float* __restrict__ db1,
                                                  const float* __restrict__ D2,
                                                  const float* __restrict__ db2,
                                                  const float* __restrict__ D3,
                                                  const float* __restrict__ db3,
                                                  float* __restrict__ out) {
    int b = blockIdx.x, tid = threadIdx.x;
    __shared__ float pp[8*NH];
    __shared__ float p[NH];
    __shared__ float m1[128];
    __shared__ float h2p[256];
    __shared__ float m2[128];
    __shared__ float wr[4];

    {
        int s = tid & 31, c = tid >> 5;
        float a = 0.f;
        #pragma unroll 4
        for (int k = c; k < NTRI; k += 8) a += g_part[(size_t)(b*NTRI + k)*NH + s];
        pp[tid] = a;
    }
    __syncthreads();
    if (tid < NH) {
        float t = 0.f;
        #pragma unroll
        for (int c = 0; c < 8; c++) t += pp[c*NH + tid];
        p[tid] = fmaxf(t, 0.f);
    }
    __syncthreads();
    if (tid < 128) {
        float a = db1[tid];
        #pragma unroll
        for (int q = 0; q < NH; q++) a = fmaf(p[q], D1[q*128 + tid], a);
        m1[tid] = fmaxf(a, 0.f);
    }
    __syncthreads();
    {
        int o = tid & 127, half = tid >> 7;
        float a = 0.f;
        #pragma unroll 16
        for (int e = half*64; e < half*64 + 64; e++)
            a = fmaf(m1[e], D2[e*128 + o], a);
        h2p[tid] = a;
    }
    __syncthreads();
    if (tid < 128) m2[tid] = fmaxf(h2p[tid] + h2p[128 + tid] + db2[tid], 0.f);
    __syncthreads();
    if (tid < 128) {
        float v = m2[tid] * D3[tid];
        #pragma unroll
        for (int o = 16; o; o >>= 1) v += __shfl_xor_sync(0xffffffffu, v, o);
        if ((tid & 31) == 0) wr[tid >> 5] = v;
    }
    __syncthreads();
    if (tid == 0) out[b] = wr[0] + wr[1] + wr[2] + wr[3] + db3[0];
}

extern "C" void kernel_launch(void* const* d_in, const int* in_sizes, int n_in,
                              void* d_out, int out_size) {
    const float* x   = (const float*)d_in[0];
    const float* W1  = (const float*)d_in[1];
    const float* b1  = (const float*)d_in[2];
    const float* W2  = (const float*)d_in[3];
    const float* b2  = (const float*)d_in[4];
    const float* D1  = (const float*)d_in[5];
    const float* db1 = (const float*)d_in[6];
    const float* D2  = (const float*)d_in[7];
    const float* db2 = (const float*)d_in[8];
    const float* D3  = (const float*)d_in[9];
    const float* db3 = (const float*)d_in[10];
    float* out = (float*)d_out;

    size_t k1f_smem = 55296;
    cudaFuncSetAttribute(k1f_kernel, cudaFuncAttributeMaxDynamicSharedMemorySize,
                         (int)k1f_smem);

    p1_kernel<<<dim3(NT, NB), 256>>>(x, W1, b1);                // 1
    k1f_kernel<<<dim3(NTRI, NB), 512, k1f_smem>>>(x, W1, W2);   // 2
    p2_kernel<<<dim3(NT, NB), 256>>>(W2);                       // 3
    k2b_kernel<<<dim3(NTRI, NB), 256>>>(b2);                    // 4 -> profiled
    fin_kernel<<<NB, 256>>>(D1, db1, D2, db2, D3, db3, out);    // 5
}

// round 17
// speedup vs baseline: 2.9189x; 1.0667x over previous
#include <cuda_runtime.h>
#include <cuda_bf16.h>
#include <cstdint>

#define NB   8
#define NN   256
#define NIN  16
#define NH   32
#define TILE 16
#define NT   (NN/TILE)          // 16
#define NTRI (NT*(NT+1)/2)      // 136
#define NBLK2 (NB*NTRI)         // 1088
#define STR  20                 // apS/amS row stride (u32 words): 80B

typedef unsigned long long ull;

__device__ __forceinline__ float2 bf2f(unsigned int u) {
    return __bfloat1622float2(*reinterpret_cast<__nv_bfloat162*>(&u));
}
__device__ __forceinline__ unsigned int f2bf(float a, float b) {
    __nv_bfloat162 h = __floats2bfloat162_rn(a, b);
    return *reinterpret_cast<unsigned int*>(&h);
}
__device__ __forceinline__ uint32_t smem_u32(const void* p) {
    uint32_t a;
    asm("{ .reg .u64 t; cvta.to.shared.u64 t, %1; cvt.u32.u64 %0, t; }" : "=r"(a) : "l"(p));
    return a;
}
__device__ __forceinline__ void ldsm_x4(uint32_t* r, uint32_t addr) {
    asm volatile("ldmatrix.sync.aligned.m8n8.x4.shared.b16 {%0,%1,%2,%3}, [%4];"
                 : "=r"(r[0]), "=r"(r[1]), "=r"(r[2]), "=r"(r[3]) : "r"(addr));
}
__device__ __forceinline__ void ldsm_x2t(uint32_t& r0, uint32_t& r1, uint32_t addr) {
    asm volatile("ldmatrix.sync.aligned.m8n8.x2.trans.shared.b16 {%0,%1}, [%2];"
                 : "=r"(r0), "=r"(r1) : "r"(addr));
}
__device__ __forceinline__ void mma16816(float* d, const uint32_t* a,
                                         uint32_t b0, uint32_t b1) {
    asm volatile(
        "mma.sync.aligned.m16n8k16.row.col.f32.bf16.bf16.f32 "
        "{%0,%1,%2,%3}, {%4,%5,%6,%7}, {%8,%9}, {%0,%1,%2,%3};"
        : "+f"(d[0]), "+f"(d[1]), "+f"(d[2]), "+f"(d[3])
        : "r"(a[0]), "r"(a[1]), "r"(a[2]), "r"(a[3]), "r"(b0), "r"(b1));
}

// ---- scratch (device globals) ----
// G row layout (32 u32 words): [P0,M0,P1,M1,...] interleaved pair words
__device__ __nv_bfloat16 g_G[(size_t)NB*NTRI*256*64];   // 35.6 MB
__device__ float g_R1[NB*NN*NH];
__device__ float g_Dg1[NB*NN*NH];
__device__ float g_T1[NB*NH];
__device__ float g_rp[(size_t)NB*NT*NT*512];
__device__ float g_diag[NB*NN*NH];
__device__ float g_R2[NB*NN*NH];
__device__ float g_Dg2[NB*NN*NH];
__device__ float g_t2p[NB*NT*NH];
__device__ float g_part[(size_t)NBLK2*NH];

// ============================================================
// P1: parallel positional precompute. grid (NT, NB).
// ============================================================
__global__ void __launch_bounds__(256) p1_kernel(const float* __restrict__ x,
                                                 const float* __restrict__ W1,
                                                 const float* __restrict__ b1) {
    int ti = blockIdx.x, b = blockIdx.y, t = threadIdx.x;
    __shared__ float xs[NN*17];
    __shared__ float Ws[NH*NH*5];
    __shared__ float part[16*16];
    __shared__ float Ss[NIN];

    const float4* xg = (const float4*)(x + (size_t)b*NN*NIN);
    for (int e = t; e < NN*NIN/4; e += 256) {
        float4 v = xg[e];
        int r = e >> 2, c0 = (e & 3)*4;
        float* dst = xs + r*17 + c0;
        dst[0] = v.x; dst[1] = v.y; dst[2] = v.z; dst[3] = v.w;
    }
    for (int e = t; e < NH*NH*5; e += 256) Ws[e] = W1[e];
    __syncthreads();

    {
        int ch = t >> 4, d = t & 15;
        float s = 0.f;
        #pragma unroll
        for (int r = 0; r < 16; r++) s += xs[(ch*16 + r)*17 + d];
        part[ch*16 + d] = s;
    }
    __syncthreads();
    if (t < NIN) {
        float s = 0.f;
        #pragma unroll
        for (int ch = 0; ch < 16; ch++) s += part[ch*16 + t];
        Ss[t] = s;
    }
    __syncthreads();

    const float inv_n = 1.0f/(float)NN, inv_n2 = inv_n*inv_n;
    #pragma unroll
    for (int it = 0; it < 2; it++) {
        int item = t + it*256;
        int r = item >> 5, s = item & 31;
        int i = ti*16 + r;
        float rv = 0.f, dg = 0.f;
        #pragma unroll
        for (int d = 0; d < NIN; d++) {
            float xi = xs[i*17 + d];
            const float* wd  = &Ws[(d*NH + s)*5];
            const float* wd2 = &Ws[((NIN+d)*NH + s)*5];
            rv += xi*wd[3] + xi*Ss[d]*wd2[3];
            dg += xi*(wd[0] + wd[1] + wd[2]) + xi*xi*wd2[2];
        }
        g_R1 [((size_t)b*NN + i)*NH + s] = rv*inv_n;
        g_Dg1[((size_t)b*NN + i)*NH + s] = dg;
    }
    if (ti == 0 && t < NH) {
        int s = t;
        float tv = b1[s];
        #pragma unroll
        for (int d = 0; d < NIN; d++) {
            tv += Ss[d]*inv_n2       * Ws[(d*NH + s)*5 + 4];
            tv += Ss[d]*Ss[d]*inv_n2 * Ws[((NIN+d)*NH + s)*5 + 4];
        }
        g_T1[b*NH + s] = tv;
    }
}

// ============================================================
// K1F: both layers on tensor cores. Interleaved G stores (uint2).
// ============================================================
__global__ void __launch_bounds__(512, 2) k1f_kernel(const float* __restrict__ x,
                                                     const float* __restrict__ W1,
                                                     const float* __restrict__ W2) {
    extern __shared__ __align__(16) char smraw[];
    unsigned int* Wab = (unsigned int*)smraw;        // 16x16 u32 @0
    unsigned int* Wpb = Wab + 256;                   // 32x16 u32 @1024
    unsigned int* Wmb = Wpb + 512;                   // @3072
    float* xi   = (float*)(Wmb + 512);               // 272 @5120
    float* xj   = xi + 272;                          // 272
    float* posI = xj + 272;                          // 576
    float* posJ = posI + 576;                        // 576
    float* dgs  = posJ + 576;                        // 576
    float* t1s  = dgs + 576;                         // 32
    unsigned int* apS = (unsigned int*)(t1s + 32);   // 256*20 u32
    unsigned int* amS = apS + 256*STR;               // 256*20 u32

    int tp = blockIdx.x, b = blockIdx.y, t = threadIdx.x;
    int ti = 0, rr0 = tp;
    while (rr0 >= NT - ti) { rr0 -= NT - ti; ti++; }
    int tj = ti + rr0;
    int I = ti*TILE, J = tj*TILE;
    int bid = b*NTRI + tp;
    bool isdiag = (ti == tj);

    if (t < 256) {
        int r = t >> 4, c = t & 15;
        xi[r*17 + c] = x[(size_t)b*NN*NIN + (I+r)*NIN + c];
        int d = r, k = c, s0 = 2*k;
        float a0 = W1[((NIN+d)*NH + s0  )*5 + 0] + W1[((NIN+d)*NH + s0  )*5 + 1];
        float a1 = W1[((NIN+d)*NH + s0+1)*5 + 0] + W1[((NIN+d)*NH + s0+1)*5 + 1];
        Wab[d*16 + k] = f2bf(a0, a1);
    } else {
        int e = t - 256;
        int r = e >> 4, c = e & 15;
        xj[r*17 + c] = x[(size_t)b*NN*NIN + (J+r)*NIN + c];
    }
    {
        int e = t;
        int tt = e >> 4, k = e & 15, s0 = 2*k;
        float w00 = W2[(tt*NH + s0  )*5 + 0], w01 = W2[(tt*NH + s0  )*5 + 1];
        float w10 = W2[(tt*NH + s0+1)*5 + 0], w11 = W2[(tt*NH + s0+1)*5 + 1];
        Wpb[tt*16 + k] = f2bf(w00 + w01, w10 + w11);
        Wmb[tt*16 + k] = f2bf(w00 - w01, w10 - w11);
    }
    {
        int e = t;
        int r = e >> 5, s = e & 31;
        posI[r*36 + s] = g_R1 [((size_t)b*NN + I + r)*NH + s];
        posJ[r*36 + s] = g_R1 [((size_t)b*NN + J + r)*NH + s];
        dgs [r*36 + s] = g_Dg1[((size_t)b*NN + I + r)*NH + s];
    }
    if (t < NH) t1s[t] = g_T1[b*NH + t];
    __syncthreads();

    // ---- phase 1: layer-1 via MMA, A built in registers ----
    {
        int lane = t & 31, w = t >> 5;
        int p0 = w*16;
        int row = lane >> 2;
        int p1 = p0 + row, p2 = p1 + 8;
        int ii1 = p1 >> 4, jj1 = p1 & 15;
        int ii2 = p2 >> 4, jj2 = p2 & 15;
        int k0 = (lane & 3)*2;

        uint32_t A[4];
        A[0] = f2bf(xi[ii1*17 + k0]     * xj[jj1*17 + k0],
                    xi[ii1*17 + k0 + 1] * xj[jj1*17 + k0 + 1]);
        A[1] = f2bf(xi[ii2*17 + k0]     * xj[jj2*17 + k0],
                    xi[ii2*17 + k0 + 1] * xj[jj2*17 + k0 + 1]);
        A[2] = f2bf(xi[ii1*17 + k0 + 8] * xj[jj1*17 + k0 + 8],
                    xi[ii1*17 + k0 + 9] * xj[jj1*17 + k0 + 9]);
        A[3] = f2bf(xi[ii2*17 + k0 + 8] * xj[jj2*17 + k0 + 8],
                    xi[ii2*17 + k0 + 9] * xj[jj2*17 + k0 + 9]);

        uint32_t waBase = smem_u32(Wab) + (uint32_t)((lane & 15)*64);
        bool dg1 = isdiag && (ii1 == jj1);
        bool dg2 = isdiag && (ii2 == jj2);

        #pragma unroll
        for (int nt = 0; nt < 4; nt++) {
            float dd[4] = {0.f, 0.f, 0.f, 0.f};
            uint32_t b0, b1;
            ldsm_x2t(b0, b1, waBase + nt*16);
            mma16816(dd, A, b0, b1);
            int s0 = nt*8 + (lane & 3)*2;
            float2 t1v = *(const float2*)(t1s + s0);
            {
                float2 pIv = *(const float2*)(posI + ii1*36 + s0);
                float2 pJv = *(const float2*)(posJ + jj1*36 + s0);
                float e0 = 0.f, e1 = 0.f;
                if (dg1) { float2 dv = *(const float2*)(dgs + ii1*36 + s0); e0 = dv.x; e1 = dv.y; }
                float c1lo = fmaxf(dd[0] + pIv.x + t1v.x + e0, 0.f);
                float c1hi = fmaxf(dd[1] + pIv.y + t1v.y + e1, 0.f);
                float c2lo = fmaxf(dd[0] + pJv.x + t1v.x + e0, 0.f);
                float c2hi = fmaxf(dd[1] + pJv.y + t1v.y + e1, 0.f);
                apS[p1*STR + (s0 >> 1)] = f2bf(c1lo + c2lo, c1hi + c2hi);
                amS[p1*STR + (s0 >> 1)] = f2bf(c1lo - c2lo, c1hi - c2hi);
            }
            {
                float2 pIv = *(const float2*)(posI + ii2*36 + s0);
                float2 pJv = *(const float2*)(posJ + jj2*36 + s0);
                float e0 = 0.f, e1 = 0.f;
                if (dg2) { float2 dv = *(const float2*)(dgs + ii2*36 + s0); e0 = dv.x; e1 = dv.y; }
                float c1lo = fmaxf(dd[2] + pIv.x + t1v.x + e0, 0.f);
                float c1hi = fmaxf(dd[3] + pIv.y + t1v.y + e1, 0.f);
                float c2lo = fmaxf(dd[2] + pJv.x + t1v.x + e0, 0.f);
                float c2hi = fmaxf(dd[3] + pJv.y + t1v.y + e1, 0.f);
                apS[p2*STR + (s0 >> 1)] = f2bf(c1lo + c2lo, c1hi + c2hi);
                amS[p2*STR + (s0 >> 1)] = f2bf(c1lo - c2lo, c1hi - c2hi);
            }
        }
    }
    __syncthreads();

    // ---- rowsum partials + diag ----
    {
        int side = t >> 8, e = t & 255;
        int r = e >> 4, w16 = e & 15;
        if (side == 0) {
            float lo = 0.f, hi = 0.f;
            #pragma unroll
            for (int q = 0; q < 16; q++) {
                float2 fa = bf2f(apS[(r*16 + q)*STR + w16]);
                float2 fm = bf2f(amS[(r*16 + q)*STR + w16]);
                lo += fa.x + fm.x;
                hi += fa.y + fm.y;
            }
            *(float2*)(g_rp + ((size_t)((b*NT + ti)*NT + tj))*512 + r*NH + 2*w16)
                = make_float2(0.5f*lo, 0.5f*hi);
        } else if (!isdiag) {
            float lo = 0.f, hi = 0.f;
            #pragma unroll
            for (int q = 0; q < 16; q++) {
                float2 fa = bf2f(apS[(q*16 + r)*STR + w16]);
                float2 fm = bf2f(amS[(q*16 + r)*STR + w16]);
                lo += fa.x - fm.x;
                hi += fa.y - fm.y;
            }
            *(float2*)(g_rp + ((size_t)((b*NT + tj)*NT + ti))*512 + r*NH + 2*w16)
                = make_float2(0.5f*lo, 0.5f*hi);
        } else {
            float2 fa = bf2f(apS[(r*16 + r)*STR + w16]);
            float2 fm = bf2f(amS[(r*16 + r)*STR + w16]);
            *(float2*)(g_diag + ((size_t)b*NN + I + r)*NH + 2*w16)
                = make_float2(0.5f*(fa.x + fm.x), 0.5f*(fa.y + fm.y));
        }
    }

    // ---- phase 2: layer-2 GEMM, both forms per nt, interleaved uint2 stores ----
    {
        int lane = t & 31, w = t >> 5;
        int p0 = w*16;
        uint32_t aBase = smem_u32(apS) + (uint32_t)((p0 + (lane & 15))*80 + (lane >> 4)*16);
        uint32_t amOff = (uint32_t)(256*STR*4);
        uint32_t wpBase = smem_u32(Wpb) + (uint32_t)((lane & 15)*64);

        uint32_t A0p[4], A1p[4], A0m[4], A1m[4];
        ldsm_x4(A0p, aBase);
        ldsm_x4(A1p, aBase + 32);
        ldsm_x4(A0m, aBase + amOff);
        ldsm_x4(A1m, aBase + amOff + 32);

        int rowA = lane >> 2;
        unsigned int* GA = (unsigned int*)(g_G + ((size_t)bid*256 + p0 + rowA)*64);
        unsigned int* GB = (unsigned int*)(g_G + ((size_t)bid*256 + p0 + rowA + 8)*64);

        #pragma unroll
        for (int nt = 0; nt < 4; nt++) {
            float dP[4] = {0.f, 0.f, 0.f, 0.f};
            float dM[4] = {0.f, 0.f, 0.f, 0.f};
            uint32_t b0, b1, b2, b3;
            ldsm_x2t(b0, b1, wpBase + nt*16);
            ldsm_x2t(b2, b3, wpBase + 16*64 + nt*16);
            mma16816(dP, A0p, b0, b1);
            mma16816(dP, A1p, b2, b3);
            ldsm_x2t(b0, b1, wpBase + 2048u + nt*16);
            ldsm_x2t(b2, b3, wpBase + 2048u + 16*64 + nt*16);
            mma16816(dM, A0m, b0, b1);
            mma16816(dM, A1m, b2, b3);
            int c = nt*4 + (lane & 3);    // pair index 0..15
            *(uint2*)(GA + 2*c) = make_uint2(f2bf(0.5f*dP[0], 0.5f*dP[1]),
                                             f2bf(0.5f*dM[0], 0.5f*dM[1]));
            *(uint2*)(GB + 2*c) = make_uint2(f2bf(0.5f*dP[2], 0.5f*dP[3]),
                                             f2bf(0.5f*dM[2], 0.5f*dM[3]));
        }
    }
}

// ============================================================
// P2: coalesced rowsum gather + layer-2 positional terms + T2 partials.
// ============================================================
__global__ void __launch_bounds__(256) p2_kernel(const float* __restrict__ W2) {
    int ti = blockIdx.x, b = blockIdx.y, t = threadIdx.x;
    __shared__ float Ws3[NH*NH], Ws2s[NH*NH], Ws4[NH*NH];
    __shared__ float raS[16*33], dvS[16*33];
    __shared__ float totS[NH];

    for (int e = t; e < NH*NH; e += 256) {
        Ws3[e]  = W2[e*5 + 3];
        Ws2s[e] = W2[e*5 + 2];
        Ws4[e]  = W2[e*5 + 4];
    }

    int ii = t >> 4, sp = t & 15;
    float2 acc = make_float2(0.f, 0.f);
    const float* base = g_rp + (size_t)(b*NT + ti)*NT*512 + ii*NH + 2*sp;
    #pragma unroll
    for (int tj = 0; tj < NT; tj++) {
        float2 v = *(const float2*)(base + tj*512);
        acc.x += v.x; acc.y += v.y;
    }
    raS[ii*33 + 2*sp] = acc.x; raS[ii*33 + 2*sp + 1] = acc.y;
    {
        float2 dv = *(const float2*)(g_diag + ((size_t)b*NN + ti*16 + ii)*NH + 2*sp);
        dvS[ii*33 + 2*sp] = dv.x; dvS[ii*33 + 2*sp + 1] = dv.y;
    }
    __syncthreads();

    if (t < NH) {
        float s = 0.f;
        #pragma unroll
        for (int r = 0; r < 16; r++) s += raS[r*33 + t];
        totS[t] = s;
    }
    __syncthreads();
    if (t < NH) {
        float a = 0.f;
        #pragma unroll
        for (int q = 0; q < NH; q++) a = fmaf(totS[q], Ws4[q*NH + t], a);
        g_t2p[(b*NT + ti)*NH + t] = a;
    }

    const float inv_n = 1.0f/(float)NN;
    int s0 = t & 15;
    float r2a = 0.f, r2b = 0.f, d2a = 0.f, d2b = 0.f;
    #pragma unroll
    for (int q = 0; q < NH; q++) {
        float rq = raS[ii*33 + q]*inv_n;
        float dq = dvS[ii*33 + q];
        r2a = fmaf(rq, Ws3[q*NH + s0],      r2a);
        r2b = fmaf(rq, Ws3[q*NH + s0 + 16], r2b);
        d2a = fmaf(dq, Ws2s[q*NH + s0],      d2a);
        d2b = fmaf(dq, Ws2s[q*NH + s0 + 16], d2b);
    }
    size_t ro = ((size_t)b*NN + ti*16 + ii)*NH;
    g_R2 [ro + s0]      = r2a;
    g_R2 [ro + s0 + 16] = r2b;
    g_Dg2[ro + s0]      = d2a;
    g_Dg2[ro + s0 + 16] = d2b;
}

// ============================================================
// K2B: register-accumulating epilogue, uint4 interleaved G loads,
// uniform diag/non-diag branch split.
// ============================================================
__global__ void __launch_bounds__(256) k2b_kernel(const float* __restrict__ b2) {
    __shared__ float bs1[16*36], bs2[16*36], dgI[16*36];
    __shared__ float t2s[NH];
    __shared__ float red[2*16*36];

    int tp = blockIdx.x, b = blockIdx.y, t = threadIdx.x;
    int ti = 0, rr0 = tp;
    while (rr0 >= NT - ti) { rr0 -= NT - ti; ti++; }
    int tj = ti + rr0;
    int I = ti*TILE, J = tj*TILE;
    int bid = b*NTRI + tp;
    bool isdiag = (ti == tj);

    if (t < NH) {
        const float inv_n2 = 1.0f/((float)NN*(float)NN);
        float a = 0.f;
        #pragma unroll
        for (int k = 0; k < NT; k++) a += g_t2p[(b*NT + k)*NH + t];
        t2s[t] = b2[t] + a*inv_n2;
    }
    __syncthreads();
    for (int e = t; e < 512; e += 256) {
        int r = e >> 5, s = e & 31;
        float t2v = t2s[s];
        bs1[r*36 + s] = g_R2[((size_t)b*NN + I + r)*NH + s] + t2v;
        bs2[r*36 + s] = g_R2[((size_t)b*NN + J + r)*NH + s] + t2v;
        dgI[r*36 + s] = g_Dg2[((size_t)b*NN + I + r)*NH + s];
    }
    __syncthreads();

    int pg = t >> 4, sq = (t >> 1) & 7, qh = t & 1;
    const uint4* Gu4 = (const uint4*)(g_G + (size_t)bid*256*64);
    float4 b1v = *(const float4*)(bs1 + pg*36 + 4*sq);

    float a0 = 0.f, a1 = 0.f, a2 = 0.f, a3 = 0.f;
    if (!isdiag) {
        #pragma unroll
        for (int qq = 0; qq < 8; qq++) {
            int q = qh*8 + qq;
            int p = pg*16 + q;
            uint4 g = Gu4[p*8 + sq];          // P_c0, M_c0, P_c1, M_c1
            float4 b2v = *(const float4*)(bs2 + q*36 + 4*sq);
            float2 fp0 = bf2f(g.x), fm0 = bf2f(g.y);
            float2 fp1 = bf2f(g.z), fm1 = bf2f(g.w);
            a0 += fmaxf(fp0.x + fm0.x + b1v.x, 0.f) + fmaxf(fp0.x - fm0.x + b2v.x, 0.f);
            a1 += fmaxf(fp0.y + fm0.y + b1v.y, 0.f) + fmaxf(fp0.y - fm0.y + b2v.y, 0.f);
            a2 += fmaxf(fp1.x + fm1.x + b1v.z, 0.f) + fmaxf(fp1.x - fm1.x + b2v.z, 0.f);
            a3 += fmaxf(fp1.y + fm1.y + b1v.w, 0.f) + fmaxf(fp1.y - fm1.y + b2v.w, 0.f);
        }
    } else {
        float4 dgv = *(const float4*)(dgI + pg*36 + 4*sq);
        #pragma unroll
        for (int qq = 0; qq < 8; qq++) {
            int q = qh*8 + qq;
            int p = pg*16 + q;
            uint4 g = Gu4[p*8 + sq];
            float4 b2v = *(const float4*)(bs2 + q*36 + 4*sq);
            bool dflag = (pg == q);
            float2 fp0 = bf2f(g.x), fm0 = bf2f(g.y);
            float2 fp1 = bf2f(g.z), fm1 = bf2f(g.w);
            {
                float c1 = fmaxf(fp0.x + fm0.x + b1v.x + (dflag ? dgv.x : 0.f), 0.f);
                float c2 = fmaxf(fp0.x - fm0.x + b2v.x, 0.f);
                a0 += (pg < q) ? (c1 + c2) : (dflag ? c1 : 0.f);
            }
            {
                float c1 = fmaxf(fp0.y + fm0.y + b1v.y + (dflag ? dgv.y : 0.f), 0.f);
                float c2 = fmaxf(fp0.y - fm0.y + b2v.y, 0.f);
                a1 += (pg < q) ? (c1 + c2) : (dflag ? c1 : 0.f);
            }
            {
                float c1 = fmaxf(fp1.x + fm1.x + b1v.z + (dflag ? dgv.z : 0.f), 0.f);
                float c2 = fmaxf(fp1.x - fm1.x + b2v.z, 0.f);
                a2 += (pg < q) ? (c1 + c2) : (dflag ? c1 : 0.f);
            }
            {
                float c1 = fmaxf(fp1.y + fm1.y + b1v.w + (dflag ? dgv.w : 0.f), 0.f);
                float c2 = fmaxf(fp1.y - fm1.y + b2v.w, 0.f);
                a3 += (pg < q) ? (c1 + c2) : (dflag ? c1 : 0.f);
            }
        }
    }
    *(float4*)(red + qh*16*36 + pg*36 + 4*sq) = make_float4(a0, a1, a2, a3);
    __syncthreads();
    if (t < NH) {
        float p = 0.f;
        #pragma unroll
        for (int pg2 = 0; pg2 < 16; pg2++)
            p += red[pg2*36 + t] + red[16*36 + pg2*36 + t];
        g_part[(size_t)bid*NH + t] = p;
    }
}

// ============================================================
// Final: parallel partial reduce + MLP 32->128->128->1.
// ============================================================
__global__ void __launch_bounds__(256) fin_kernel(const float* __restrict__ D1,
                                                  const float* __restrict__ db1,
                                                  const float* __restrict__ D2,
                                                  const float* __restrict__ db2,
                                                  const float* __restrict__ D3,
                                                  const float* __restrict__ db3,
                                                  float* __restrict__ out) {
    int b = blockIdx.x, tid = threadIdx.x;
    __shared__ float pp[8*NH];
    __shared__ float p[NH];
    __shared__ float m1[128];
    __shared__ float h2p[256];
    __shared__ float m2[128];
    __shared__ float wr[4];

    {
        int s = tid & 31, c = tid >> 5;
        float a = 0.f;
        #pragma unroll 4
        for (int k = c; k < NTRI; k += 8) a += g_part[(size_t)(b*NTRI + k)*NH + s];
        pp[tid] = a;
    }
    __syncthreads();
    if (tid < NH) {
        float t = 0.f;
        #pragma unroll
        for (int c = 0; c < 8; c++) t += pp[c*NH + tid];
        p[tid] = fmaxf(t, 0.f);
    }
    __syncthreads();
    if (tid < 128) {
        float a = db1[tid];
        #pragma unroll
        for (int q = 0; q < NH; q++) a = fmaf(p[q], D1[q*128 + tid], a);
        m1[tid] = fmaxf(a, 0.f);
    }
    __syncthreads();
    {
        int o = tid & 127, half = tid >> 7;
        float a = 0.f;
        #pragma unroll 16
        for (int e = half*64; e < half*64 + 64; e++)
            a = fmaf(m1[e], D2[e*128 + o], a);
        h2p[tid] = a;
    }
    __syncthreads();
    if (tid < 128) m2[tid] = fmaxf(h2p[tid] + h2p[128 + tid] + db2[tid], 0.f);
    __syncthreads();
    if (tid < 128) {
        float v = m2[tid] * D3[tid];
        #pragma unroll
        for (int o = 16; o; o >>= 1) v += __shfl_xor_sync(0xffffffffu, v, o);
        if ((tid & 31) == 0) wr[tid >> 5] = v;
    }
    __syncthreads();
    if (tid == 0) out[b] = wr[0] + wr[1] + wr[2] + wr[3] + db3[0];
}

extern "C" void kernel_launch(void* const* d_in, const int* in_sizes, int n_in,
                              void* d_out, int out_size) {
    const float* x   = (const float*)d_in[0];
    const float* W1  = (const float*)d_in[1];
    const float* b1  = (const float*)d_in[2];
    const float* W2  = (const float*)d_in[3];
    const float* b2  = (const float*)d_in[4];
    const float* D1  = (const float*)d_in[5];
    const float* db1 = (const float*)d_in[6];
    const float* D2  = (const float*)d_in[7];
    const float* db2 = (const float*)d_in[8];
    const float* D3  = (const float*)d_in[9];
    const float* db3 = (const float*)d_in[10];
    float* out = (float*)d_out;

    size_t k1f_smem = 55296;
    cudaFuncSetAttribute(k1f_kernel, cudaFuncAttributeMaxDynamicSharedMemorySize,
                         (int)k1f_smem);

    p1_kernel<<<dim3(NT, NB), 256>>>(x, W1, b1);                // 1
    k1f_kernel<<<dim3(NTRI, NB), 512, k1f_smem>>>(x, W1, W2);   // 2
    p2_kernel<<<dim3(NT, NB), 256>>>(W2);                       // 3
    k2b_kernel<<<dim3(NTRI, NB), 256>>>(b2);                    // 4 -> profiled
    fin_kernel<<<NB, 256>>>(D1, db1, D2, db2, D3, db3, out);    // 5
}